// round 8
// baseline (speedup 1.0000x reference)
#include <cuda_runtime.h>
#include <cuda_bf16.h>
#include <cstdint>
#include <cstddef>

// Problem constants
#define B_   2
#define L_   2048
#define D_   1024
#define H_   16
#define HD_  64
#define TOK  (B_ * L_)          // 4096 tokens

// ---------------------------------------------------------------------------
// Scratch (__device__ globals; no cudaMalloc allowed)
// ---------------------------------------------------------------------------
__device__ __align__(16) __nv_bfloat16 g_xh[(size_t)TOK * D_];
__device__ __align__(16) __nv_bfloat16 g_xl[(size_t)TOK * D_];
__device__ __align__(16) __nv_bfloat16 g_wqh[(size_t)3 * D_ * D_];
__device__ __align__(16) __nv_bfloat16 g_wql[(size_t)3 * D_ * D_];
__device__ __align__(16) __nv_bfloat16 g_woh[(size_t)D_ * D_];
__device__ __align__(16) __nv_bfloat16 g_wol[(size_t)D_ * D_];
// head-major split qkv: [part(q/k/v)][b][h][l][64]
__device__ __align__(16) __nv_bfloat16 g_qkvh[(size_t)3 * TOK * D_];
__device__ __align__(16) __nv_bfloat16 g_qkvl[(size_t)3 * TOK * D_];
// attention context, split: [tok][1024]
__device__ __align__(16) __nv_bfloat16 g_ch[(size_t)TOK * D_];
__device__ __align__(16) __nv_bfloat16 g_cl[(size_t)TOK * D_];

// ---------------------------------------------------------------------------
// Helpers
// ---------------------------------------------------------------------------
__device__ __forceinline__ uint32_t smem_u32(const void* p) {
    uint32_t a;
    asm("{ .reg .u64 t; cvta.to.shared.u64 t, %1; cvt.u32.u64 %0, t; }" : "=r"(a) : "l"(p));
    return a;
}

__device__ __forceinline__ void mma16816(float* c, const uint32_t* a, const uint32_t* b) {
    asm volatile("mma.sync.aligned.m16n8k16.row.col.f32.bf16.bf16.f32 "
                 "{%0,%1,%2,%3}, {%4,%5,%6,%7}, {%8,%9}, {%0,%1,%2,%3};"
                 : "+f"(c[0]), "+f"(c[1]), "+f"(c[2]), "+f"(c[3])
                 : "r"(a[0]), "r"(a[1]), "r"(a[2]), "r"(a[3]),
                   "r"(b[0]), "r"(b[1]));
}

__device__ __forceinline__ void ldsm4(uint32_t* r, uint32_t addr) {
    asm volatile("ldmatrix.sync.aligned.m8n8.x4.shared.b16 {%0,%1,%2,%3}, [%4];"
                 : "=r"(r[0]), "=r"(r[1]), "=r"(r[2]), "=r"(r[3]) : "r"(addr));
}
__device__ __forceinline__ void ldsm4t(uint32_t* r, uint32_t addr) {
    asm volatile("ldmatrix.sync.aligned.m8n8.x4.trans.shared.b16 {%0,%1,%2,%3}, [%4];"
                 : "=r"(r[0]), "=r"(r[1]), "=r"(r[2]), "=r"(r[3]) : "r"(addr));
}

__device__ __forceinline__ uint32_t pack_bf(__nv_bfloat16 lo, __nv_bfloat16 hi) {
    return (uint32_t)__bfloat16_as_ushort(lo) | ((uint32_t)__bfloat16_as_ushort(hi) << 16);
}
// split two floats into packed bf16 hi-pair and lo-pair (element0 in low half)
__device__ __forceinline__ void split_pack2(float x, float y, uint32_t& hp, uint32_t& lp) {
    __nv_bfloat16 hx = __float2bfloat16(x), hy = __float2bfloat16(y);
    __nv_bfloat16 lx = __float2bfloat16(x - __bfloat162float(hx));
    __nv_bfloat16 ly = __float2bfloat16(y - __bfloat162float(hy));
    hp = pack_bf(hx, hy);
    lp = pack_bf(lx, ly);
}

#define CP_ASYNC16(dst, src) \
    asm volatile("cp.async.cg.shared.global [%0], [%1], 16;" :: "r"(dst), "l"(src) : "memory")
#define CP_COMMIT() asm volatile("cp.async.commit_group;" ::: "memory")
#define CP_WAIT1()  asm volatile("cp.async.wait_group 1;" ::: "memory")
#define CP_WAIT0()  asm volatile("cp.async.wait_group 0;" ::: "memory")

// ---------------------------------------------------------------------------
// split fp32 -> bf16 hi + lo (for x, w_qkv, w_out)
// ---------------------------------------------------------------------------
__global__ void __launch_bounds__(256) split_bf16(
    const float* __restrict__ in, __nv_bfloat16* __restrict__ hi,
    __nv_bfloat16* __restrict__ lo, int n4)
{
    int i = blockIdx.x * 256 + threadIdx.x;
    if (i >= n4) return;
    float4 v = ((const float4*)in)[i];
    uint32_t h0, l0v, h1, l1v;
    split_pack2(v.x, v.y, h0, l0v);
    split_pack2(v.z, v.w, h1, l1v);
    ((uint32_t*)hi)[i * 2 + 0] = h0;
    ((uint32_t*)hi)[i * 2 + 1] = h1;
    ((uint32_t*)lo)[i * 2 + 0] = l0v;
    ((uint32_t*)lo)[i * 2 + 1] = l1v;
}

// ---------------------------------------------------------------------------
// GEMM: 128x128 CTA tile, BK=32, 256 threads (8 warps, 2x4), warp tile 64x32,
// 3-stage cp.async pipeline, ldmatrix fragments, term-major MMA order.
// C = (Ah+Al)(Bh+Bl)^T dropping Al*Bl.
// ---------------------------------------------------------------------------
#define SROW 40
#define G_TILE_B  (128 * SROW * 2)        // 10240 B per matrix tile
#define G_STAGE_B (4 * G_TILE_B)          // 40960 B
#define G_SMEM    (3 * G_STAGE_B)         // 122880 B

#define GEMM_BODY(Ah, Al, Bh, Bl, K)                                           \
    extern __shared__ __align__(16) char smemraw[];                            \
    const uint32_t sb = smem_u32(smemraw);                                     \
    const int tid  = threadIdx.x;                                              \
    const int lane = tid & 31;                                                 \
    const int warp = tid >> 5;                                                 \
    const int wm   = warp >> 2;          /* 0..1 : 64-row slice */             \
    const int wn   = warp & 3;           /* 0..3 : 32-col slice */             \
    const int bm   = blockIdx.y * 128;                                         \
    const int bn   = blockIdx.x * 128;                                         \
    float acc[4][4][4];                                                        \
    _Pragma("unroll")                                                          \
    for (int i = 0; i < 4; i++)                                                \
        _Pragma("unroll")                                                      \
        for (int j = 0; j < 4; j++)                                            \
            _Pragma("unroll")                                                  \
            for (int e = 0; e < 4; e++) acc[i][j][e] = 0.0f;                   \
    const int nk = K / 32;                                                     \
    auto load_st = [&](int kt, int st) {                                       \
        const uint32_t base = sb + st * G_STAGE_B;                             \
        const size_t ko = (size_t)kt * 32;                                     \
        _Pragma("unroll")                                                      \
        for (int i = 0; i < 2; i++) {                                          \
            const int c = tid + i * 256;                                       \
            const int row = c >> 2, seg = c & 3;                               \
            const uint32_t dof = base + (uint32_t)(row * SROW + seg * 8) * 2;  \
            const size_t gA = (size_t)(bm + row) * K + seg * 8 + ko;           \
            const size_t gB = (size_t)(bn + row) * K + seg * 8 + ko;           \
            CP_ASYNC16(dof + 0 * G_TILE_B, Ah + gA);                           \
            CP_ASYNC16(dof + 1 * G_TILE_B, Al + gA);                           \
            CP_ASYNC16(dof + 2 * G_TILE_B, Bh + gB);                           \
            CP_ASYNC16(dof + 3 * G_TILE_B, Bl + gB);                           \
        }                                                                      \
        CP_COMMIT();                                                           \
    };                                                                         \
    load_st(0, 0);                                                             \
    load_st(1, 1);                                                             \
    for (int kt = 0; kt < nk; kt++) {                                          \
        const int st = kt % 3;                                                 \
        if (kt < nk - 1) { CP_WAIT1(); } else { CP_WAIT0(); }                  \
        __syncthreads();                                                       \
        if (kt + 2 < nk) load_st(kt + 2, (kt + 2) % 3);                        \
        const uint32_t aAh = sb + st * G_STAGE_B;                              \
        const uint32_t aAl = aAh + G_TILE_B;                                   \
        const uint32_t aBh = aAh + 2 * G_TILE_B;                               \
        const uint32_t aBl = aAh + 3 * G_TILE_B;                               \
        _Pragma("unroll")                                                      \
        for (int ks = 0; ks < 32; ks += 16) {                                  \
            const uint32_t a_lro =                                             \
                (uint32_t)((lane & 15) * SROW + (lane >> 4) * 8 + ks) * 2;     \
            const uint32_t b_lro =                                             \
                (uint32_t)((((lane >> 4) << 3) + (lane & 7)) * SROW +          \
                           ((lane >> 3) & 1) * 8 + ks) * 2;                    \
            uint32_t fAh[4][4], fAl[4][4], fB_h[2][4], fB_l[2][4];             \
            _Pragma("unroll")                                                  \
            for (int mi = 0; mi < 4; mi++) {                                   \
                const uint32_t mo = (uint32_t)((wm * 64 + mi * 16) * SROW) * 2;\
                ldsm4(fAh[mi], aAh + mo + a_lro);                              \
                ldsm4(fAl[mi], aAl + mo + a_lro);                              \
            }                                                                  \
            _Pragma("unroll")                                                  \
            for (int jp = 0; jp < 2; jp++) {                                   \
                const uint32_t no = (uint32_t)((wn * 32 + jp * 16) * SROW) * 2;\
                ldsm4(fB_h[jp], aBh + no + b_lro);                             \
                ldsm4(fB_l[jp], aBl + no + b_lro);                             \
            }                                                                  \
            _Pragma("unroll")                                                  \
            for (int mi = 0; mi < 4; mi++)                                     \
                _Pragma("unroll")                                              \
                for (int nj = 0; nj < 4; nj++)                                 \
                    mma16816(acc[mi][nj], fAh[mi],                             \
                             &fB_h[nj >> 1][(nj & 1) * 2]);                    \
            _Pragma("unroll")                                                  \
            for (int mi = 0; mi < 4; mi++)                                     \
                _Pragma("unroll")                                              \
                for (int nj = 0; nj < 4; nj++)                                 \
                    mma16816(acc[mi][nj], fAh[mi],                             \
                             &fB_l[nj >> 1][(nj & 1) * 2]);                    \
            _Pragma("unroll")                                                  \
            for (int mi = 0; mi < 4; mi++)                                     \
                _Pragma("unroll")                                              \
                for (int nj = 0; nj < 4; nj++)                                 \
                    mma16816(acc[mi][nj], fAl[mi],                             \
                             &fB_h[nj >> 1][(nj & 1) * 2]);                    \
        }                                                                      \
    }

// Out-proj GEMM: fp32 output, row-major C[M,N]
__global__ void __launch_bounds__(256) gemm_mma(
    const __nv_bfloat16* __restrict__ Ah, const __nv_bfloat16* __restrict__ Al,
    const __nv_bfloat16* __restrict__ Bh, const __nv_bfloat16* __restrict__ Bl,
    float* __restrict__ C, int N, int K)
{
    GEMM_BODY(Ah, Al, Bh, Bl, K)
    #pragma unroll
    for (int mi = 0; mi < 4; mi++) {
        const int m = bm + wm * 64 + mi * 16 + (lane >> 2);
        #pragma unroll
        for (int nj = 0; nj < 4; nj++) {
            const int n = bn + wn * 32 + nj * 8 + (lane & 3) * 2;
            *(float2*)(C + (size_t)m * N + n)       = make_float2(acc[mi][nj][0], acc[mi][nj][1]);
            *(float2*)(C + (size_t)(m + 8) * N + n) = make_float2(acc[mi][nj][2], acc[mi][nj][3]);
        }
    }
}

// QKV GEMM: writes split bf16 head-major qkv [part][b][h][l][64]
__global__ void __launch_bounds__(256) gemm_mma_qkv(
    const __nv_bfloat16* __restrict__ Ah, const __nv_bfloat16* __restrict__ Al,
    const __nv_bfloat16* __restrict__ Bh, const __nv_bfloat16* __restrict__ Bl,
    __nv_bfloat16* __restrict__ Qh, __nv_bfloat16* __restrict__ Ql, int K)
{
    GEMM_BODY(Ah, Al, Bh, Bl, K)
    #pragma unroll
    for (int mi = 0; mi < 4; mi++) {
        const int m = bm + wm * 64 + mi * 16 + (lane >> 2);   // token
        const int bb = m >> 11, ll = m & 2047;
        #pragma unroll
        for (int nj = 0; nj < 4; nj++) {
            const int n = bn + wn * 32 + nj * 8 + (lane & 3) * 2;
            const int part = n >> 10, rem = n & 1023, hh = rem >> 6, dd = rem & 63;
            const size_t off = (((size_t)(part * B_ + bb) * H_ + hh) * L_ + ll) * HD_ + dd;
            uint32_t hp, lp;
            split_pack2(acc[mi][nj][0], acc[mi][nj][1], hp, lp);
            *(uint32_t*)(Qh + off) = hp;
            *(uint32_t*)(Ql + off) = lp;
            split_pack2(acc[mi][nj][2], acc[mi][nj][3], hp, lp);
            *(uint32_t*)(Qh + off + (size_t)8 * HD_) = hp;
            *(uint32_t*)(Ql + off + (size_t)8 * HD_) = lp;
        }
    }
}

// ---------------------------------------------------------------------------
// Tensor-core causal flash attention (ldmatrix fragments) — unchanged from R7.
// ---------------------------------------------------------------------------
#define KSTR  72                         // smem row stride (bf16 elems)
#define AT_TILE  (64 * KSTR * 2)         // 9216 B per matrix tile
#define AT_STAGE (4 * AT_TILE)           // Kh,Kl,Vh,Vl
#define AT_SMEM  (2 * AT_STAGE)          // 73728 B

__global__ void __launch_bounds__(256, 2) attn_mma(
    const __nv_bfloat16* __restrict__ qkvh,
    const __nv_bfloat16* __restrict__ qkvl,
    __nv_bfloat16* __restrict__ ch, __nv_bfloat16* __restrict__ cl)
{
    extern __shared__ __align__(16) char smem[];
    const uint32_t sb = smem_u32(smem);
    const int tid = threadIdx.x, lane = tid & 31, warp = tid >> 5;
    const int qt = (int)gridDim.x - 1 - (int)blockIdx.x;   // long blocks first
    const int bh = blockIdx.y, b = bh >> 4, h = bh & 15;
    const int q0 = qt * 128;
    const size_t PART = (size_t)TOK * D_;
    const size_t headoff = (size_t)bh * L_ * HD_;
    const __nv_bfloat16* Qh = qkvh + headoff;
    const __nv_bfloat16* Ql = qkvl + headoff;
    const __nv_bfloat16* Kh = qkvh + PART + headoff;
    const __nv_bfloat16* Kl = qkvl + PART + headoff;
    const __nv_bfloat16* Vh = qkvh + 2 * PART + headoff;
    const __nv_bfloat16* Vl = qkvl + 2 * PART + headoff;

    const int r0 = q0 + warp * 16 + (lane >> 2);   // this lane's first row

    // Q fragments (hi/lo) from global, a-frag m16k16 layout, 4 k-steps
    uint32_t qfh[4][4], qfl[4][4];
    {
        const __nv_bfloat16* p0  = Qh + (size_t)r0 * HD_;
        const __nv_bfloat16* p8  = p0 + 8 * HD_;
        const __nv_bfloat16* p0l = Ql + (size_t)r0 * HD_;
        const __nv_bfloat16* p8l = p0l + 8 * HD_;
        #pragma unroll
        for (int t = 0; t < 4; t++) {
            const int d0 = t * 16 + 2 * (lane & 3);
            qfh[t][0] = *(const uint32_t*)(p0 + d0);
            qfh[t][1] = *(const uint32_t*)(p8 + d0);
            qfh[t][2] = *(const uint32_t*)(p0 + d0 + 8);
            qfh[t][3] = *(const uint32_t*)(p8 + d0 + 8);
            qfl[t][0] = *(const uint32_t*)(p0l + d0);
            qfl[t][1] = *(const uint32_t*)(p8l + d0);
            qfl[t][2] = *(const uint32_t*)(p0l + d0 + 8);
            qfl[t][3] = *(const uint32_t*)(p8l + d0 + 8);
        }
    }

    float Oa[8][4];
    #pragma unroll
    for (int j = 0; j < 8; j++)
        #pragma unroll
        for (int e = 0; e < 4; e++) Oa[j][e] = 0.0f;
    float m0 = -1e30f, m1 = -1e30f, l0 = 0.0f, l1 = 0.0f;

    const int ntiles = 2 * qt + 2;

    auto load_tile = [&](int kt, int stage) {
        const uint32_t dstbase = sb + stage * AT_STAGE;
        #pragma unroll
        for (int i = 0; i < 2; i++) {
            const int rem = tid + i * 256;          // 0..511
            const int row = rem >> 3, dch = rem & 7;
            const size_t g = (size_t)(kt * 64 + row) * HD_ + dch * 8;
            const uint32_t dof = dstbase + row * (KSTR * 2) + dch * 16;
            CP_ASYNC16(dof + 0 * AT_TILE, Kh + g);
            CP_ASYNC16(dof + 1 * AT_TILE, Kl + g);
            CP_ASYNC16(dof + 2 * AT_TILE, Vh + g);
            CP_ASYNC16(dof + 3 * AT_TILE, Vl + g);
        }
        CP_COMMIT();
    };

    load_tile(0, 0);

    for (int kt = 0; kt < ntiles; kt++) {
        const int stage = kt & 1;
        if (kt + 1 < ntiles) { load_tile(kt + 1, (kt + 1) & 1); CP_WAIT1(); }
        else                 { CP_WAIT0(); }
        __syncthreads();

        const int k0 = kt * 64;
        if (k0 <= q0 + warp * 16 + 15) {          // warp-uniform: any work?
            const uint32_t kbh = sb + stage * AT_STAGE;
            const uint32_t kbl = kbh + AT_TILE;
            const uint32_t vbh = kbh + 2 * AT_TILE;
            const uint32_t vbl = kbh + 3 * AT_TILE;

            // ---- S = Q K^T ----
            float Sa[8][4];
            #pragma unroll
            for (int j = 0; j < 8; j++)
                #pragma unroll
                for (int e = 0; e < 4; e++) Sa[j][e] = 0.0f;

            const uint32_t k_lro =
                (uint32_t)((((lane >> 4) << 3) + (lane & 7)) * KSTR +
                           ((lane >> 3) & 1) * 8) * 2;
            #pragma unroll
            for (int jp = 0; jp < 4; jp++) {
                const uint32_t no = (uint32_t)(jp * 16 * KSTR) * 2;
                #pragma unroll
                for (int t = 0; t < 4; t++) {
                    const uint32_t co = (uint32_t)(t * 16) * 2;
                    uint32_t kb4h[4], kb4l[4];
                    ldsm4(kb4h, kbh + no + k_lro + co);
                    ldsm4(kb4l, kbl + no + k_lro + co);
                    mma16816(Sa[2 * jp],     qfh[t], &kb4h[0]);
                    mma16816(Sa[2 * jp],     qfh[t], &kb4l[0]);
                    mma16816(Sa[2 * jp],     qfl[t], &kb4h[0]);
                    mma16816(Sa[2 * jp + 1], qfh[t], &kb4h[2]);
                    mma16816(Sa[2 * jp + 1], qfh[t], &kb4l[2]);
                    mma16816(Sa[2 * jp + 1], qfl[t], &kb4h[2]);
                }
            }

            // ---- scale + causal mask ----
            const bool needmask = (k0 + 63 > q0 + warp * 16);
            #pragma unroll
            for (int j = 0; j < 8; j++) {
                #pragma unroll
                for (int e = 0; e < 4; e++) Sa[j][e] *= 0.125f;
                if (needmask) {
                    const int key0 = k0 + j * 8 + 2 * (lane & 3);
                    if (key0     > r0)     Sa[j][0] = -1e30f;
                    if (key0 + 1 > r0)     Sa[j][1] = -1e30f;
                    if (key0     > r0 + 8) Sa[j][2] = -1e30f;
                    if (key0 + 1 > r0 + 8) Sa[j][3] = -1e30f;
                }
            }

            // ---- online softmax (2 rows per lane, quad reductions) ----
            float mx0 = -1e30f, mx1 = -1e30f;
            #pragma unroll
            for (int j = 0; j < 8; j++) {
                mx0 = fmaxf(mx0, fmaxf(Sa[j][0], Sa[j][1]));
                mx1 = fmaxf(mx1, fmaxf(Sa[j][2], Sa[j][3]));
            }
            mx0 = fmaxf(mx0, __shfl_xor_sync(0xffffffffu, mx0, 1));
            mx0 = fmaxf(mx0, __shfl_xor_sync(0xffffffffu, mx0, 2));
            mx1 = fmaxf(mx1, __shfl_xor_sync(0xffffffffu, mx1, 1));
            mx1 = fmaxf(mx1, __shfl_xor_sync(0xffffffffu, mx1, 2));
            const float mn0 = fmaxf(m0, mx0), mn1 = fmaxf(m1, mx1);
            const float a0 = __expf(m0 - mn0), a1 = __expf(m1 - mn1);
            m0 = mn0; m1 = mn1;
            float rs0 = 0.0f, rs1 = 0.0f;
            #pragma unroll
            for (int j = 0; j < 8; j++) {
                Sa[j][0] = __expf(Sa[j][0] - mn0); rs0 += Sa[j][0];
                Sa[j][1] = __expf(Sa[j][1] - mn0); rs0 += Sa[j][1];
                Sa[j][2] = __expf(Sa[j][2] - mn1); rs1 += Sa[j][2];
                Sa[j][3] = __expf(Sa[j][3] - mn1); rs1 += Sa[j][3];
            }
            rs0 += __shfl_xor_sync(0xffffffffu, rs0, 1);
            rs0 += __shfl_xor_sync(0xffffffffu, rs0, 2);
            rs1 += __shfl_xor_sync(0xffffffffu, rs1, 1);
            rs1 += __shfl_xor_sync(0xffffffffu, rs1, 2);
            l0 = l0 * a0 + rs0;
            l1 = l1 * a1 + rs1;
            #pragma unroll
            for (int j = 0; j < 8; j++) {
                Oa[j][0] *= a0; Oa[j][1] *= a0;
                Oa[j][2] *= a1; Oa[j][3] *= a1;
            }

            // ---- O += P V (P from accumulators; V frags via ldmatrix.trans) --
            const uint32_t v_lro =
                (uint32_t)((((lane >> 3) & 1) * 8 + (lane & 7)) * KSTR +
                           (lane >> 4) * 8) * 2;
            #pragma unroll
            for (int t = 0; t < 4; t++) {
                uint32_t ah[4], al[4];
                split_pack2(Sa[2 * t][0],     Sa[2 * t][1],     ah[0], al[0]);
                split_pack2(Sa[2 * t][2],     Sa[2 * t][3],     ah[1], al[1]);
                split_pack2(Sa[2 * t + 1][0], Sa[2 * t + 1][1], ah[2], al[2]);
                split_pack2(Sa[2 * t + 1][2], Sa[2 * t + 1][3], ah[3], al[3]);
                const uint32_t ro = (uint32_t)(t * 16 * KSTR) * 2;
                #pragma unroll
                for (int jp = 0; jp < 4; jp++) {
                    const uint32_t co = (uint32_t)(jp * 16) * 2;
                    uint32_t vh4[4], vl4[4];
                    ldsm4t(vh4, vbh + ro + v_lro + co);
                    ldsm4t(vl4, vbl + ro + v_lro + co);
                    mma16816(Oa[2 * jp],     ah, &vh4[0]);
                    mma16816(Oa[2 * jp],     ah, &vl4[0]);
                    mma16816(Oa[2 * jp],     al, &vh4[0]);
                    mma16816(Oa[2 * jp + 1], ah, &vh4[2]);
                    mma16816(Oa[2 * jp + 1], ah, &vl4[2]);
                    mma16816(Oa[2 * jp + 1], al, &vh4[2]);
                }
            }
        }
        __syncthreads();
    }

    // ---- finalize: write ctx hi/lo bf16 [tok][1024] ----
    const float inv0 = 1.0f / l0, inv1 = 1.0f / l1;
    const size_t row_off = (size_t)(b * L_ + r0) * D_ + h * 64;
    #pragma unroll
    for (int j = 0; j < 8; j++) {
        const int n = j * 8 + 2 * (lane & 3);
        uint32_t hp, lp;
        split_pack2(Oa[j][0] * inv0, Oa[j][1] * inv0, hp, lp);
        *(uint32_t*)(ch + row_off + n) = hp;
        *(uint32_t*)(cl + row_off + n) = lp;
        split_pack2(Oa[j][2] * inv1, Oa[j][3] * inv1, hp, lp);
        *(uint32_t*)(ch + row_off + (size_t)8 * D_ + n) = hp;
        *(uint32_t*)(cl + row_off + (size_t)8 * D_ + n) = lp;
    }
}

// ---------------------------------------------------------------------------
// kernel_launch — graph-capturable, allocation-free
// ---------------------------------------------------------------------------
extern "C" void kernel_launch(void* const* d_in, const int* in_sizes, int n_in,
                              void* d_out, int out_size)
{
    (void)in_sizes; (void)n_in; (void)out_size;
    const float* x     = (const float*)d_in[0];
    const float* w_qkv = (const float*)d_in[1];
    const float* w_out = (const float*)d_in[2];
    float* out = (float*)d_out;

    __nv_bfloat16 *xh, *xl, *wqh, *wql, *woh, *wol, *qh, *ql, *ch, *cl;
    cudaGetSymbolAddress((void**)&xh, g_xh);
    cudaGetSymbolAddress((void**)&xl, g_xl);
    cudaGetSymbolAddress((void**)&wqh, g_wqh);
    cudaGetSymbolAddress((void**)&wql, g_wql);
    cudaGetSymbolAddress((void**)&woh, g_woh);
    cudaGetSymbolAddress((void**)&wol, g_wol);
    cudaGetSymbolAddress((void**)&qh, g_qkvh);
    cudaGetSymbolAddress((void**)&ql, g_qkvl);
    cudaGetSymbolAddress((void**)&ch, g_ch);
    cudaGetSymbolAddress((void**)&cl, g_cl);

    cudaFuncSetAttribute(attn_mma,
                         cudaFuncAttributeMaxDynamicSharedMemorySize, AT_SMEM);
    cudaFuncSetAttribute(gemm_mma,
                         cudaFuncAttributeMaxDynamicSharedMemorySize, G_SMEM);
    cudaFuncSetAttribute(gemm_mma_qkv,
                         cudaFuncAttributeMaxDynamicSharedMemorySize, G_SMEM);

    // splits
    split_bf16<<<(TOK * D_) / 1024, 256>>>(x, xh, xl, (TOK * D_) / 4);
    split_bf16<<<(3 * D_ * D_) / 1024, 256>>>(w_qkv, wqh, wql, (3 * D_ * D_) / 4);
    split_bf16<<<(D_ * D_) / 1024, 256>>>(w_out, woh, wol, (D_ * D_) / 4);

    // 1) QKV projection -> split bf16 head-major qkv
    {
        dim3 grid(3 * D_ / 128, TOK / 128);
        gemm_mma_qkv<<<grid, 256, G_SMEM>>>(xh, xl, wqh, wql, qh, ql, D_);
    }
    // 2) tensor-core flash attention -> split bf16 ctx
    {
        dim3 grid(L_ / 128, B_ * H_);
        attn_mma<<<grid, 256, AT_SMEM>>>(qh, ql, ch, cl);
    }
    // 3) output projection
    {
        dim3 grid(D_ / 128, TOK / 128);
        gemm_mma<<<grid, 256, G_SMEM>>>(ch, cl, woh, wol, out, D_, D_);
    }
}

// round 10
// speedup vs baseline: 1.1397x; 1.1397x over previous
#include <cuda_runtime.h>
#include <cuda_bf16.h>
#include <cstdint>
#include <cstddef>

// Problem constants
#define B_   2
#define L_   2048
#define D_   1024
#define H_   16
#define HD_  64
#define TOK  (B_ * L_)          // 4096 tokens

// ---------------------------------------------------------------------------
// Scratch (__device__ globals; no cudaMalloc allowed)
// ---------------------------------------------------------------------------
__device__ float g_scale[4];    // abs-max: [0]=x, [1]=w_qkv, [2]=w_out, [3]=ctx
__device__ __align__(16) int8_t g_x1[(size_t)TOK * D_];
__device__ __align__(16) int8_t g_x2[(size_t)TOK * D_];
__device__ __align__(16) int8_t g_wq1[(size_t)3 * D_ * D_];
__device__ __align__(16) int8_t g_wq2[(size_t)3 * D_ * D_];
__device__ __align__(16) int8_t g_wo1[(size_t)D_ * D_];
__device__ __align__(16) int8_t g_wo2[(size_t)D_ * D_];
__device__ __align__(16) int8_t g_c1[(size_t)TOK * D_];
__device__ __align__(16) int8_t g_c2[(size_t)TOK * D_];
// head-major split qkv for attention: [part(q/k/v)][b][h][l][64] bf16 hi/lo
__device__ __align__(16) __nv_bfloat16 g_qkvh[(size_t)3 * TOK * D_];
__device__ __align__(16) __nv_bfloat16 g_qkvl[(size_t)3 * TOK * D_];
// attention context fp32 [tok][1024]
__device__ __align__(16) float g_ctx[(size_t)TOK * D_];

// ---------------------------------------------------------------------------
// Helpers
// ---------------------------------------------------------------------------
__device__ __forceinline__ uint32_t smem_u32(const void* p) {
    uint32_t a;
    asm("{ .reg .u64 t; cvta.to.shared.u64 t, %1; cvt.u32.u64 %0, t; }" : "=r"(a) : "l"(p));
    return a;
}

__device__ __forceinline__ void mma16816(float* c, const uint32_t* a, const uint32_t* b) {
    asm volatile("mma.sync.aligned.m16n8k16.row.col.f32.bf16.bf16.f32 "
                 "{%0,%1,%2,%3}, {%4,%5,%6,%7}, {%8,%9}, {%0,%1,%2,%3};"
                 : "+f"(c[0]), "+f"(c[1]), "+f"(c[2]), "+f"(c[3])
                 : "r"(a[0]), "r"(a[1]), "r"(a[2]), "r"(a[3]),
                   "r"(b[0]), "r"(b[1]));
}

__device__ __forceinline__ void mma_i8(int* c, const uint32_t* a, const uint32_t* b) {
    asm volatile("mma.sync.aligned.m16n8k32.row.col.s32.s8.s8.s32 "
                 "{%0,%1,%2,%3}, {%4,%5,%6,%7}, {%8,%9}, {%0,%1,%2,%3};"
                 : "+r"(c[0]), "+r"(c[1]), "+r"(c[2]), "+r"(c[3])
                 : "r"(a[0]), "r"(a[1]), "r"(a[2]), "r"(a[3]),
                   "r"(b[0]), "r"(b[1]));
}

__device__ __forceinline__ void ldsm4(uint32_t* r, uint32_t addr) {
    asm volatile("ldmatrix.sync.aligned.m8n8.x4.shared.b16 {%0,%1,%2,%3}, [%4];"
                 : "=r"(r[0]), "=r"(r[1]), "=r"(r[2]), "=r"(r[3]) : "r"(addr));
}
__device__ __forceinline__ void ldsm4t(uint32_t* r, uint32_t addr) {
    asm volatile("ldmatrix.sync.aligned.m8n8.x4.trans.shared.b16 {%0,%1,%2,%3}, [%4];"
                 : "=r"(r[0]), "=r"(r[1]), "=r"(r[2]), "=r"(r[3]) : "r"(addr));
}

__device__ __forceinline__ uint32_t pack_bf(__nv_bfloat16 lo, __nv_bfloat16 hi) {
    return (uint32_t)__bfloat16_as_ushort(lo) | ((uint32_t)__bfloat16_as_ushort(hi) << 16);
}
__device__ __forceinline__ void split_pack2(float x, float y, uint32_t& hp, uint32_t& lp) {
    __nv_bfloat16 hx = __float2bfloat16(x), hy = __float2bfloat16(y);
    __nv_bfloat16 lx = __float2bfloat16(x - __bfloat162float(hx));
    __nv_bfloat16 ly = __float2bfloat16(y - __bfloat162float(hy));
    hp = pack_bf(hx, hy);
    lp = pack_bf(lx, ly);
}

#define CP_ASYNC16(dst, src) \
    asm volatile("cp.async.cg.shared.global [%0], [%1], 16;" :: "r"(dst), "l"(src) : "memory")
#define CP_COMMIT() asm volatile("cp.async.commit_group;" ::: "memory")
#define CP_WAIT2()  asm volatile("cp.async.wait_group 2;" ::: "memory")
#define CP_WAIT1()  asm volatile("cp.async.wait_group 1;" ::: "memory")
#define CP_WAIT0()  asm volatile("cp.async.wait_group 0;" ::: "memory")

// ---------------------------------------------------------------------------
// Scale / quantization kernels
// ---------------------------------------------------------------------------
__global__ void scale_init() {
    if (threadIdx.x < 4) g_scale[threadIdx.x] = 0.0f;
}

__global__ void __launch_bounds__(256) absmax_k(
    const float4* __restrict__ in, int n4, float* __restrict__ out)
{
    float m = 0.0f;
    for (int i = blockIdx.x * 256 + threadIdx.x; i < n4; i += gridDim.x * 256) {
        float4 v = in[i];
        m = fmaxf(m, fmaxf(fmaxf(fabsf(v.x), fabsf(v.y)),
                           fmaxf(fabsf(v.z), fabsf(v.w))));
    }
    #pragma unroll
    for (int o = 16; o; o >>= 1) m = fmaxf(m, __shfl_xor_sync(0xffffffffu, m, o));
    if ((threadIdx.x & 31) == 0)
        atomicMax((unsigned int*)out, __float_as_uint(m));
}

// two-level int8 quant: x = s/127*(Q1 + Q2/254), |err| <= s/(127*254*2)
__global__ void __launch_bounds__(256) quant8_k(
    const float4* __restrict__ in, char4* __restrict__ q1,
    char4* __restrict__ q2, const float* __restrict__ sp, int n4)
{
    int i = blockIdx.x * 256 + threadIdx.x;
    if (i >= n4) return;
    const float s = fmaxf(__ldg(sp), 1e-20f);
    const float k = 127.0f / s;
    float4 v = in[i];
    float u0 = v.x * k, u1 = v.y * k, u2 = v.z * k, u3 = v.w * k;
    float a0 = rintf(u0), a1 = rintf(u1), a2 = rintf(u2), a3 = rintf(u3);
    float b0 = rintf((u0 - a0) * 254.0f), b1 = rintf((u1 - a1) * 254.0f);
    float b2 = rintf((u2 - a2) * 254.0f), b3 = rintf((u3 - a3) * 254.0f);
    q1[i] = make_char4((int)a0, (int)a1, (int)a2, (int)a3);
    q2[i] = make_char4((int)b0, (int)b1, (int)b2, (int)b3);
}

// ---------------------------------------------------------------------------
// int8 GEMM (EXACT 4-term): C = sA*sB/127^2 *
//     (A1B1 + (A1B2 + A2B1)/254 + A2B2/254^2),   A[M,K] * B[N,K]^T.
// CTA tile 64x128, BK=32 bytes, 256 threads (8 warps 2x4), warp tile 32x32,
// 4-stage cp.async pipeline, ldmatrix fragments.
// Smem row stride 48B: 12r mod 32 covers all banks -> conflict-free LDSM.
// ---------------------------------------------------------------------------
#define ISROW   48
#define IT_A    (64 * ISROW)             // 3072
#define IT_B    (128 * ISROW)            // 6144
#define I_STAGE (2 * IT_A + 2 * IT_B)    // 18432
#define I_SMEM  (4 * I_STAGE)            // 73728

#define GEMM_I8_BODY(A1p, A2p, B1p, B2p, K)                                    \
    extern __shared__ __align__(16) char smemraw[];                            \
    const uint32_t sb = smem_u32(smemraw);                                     \
    const int tid = threadIdx.x, lane = tid & 31, warp = tid >> 5;             \
    const int wm = warp >> 2, wn = warp & 3;                                   \
    const int bm = blockIdx.y * 64, bn = blockIdx.x * 128;                     \
    int acc1[2][4][4], accX[2][4][4], acc2[2][4][4];                           \
    _Pragma("unroll")                                                          \
    for (int i = 0; i < 2; i++)                                                \
        _Pragma("unroll")                                                      \
        for (int j = 0; j < 4; j++)                                            \
            _Pragma("unroll")                                                  \
            for (int e = 0; e < 4; e++) {                                      \
                acc1[i][j][e] = 0; accX[i][j][e] = 0; acc2[i][j][e] = 0;       \
            }                                                                  \
    const int nk = K / 32;                                                     \
    auto load_st = [&](int kt, int st) {                                       \
        const uint32_t base = sb + st * I_STAGE;                               \
        const int ko = kt * 32;                                                \
        _Pragma("unroll")                                                      \
        for (int i = 0; i < 3; i++) {                                          \
            const int idx = tid + i * 256;     /* 0..767 */                    \
            uint32_t dst; const int8_t* src;                                   \
            if (idx < 256) {                                                   \
                const int var = idx >> 7, rem = idx & 127;                     \
                const int row = rem >> 1, seg = rem & 1;                       \
                dst = base + var * IT_A + row * ISROW + seg * 16;              \
                src = (var == 0 ? A1p : A2p) +                                 \
                      (size_t)(bm + row) * K + ko + seg * 16;                  \
            } else {                                                           \
                const int j2 = idx - 256;                                      \
                const int var = j2 >> 8, rem = j2 & 255;                       \
                const int row = rem >> 1, seg = rem & 1;                       \
                dst = base + 2 * IT_A + var * IT_B + row * ISROW + seg * 16;   \
                src = (var == 0 ? B1p : B2p) +                                 \
                      (size_t)(bn + row) * K + ko + seg * 16;                  \
            }                                                                  \
            CP_ASYNC16(dst, src);                                              \
        }                                                                      \
        CP_COMMIT();                                                           \
    };                                                                         \
    load_st(0, 0); load_st(1, 1); load_st(2, 2);                               \
    for (int kt = 0; kt < nk; kt++) {                                          \
        const int st = kt & 3;                                                 \
        if (kt + 2 < nk)      { CP_WAIT2(); }                                  \
        else if (kt + 1 < nk) { CP_WAIT1(); }                                  \
        else                  { CP_WAIT0(); }                                  \
        __syncthreads();                                                       \
        if (kt + 3 < nk) load_st(kt + 3, (kt + 3) & 3);                        \
        const uint32_t aT = sb + st * I_STAGE;                                 \
        const uint32_t a_lro = (uint32_t)((lane & 15) * ISROW + (lane >> 4) * 16); \
        const uint32_t b_lro = (uint32_t)((((lane >> 4) << 3) + (lane & 7)) * ISROW + \
                                          ((lane >> 3) & 1) * 16);             \
        uint32_t f1[2][4], f2[2][4], gB1[2][4], gB2[2][4];                     \
        _Pragma("unroll")                                                      \
        for (int mi = 0; mi < 2; mi++) {                                       \
            const uint32_t mo = (uint32_t)((wm * 32 + mi * 16) * ISROW);       \
            ldsm4(f1[mi], aT + 0 * IT_A + mo + a_lro);                         \
            ldsm4(f2[mi], aT + 1 * IT_A + mo + a_lro);                         \
        }                                                                      \
        _Pragma("unroll")                                                      \
        for (int np = 0; np < 2; np++) {                                       \
            const uint32_t no = (uint32_t)((wn * 32 + np * 16) * ISROW);       \
            ldsm4(gB1[np], aT + 2 * IT_A + no + b_lro);                        \
            ldsm4(gB2[np], aT + 2 * IT_A + IT_B + no + b_lro);                 \
        }                                                                      \
        _Pragma("unroll")                                                      \
        for (int mi = 0; mi < 2; mi++)                                         \
            _Pragma("unroll")                                                  \
            for (int nj = 0; nj < 4; nj++)                                     \
                mma_i8(acc1[mi][nj], f1[mi], &gB1[nj >> 1][(nj & 1) * 2]);     \
        _Pragma("unroll")                                                      \
        for (int mi = 0; mi < 2; mi++)                                         \
            _Pragma("unroll")                                                  \
            for (int nj = 0; nj < 4; nj++)                                     \
                mma_i8(accX[mi][nj], f1[mi], &gB2[nj >> 1][(nj & 1) * 2]);     \
        _Pragma("unroll")                                                      \
        for (int mi = 0; mi < 2; mi++)                                         \
            _Pragma("unroll")                                                  \
            for (int nj = 0; nj < 4; nj++)                                     \
                mma_i8(accX[mi][nj], f2[mi], &gB1[nj >> 1][(nj & 1) * 2]);     \
        _Pragma("unroll")                                                      \
        for (int mi = 0; mi < 2; mi++)                                         \
            _Pragma("unroll")                                                  \
            for (int nj = 0; nj < 4; nj++)                                     \
                mma_i8(acc2[mi][nj], f2[mi], &gB2[nj >> 1][(nj & 1) * 2]);     \
    }

#define DEQ(mi, nj, e) \
    (fsc * ((float)acc1[mi][nj][e] + (float)accX[mi][nj][e] * (1.0f / 254.0f) \
            + (float)acc2[mi][nj][e] * (1.0f / 64516.0f)))

// QKV projection: dequant + split bf16 head-major writeout
__global__ void __launch_bounds__(256) gemm_i8_qkv(
    const int8_t* __restrict__ A1p, const int8_t* __restrict__ A2p,
    const int8_t* __restrict__ B1p, const int8_t* __restrict__ B2p,
    const float* __restrict__ sap, const float* __restrict__ sbp,
    __nv_bfloat16* __restrict__ Qh, __nv_bfloat16* __restrict__ Ql, int K)
{
    GEMM_I8_BODY(A1p, A2p, B1p, B2p, K)
    const float fsc = __ldg(sap) * __ldg(sbp) * (1.0f / 16129.0f);
    #pragma unroll
    for (int mi = 0; mi < 2; mi++) {
        const int m = bm + wm * 32 + mi * 16 + (lane >> 2);   // token
        const int bb = m >> 11, ll = m & 2047;
        #pragma unroll
        for (int nj = 0; nj < 4; nj++) {
            const int n = bn + wn * 32 + nj * 8 + (lane & 3) * 2;
            const int part = n >> 10, rem = n & 1023, hh = rem >> 6, dd = rem & 63;
            const size_t off = (((size_t)(part * B_ + bb) * H_ + hh) * L_ + ll) * HD_ + dd;
            uint32_t hp, lp;
            split_pack2(DEQ(mi, nj, 0), DEQ(mi, nj, 1), hp, lp);
            *(uint32_t*)(Qh + off) = hp;
            *(uint32_t*)(Ql + off) = lp;
            split_pack2(DEQ(mi, nj, 2), DEQ(mi, nj, 3), hp, lp);
            *(uint32_t*)(Qh + off + (size_t)8 * HD_) = hp;
            *(uint32_t*)(Ql + off + (size_t)8 * HD_) = lp;
        }
    }
}

// Output projection: dequant + fp32 row-major C[M,N]
__global__ void __launch_bounds__(256) gemm_i8_out(
    const int8_t* __restrict__ A1p, const int8_t* __restrict__ A2p,
    const int8_t* __restrict__ B1p, const int8_t* __restrict__ B2p,
    const float* __restrict__ sap, const float* __restrict__ sbp,
    float* __restrict__ C, int N, int K)
{
    GEMM_I8_BODY(A1p, A2p, B1p, B2p, K)
    const float fsc = __ldg(sap) * __ldg(sbp) * (1.0f / 16129.0f);
    #pragma unroll
    for (int mi = 0; mi < 2; mi++) {
        const int m = bm + wm * 32 + mi * 16 + (lane >> 2);
        #pragma unroll
        for (int nj = 0; nj < 4; nj++) {
            const int n = bn + wn * 32 + nj * 8 + (lane & 3) * 2;
            *(float2*)(C + (size_t)m * N + n)       = make_float2(DEQ(mi, nj, 0), DEQ(mi, nj, 1));
            *(float2*)(C + (size_t)(m + 8) * N + n) = make_float2(DEQ(mi, nj, 2), DEQ(mi, nj, 3));
        }
    }
}

// ---------------------------------------------------------------------------
// Tensor-core causal flash attention (bf16 3-term, ldmatrix) — proven kernel,
// fp32 ctx epilogue.
// ---------------------------------------------------------------------------
#define KSTR  72
#define AT_TILE  (64 * KSTR * 2)
#define AT_STAGE (4 * AT_TILE)
#define AT_SMEM  (2 * AT_STAGE)          // 73728 B

__global__ void __launch_bounds__(256, 2) attn_mma(
    const __nv_bfloat16* __restrict__ qkvh,
    const __nv_bfloat16* __restrict__ qkvl,
    float* __restrict__ ctx)
{
    extern __shared__ __align__(16) char smem[];
    const uint32_t sb = smem_u32(smem);
    const int tid = threadIdx.x, lane = tid & 31, warp = tid >> 5;
    const int qt = (int)gridDim.x - 1 - (int)blockIdx.x;
    const int bh = blockIdx.y, b = bh >> 4, h = bh & 15;
    const int q0 = qt * 128;
    const size_t PART = (size_t)TOK * D_;
    const size_t headoff = (size_t)bh * L_ * HD_;
    const __nv_bfloat16* Qh = qkvh + headoff;
    const __nv_bfloat16* Ql = qkvl + headoff;
    const __nv_bfloat16* Kh = qkvh + PART + headoff;
    const __nv_bfloat16* Kl = qkvl + PART + headoff;
    const __nv_bfloat16* Vh = qkvh + 2 * PART + headoff;
    const __nv_bfloat16* Vl = qkvl + 2 * PART + headoff;

    const int r0 = q0 + warp * 16 + (lane >> 2);

    uint32_t qfh[4][4], qfl[4][4];
    {
        const __nv_bfloat16* p0  = Qh + (size_t)r0 * HD_;
        const __nv_bfloat16* p8  = p0 + 8 * HD_;
        const __nv_bfloat16* p0l = Ql + (size_t)r0 * HD_;
        const __nv_bfloat16* p8l = p0l + 8 * HD_;
        #pragma unroll
        for (int t = 0; t < 4; t++) {
            const int d0 = t * 16 + 2 * (lane & 3);
            qfh[t][0] = *(const uint32_t*)(p0 + d0);
            qfh[t][1] = *(const uint32_t*)(p8 + d0);
            qfh[t][2] = *(const uint32_t*)(p0 + d0 + 8);
            qfh[t][3] = *(const uint32_t*)(p8 + d0 + 8);
            qfl[t][0] = *(const uint32_t*)(p0l + d0);
            qfl[t][1] = *(const uint32_t*)(p8l + d0);
            qfl[t][2] = *(const uint32_t*)(p0l + d0 + 8);
            qfl[t][3] = *(const uint32_t*)(p8l + d0 + 8);
        }
    }

    float Oa[8][4];
    #pragma unroll
    for (int j = 0; j < 8; j++)
        #pragma unroll
        for (int e = 0; e < 4; e++) Oa[j][e] = 0.0f;
    float m0 = -1e30f, m1 = -1e30f, l0 = 0.0f, l1 = 0.0f;

    const int ntiles = 2 * qt + 2;

    auto load_tile = [&](int kt, int stage) {
        const uint32_t dstbase = sb + stage * AT_STAGE;
        #pragma unroll
        for (int i = 0; i < 2; i++) {
            const int rem = tid + i * 256;
            const int row = rem >> 3, dch = rem & 7;
            const size_t g = (size_t)(kt * 64 + row) * HD_ + dch * 8;
            const uint32_t dof = dstbase + row * (KSTR * 2) + dch * 16;
            CP_ASYNC16(dof + 0 * AT_TILE, Kh + g);
            CP_ASYNC16(dof + 1 * AT_TILE, Kl + g);
            CP_ASYNC16(dof + 2 * AT_TILE, Vh + g);
            CP_ASYNC16(dof + 3 * AT_TILE, Vl + g);
        }
        CP_COMMIT();
    };

    load_tile(0, 0);

    for (int kt = 0; kt < ntiles; kt++) {
        const int stage = kt & 1;
        if (kt + 1 < ntiles) { load_tile(kt + 1, (kt + 1) & 1); CP_WAIT1(); }
        else                 { CP_WAIT0(); }
        __syncthreads();

        const int k0 = kt * 64;
        if (k0 <= q0 + warp * 16 + 15) {
            const uint32_t kbh = sb + stage * AT_STAGE;
            const uint32_t kbl = kbh + AT_TILE;
            const uint32_t vbh = kbh + 2 * AT_TILE;
            const uint32_t vbl = kbh + 3 * AT_TILE;

            float Sa[8][4];
            #pragma unroll
            for (int j = 0; j < 8; j++)
                #pragma unroll
                for (int e = 0; e < 4; e++) Sa[j][e] = 0.0f;

            const uint32_t k_lro =
                (uint32_t)((((lane >> 4) << 3) + (lane & 7)) * KSTR +
                           ((lane >> 3) & 1) * 8) * 2;
            #pragma unroll
            for (int jp = 0; jp < 4; jp++) {
                const uint32_t no = (uint32_t)(jp * 16 * KSTR) * 2;
                #pragma unroll
                for (int t = 0; t < 4; t++) {
                    const uint32_t co = (uint32_t)(t * 16) * 2;
                    uint32_t kb4h[4], kb4l[4];
                    ldsm4(kb4h, kbh + no + k_lro + co);
                    ldsm4(kb4l, kbl + no + k_lro + co);
                    mma16816(Sa[2 * jp],     qfh[t], &kb4h[0]);
                    mma16816(Sa[2 * jp],     qfh[t], &kb4l[0]);
                    mma16816(Sa[2 * jp],     qfl[t], &kb4h[0]);
                    mma16816(Sa[2 * jp + 1], qfh[t], &kb4h[2]);
                    mma16816(Sa[2 * jp + 1], qfh[t], &kb4l[2]);
                    mma16816(Sa[2 * jp + 1], qfl[t], &kb4h[2]);
                }
            }

            const bool needmask = (k0 + 63 > q0 + warp * 16);
            #pragma unroll
            for (int j = 0; j < 8; j++) {
                #pragma unroll
                for (int e = 0; e < 4; e++) Sa[j][e] *= 0.125f;
                if (needmask) {
                    const int key0 = k0 + j * 8 + 2 * (lane & 3);
                    if (key0     > r0)     Sa[j][0] = -1e30f;
                    if (key0 + 1 > r0)     Sa[j][1] = -1e30f;
                    if (key0     > r0 + 8) Sa[j][2] = -1e30f;
                    if (key0 + 1 > r0 + 8) Sa[j][3] = -1e30f;
                }
            }

            float mx0 = -1e30f, mx1 = -1e30f;
            #pragma unroll
            for (int j = 0; j < 8; j++) {
                mx0 = fmaxf(mx0, fmaxf(Sa[j][0], Sa[j][1]));
                mx1 = fmaxf(mx1, fmaxf(Sa[j][2], Sa[j][3]));
            }
            mx0 = fmaxf(mx0, __shfl_xor_sync(0xffffffffu, mx0, 1));
            mx0 = fmaxf(mx0, __shfl_xor_sync(0xffffffffu, mx0, 2));
            mx1 = fmaxf(mx1, __shfl_xor_sync(0xffffffffu, mx1, 1));
            mx1 = fmaxf(mx1, __shfl_xor_sync(0xffffffffu, mx1, 2));
            const float mn0 = fmaxf(m0, mx0), mn1 = fmaxf(m1, mx1);
            const float a0 = __expf(m0 - mn0), a1 = __expf(m1 - mn1);
            m0 = mn0; m1 = mn1;
            float rs0 = 0.0f, rs1 = 0.0f;
            #pragma unroll
            for (int j = 0; j < 8; j++) {
                Sa[j][0] = __expf(Sa[j][0] - mn0); rs0 += Sa[j][0];
                Sa[j][1] = __expf(Sa[j][1] - mn0); rs0 += Sa[j][1];
                Sa[j][2] = __expf(Sa[j][2] - mn1); rs1 += Sa[j][2];
                Sa[j][3] = __expf(Sa[j][3] - mn1); rs1 += Sa[j][3];
            }
            rs0 += __shfl_xor_sync(0xffffffffu, rs0, 1);
            rs0 += __shfl_xor_sync(0xffffffffu, rs0, 2);
            rs1 += __shfl_xor_sync(0xffffffffu, rs1, 1);
            rs1 += __shfl_xor_sync(0xffffffffu, rs1, 2);
            l0 = l0 * a0 + rs0;
            l1 = l1 * a1 + rs1;
            #pragma unroll
            for (int j = 0; j < 8; j++) {
                Oa[j][0] *= a0; Oa[j][1] *= a0;
                Oa[j][2] *= a1; Oa[j][3] *= a1;
            }

            const uint32_t v_lro =
                (uint32_t)((((lane >> 3) & 1) * 8 + (lane & 7)) * KSTR +
                           (lane >> 4) * 8) * 2;
            #pragma unroll
            for (int t = 0; t < 4; t++) {
                uint32_t ah[4], al[4];
                split_pack2(Sa[2 * t][0],     Sa[2 * t][1],     ah[0], al[0]);
                split_pack2(Sa[2 * t][2],     Sa[2 * t][3],     ah[1], al[1]);
                split_pack2(Sa[2 * t + 1][0], Sa[2 * t + 1][1], ah[2], al[2]);
                split_pack2(Sa[2 * t + 1][2], Sa[2 * t + 1][3], ah[3], al[3]);
                const uint32_t ro = (uint32_t)(t * 16 * KSTR) * 2;
                #pragma unroll
                for (int jp = 0; jp < 4; jp++) {
                    const uint32_t co = (uint32_t)(jp * 16) * 2;
                    uint32_t vh4[4], vl4[4];
                    ldsm4t(vh4, vbh + ro + v_lro + co);
                    ldsm4t(vl4, vbl + ro + v_lro + co);
                    mma16816(Oa[2 * jp],     ah, &vh4[0]);
                    mma16816(Oa[2 * jp],     ah, &vl4[0]);
                    mma16816(Oa[2 * jp],     al, &vh4[0]);
                    mma16816(Oa[2 * jp + 1], ah, &vh4[2]);
                    mma16816(Oa[2 * jp + 1], ah, &vl4[2]);
                    mma16816(Oa[2 * jp + 1], al, &vh4[2]);
                }
            }
        }
        __syncthreads();
    }

    // ---- finalize: write fp32 ctx [tok][1024] ----
    const float inv0 = 1.0f / l0, inv1 = 1.0f / l1;
    const size_t row_off = (size_t)(b * L_ + r0) * D_ + h * 64;
    #pragma unroll
    for (int j = 0; j < 8; j++) {
        const int n = j * 8 + 2 * (lane & 3);
        *(float2*)(ctx + row_off + n) =
            make_float2(Oa[j][0] * inv0, Oa[j][1] * inv0);
        *(float2*)(ctx + row_off + (size_t)8 * D_ + n) =
            make_float2(Oa[j][2] * inv1, Oa[j][3] * inv1);
    }
}

// ---------------------------------------------------------------------------
// kernel_launch — graph-capturable, allocation-free
// ---------------------------------------------------------------------------
extern "C" void kernel_launch(void* const* d_in, const int* in_sizes, int n_in,
                              void* d_out, int out_size)
{
    (void)in_sizes; (void)n_in; (void)out_size;
    const float* x     = (const float*)d_in[0];
    const float* w_qkv = (const float*)d_in[1];
    const float* w_out = (const float*)d_in[2];
    float* out = (float*)d_out;

    int8_t *x1, *x2, *wq1, *wq2, *wo1, *wo2, *c1, *c2;
    __nv_bfloat16 *qh, *ql;
    float *ctx, *sc;
    cudaGetSymbolAddress((void**)&x1, g_x1);
    cudaGetSymbolAddress((void**)&x2, g_x2);
    cudaGetSymbolAddress((void**)&wq1, g_wq1);
    cudaGetSymbolAddress((void**)&wq2, g_wq2);
    cudaGetSymbolAddress((void**)&wo1, g_wo1);
    cudaGetSymbolAddress((void**)&wo2, g_wo2);
    cudaGetSymbolAddress((void**)&c1, g_c1);
    cudaGetSymbolAddress((void**)&c2, g_c2);
    cudaGetSymbolAddress((void**)&qh, g_qkvh);
    cudaGetSymbolAddress((void**)&ql, g_qkvl);
    cudaGetSymbolAddress((void**)&ctx, g_ctx);
    cudaGetSymbolAddress((void**)&sc, g_scale);

    cudaFuncSetAttribute(attn_mma,
                         cudaFuncAttributeMaxDynamicSharedMemorySize, AT_SMEM);
    cudaFuncSetAttribute(gemm_i8_qkv,
                         cudaFuncAttributeMaxDynamicSharedMemorySize, I_SMEM);
    cudaFuncSetAttribute(gemm_i8_out,
                         cudaFuncAttributeMaxDynamicSharedMemorySize, I_SMEM);

    const int n4_x  = TOK * D_ / 4;          // 1M
    const int n4_wq = 3 * D_ * D_ / 4;       // 768K
    const int n4_wo = D_ * D_ / 4;           // 256K

    auto gmax = [](int n4) { int g = (n4 + 255) / 256; return g > 2048 ? 2048 : g; };

    // scales + quantization of inputs/weights
    scale_init<<<1, 4>>>();
    absmax_k<<<gmax(n4_x), 256>>>((const float4*)x, n4_x, sc + 0);
    absmax_k<<<gmax(n4_wq), 256>>>((const float4*)w_qkv, n4_wq, sc + 1);
    absmax_k<<<gmax(n4_wo), 256>>>((const float4*)w_out, n4_wo, sc + 2);
    quant8_k<<<(n4_x + 255) / 256, 256>>>((const float4*)x, (char4*)x1, (char4*)x2, sc + 0, n4_x);
    quant8_k<<<(n4_wq + 255) / 256, 256>>>((const float4*)w_qkv, (char4*)wq1, (char4*)wq2, sc + 1, n4_wq);
    quant8_k<<<(n4_wo + 255) / 256, 256>>>((const float4*)w_out, (char4*)wo1, (char4*)wo2, sc + 2, n4_wo);

    // 1) QKV projection (int8, exact 4-term) -> split bf16 head-major qkv
    {
        dim3 grid(3 * D_ / 128, TOK / 64);
        gemm_i8_qkv<<<grid, 256, I_SMEM>>>(x1, x2, wq1, wq2, sc + 0, sc + 1, qh, ql, D_);
    }
    // 2) tensor-core flash attention (bf16) -> fp32 ctx
    {
        dim3 grid(L_ / 128, B_ * H_);
        attn_mma<<<grid, 256, AT_SMEM>>>(qh, ql, ctx);
    }
    // 3) quantize ctx, output projection (int8, exact 4-term) -> fp32 out
    absmax_k<<<gmax(n4_x), 256>>>((const float4*)ctx, n4_x, sc + 3);
    quant8_k<<<(n4_x + 255) / 256, 256>>>((const float4*)ctx, (char4*)c1, (char4*)c2, sc + 3, n4_x);
    {
        dim3 grid(D_ / 128, TOK / 64);
        gemm_i8_out<<<grid, 256, I_SMEM>>>(c1, c2, wo1, wo2, sc + 3, sc + 2, out, D_, D_);
    }
}

// round 11
// speedup vs baseline: 1.2304x; 1.0796x over previous
#include <cuda_runtime.h>
#include <cuda_bf16.h>
#include <cstdint>
#include <cstddef>

// Problem constants
#define B_   2
#define L_   2048
#define D_   1024
#define H_   16
#define HD_  64
#define TOK  (B_ * L_)          // 4096 tokens

// ---------------------------------------------------------------------------
// Scratch (__device__ globals; no cudaMalloc allowed)
// ---------------------------------------------------------------------------
__device__ __align__(16) int8_t g_x1[(size_t)TOK * D_];
__device__ __align__(16) int8_t g_x2[(size_t)TOK * D_];
__device__ __align__(16) int8_t g_wq1[(size_t)3 * D_ * D_];
__device__ __align__(16) int8_t g_wq2[(size_t)3 * D_ * D_];
__device__ __align__(16) int8_t g_wo1[(size_t)D_ * D_];
__device__ __align__(16) int8_t g_wo2[(size_t)D_ * D_];
__device__ __align__(16) int8_t g_c1[(size_t)TOK * D_];
__device__ __align__(16) int8_t g_c2[(size_t)TOK * D_];
// per-row quantization scales
__device__ float g_rsx[TOK];
__device__ float g_rswq[3 * D_];
__device__ float g_rswo[D_];
__device__ float g_rsc[TOK];
// head-major split qkv for attention: [part(q/k/v)][b][h][l][64] bf16 hi/lo
__device__ __align__(16) __nv_bfloat16 g_qkvh[(size_t)3 * TOK * D_];
__device__ __align__(16) __nv_bfloat16 g_qkvl[(size_t)3 * TOK * D_];
// attention context fp32 [tok][1024]
__device__ __align__(16) float g_ctx[(size_t)TOK * D_];

// ---------------------------------------------------------------------------
// Helpers
// ---------------------------------------------------------------------------
__device__ __forceinline__ uint32_t smem_u32(const void* p) {
    uint32_t a;
    asm("{ .reg .u64 t; cvta.to.shared.u64 t, %1; cvt.u32.u64 %0, t; }" : "=r"(a) : "l"(p));
    return a;
}

__device__ __forceinline__ void mma16816(float* c, const uint32_t* a, const uint32_t* b) {
    asm volatile("mma.sync.aligned.m16n8k16.row.col.f32.bf16.bf16.f32 "
                 "{%0,%1,%2,%3}, {%4,%5,%6,%7}, {%8,%9}, {%0,%1,%2,%3};"
                 : "+f"(c[0]), "+f"(c[1]), "+f"(c[2]), "+f"(c[3])
                 : "r"(a[0]), "r"(a[1]), "r"(a[2]), "r"(a[3]),
                   "r"(b[0]), "r"(b[1]));
}

__device__ __forceinline__ void mma_i8(int* c, const uint32_t* a, const uint32_t* b) {
    asm volatile("mma.sync.aligned.m16n8k32.row.col.s32.s8.s8.s32 "
                 "{%0,%1,%2,%3}, {%4,%5,%6,%7}, {%8,%9}, {%0,%1,%2,%3};"
                 : "+r"(c[0]), "+r"(c[1]), "+r"(c[2]), "+r"(c[3])
                 : "r"(a[0]), "r"(a[1]), "r"(a[2]), "r"(a[3]),
                   "r"(b[0]), "r"(b[1]));
}

__device__ __forceinline__ void ldsm4(uint32_t* r, uint32_t addr) {
    asm volatile("ldmatrix.sync.aligned.m8n8.x4.shared.b16 {%0,%1,%2,%3}, [%4];"
                 : "=r"(r[0]), "=r"(r[1]), "=r"(r[2]), "=r"(r[3]) : "r"(addr));
}
__device__ __forceinline__ void ldsm4t(uint32_t* r, uint32_t addr) {
    asm volatile("ldmatrix.sync.aligned.m8n8.x4.trans.shared.b16 {%0,%1,%2,%3}, [%4];"
                 : "=r"(r[0]), "=r"(r[1]), "=r"(r[2]), "=r"(r[3]) : "r"(addr));
}

__device__ __forceinline__ uint32_t pack_bf(__nv_bfloat16 lo, __nv_bfloat16 hi) {
    return (uint32_t)__bfloat16_as_ushort(lo) | ((uint32_t)__bfloat16_as_ushort(hi) << 16);
}
__device__ __forceinline__ void split_pack2(float x, float y, uint32_t& hp, uint32_t& lp) {
    __nv_bfloat16 hx = __float2bfloat16(x), hy = __float2bfloat16(y);
    __nv_bfloat16 lx = __float2bfloat16(x - __bfloat162float(hx));
    __nv_bfloat16 ly = __float2bfloat16(y - __bfloat162float(hy));
    hp = pack_bf(hx, hy);
    lp = pack_bf(lx, ly);
}

#define CP_ASYNC16(dst, src) \
    asm volatile("cp.async.cg.shared.global [%0], [%1], 16;" :: "r"(dst), "l"(src) : "memory")
#define CP_COMMIT() asm volatile("cp.async.commit_group;" ::: "memory")
#define CP_WAIT2()  asm volatile("cp.async.wait_group 2;" ::: "memory")
#define CP_WAIT1()  asm volatile("cp.async.wait_group 1;" ::: "memory")
#define CP_WAIT0()  asm volatile("cp.async.wait_group 0;" ::: "memory")

// ---------------------------------------------------------------------------
// Fused per-row absmax + two-level int8 quantization.
// One block per 1024-float row: x = s/127*(Q1 + Q2/254), s = row absmax.
// ---------------------------------------------------------------------------
__global__ void __launch_bounds__(256) rowquant_k(
    const float4* __restrict__ in, char4* __restrict__ q1,
    char4* __restrict__ q2, float* __restrict__ rs)
{
    __shared__ float red[8];
    const int r = blockIdx.x;
    const int t = threadIdx.x;
    const size_t idx = (size_t)r * 256 + t;
    float4 v = in[idx];
    float m = fmaxf(fmaxf(fabsf(v.x), fabsf(v.y)),
                    fmaxf(fabsf(v.z), fabsf(v.w)));
    #pragma unroll
    for (int o = 16; o; o >>= 1) m = fmaxf(m, __shfl_xor_sync(0xffffffffu, m, o));
    if ((t & 31) == 0) red[t >> 5] = m;
    __syncthreads();
    if (t == 0) {
        float mm = red[0];
        #pragma unroll
        for (int i = 1; i < 8; i++) mm = fmaxf(mm, red[i]);
        red[0] = fmaxf(mm, 1e-20f);
    }
    __syncthreads();
    const float s = red[0];
    const float k = 127.0f / s;
    float u0 = v.x * k, u1 = v.y * k, u2 = v.z * k, u3 = v.w * k;
    float a0 = rintf(u0), a1 = rintf(u1), a2 = rintf(u2), a3 = rintf(u3);
    float b0 = rintf((u0 - a0) * 254.0f), b1 = rintf((u1 - a1) * 254.0f);
    float b2 = rintf((u2 - a2) * 254.0f), b3 = rintf((u3 - a3) * 254.0f);
    q1[idx] = make_char4((int)a0, (int)a1, (int)a2, (int)a3);
    q2[idx] = make_char4((int)b0, (int)b1, (int)b2, (int)b3);
    if (t == 0) rs[r] = s;
}

// ---------------------------------------------------------------------------
// int8 GEMM (EXACT 4-term): C = sA[m]*sB[n]/127^2 *
//     (A1B1 + (A1B2 + A2B1)/254 + A2B2/254^2),   A[M,K] * B[N,K]^T.
// CTA tile 64x128, BK=32 bytes, 256 threads (8 warps 2x4), warp tile 32x32,
// 4-stage cp.async pipeline, ldmatrix fragments.
// Smem row stride 48B: 12r mod 32 covers all banks -> conflict-free LDSM.
// ---------------------------------------------------------------------------
#define ISROW   48
#define IT_A    (64 * ISROW)             // 3072
#define IT_B    (128 * ISROW)            // 6144
#define I_STAGE (2 * IT_A + 2 * IT_B)    // 18432
#define I_SMEM  (4 * I_STAGE)            // 73728

#define GEMM_I8_BODY(A1p, A2p, B1p, B2p, K)                                    \
    extern __shared__ __align__(16) char smemraw[];                            \
    const uint32_t sb = smem_u32(smemraw);                                     \
    const int tid = threadIdx.x, lane = tid & 31, warp = tid >> 5;             \
    const int wm = warp >> 2, wn = warp & 3;                                   \
    const int bm = blockIdx.y * 64, bn = blockIdx.x * 128;                     \
    int acc1[2][4][4], accX[2][4][4], acc2[2][4][4];                           \
    _Pragma("unroll")                                                          \
    for (int i = 0; i < 2; i++)                                                \
        _Pragma("unroll")                                                      \
        for (int j = 0; j < 4; j++)                                            \
            _Pragma("unroll")                                                  \
            for (int e = 0; e < 4; e++) {                                      \
                acc1[i][j][e] = 0; accX[i][j][e] = 0; acc2[i][j][e] = 0;       \
            }                                                                  \
    const int nk = K / 32;                                                     \
    auto load_st = [&](int kt, int st) {                                       \
        const uint32_t base = sb + st * I_STAGE;                               \
        const int ko = kt * 32;                                                \
        _Pragma("unroll")                                                      \
        for (int i = 0; i < 3; i++) {                                          \
            const int idx = tid + i * 256;     /* 0..767 */                    \
            uint32_t dst; const int8_t* src;                                   \
            if (idx < 256) {                                                   \
                const int var = idx >> 7, rem = idx & 127;                     \
                const int row = rem >> 1, seg = rem & 1;                       \
                dst = base + var * IT_A + row * ISROW + seg * 16;              \
                src = (var == 0 ? A1p : A2p) +                                 \
                      (size_t)(bm + row) * K + ko + seg * 16;                  \
            } else {                                                           \
                const int j2 = idx - 256;                                      \
                const int var = j2 >> 8, rem = j2 & 255;                       \
                const int row = rem >> 1, seg = rem & 1;                       \
                dst = base + 2 * IT_A + var * IT_B + row * ISROW + seg * 16;   \
                src = (var == 0 ? B1p : B2p) +                                 \
                      (size_t)(bn + row) * K + ko + seg * 16;                  \
            }                                                                  \
            CP_ASYNC16(dst, src);                                              \
        }                                                                      \
        CP_COMMIT();                                                           \
    };                                                                         \
    load_st(0, 0); load_st(1, 1); load_st(2, 2);                               \
    for (int kt = 0; kt < nk; kt++) {                                          \
        const int st = kt & 3;                                                 \
        if (kt + 2 < nk)      { CP_WAIT2(); }                                  \
        else if (kt + 1 < nk) { CP_WAIT1(); }                                  \
        else                  { CP_WAIT0(); }                                  \
        __syncthreads();                                                       \
        if (kt + 3 < nk) load_st(kt + 3, (kt + 3) & 3);                        \
        const uint32_t aT = sb + st * I_STAGE;                                 \
        const uint32_t a_lro = (uint32_t)((lane & 15) * ISROW + (lane >> 4) * 16); \
        const uint32_t b_lro = (uint32_t)((((lane >> 4) << 3) + (lane & 7)) * ISROW + \
                                          ((lane >> 3) & 1) * 16);             \
        uint32_t f1[2][4], f2[2][4], gB1[2][4], gB2[2][4];                     \
        _Pragma("unroll")                                                      \
        for (int mi = 0; mi < 2; mi++) {                                       \
            const uint32_t mo = (uint32_t)((wm * 32 + mi * 16) * ISROW);       \
            ldsm4(f1[mi], aT + 0 * IT_A + mo + a_lro);                         \
            ldsm4(f2[mi], aT + 1 * IT_A + mo + a_lro);                         \
        }                                                                      \
        _Pragma("unroll")                                                      \
        for (int np = 0; np < 2; np++) {                                       \
            const uint32_t no = (uint32_t)((wn * 32 + np * 16) * ISROW);       \
            ldsm4(gB1[np], aT + 2 * IT_A + no + b_lro);                        \
            ldsm4(gB2[np], aT + 2 * IT_A + IT_B + no + b_lro);                 \
        }                                                                      \
        _Pragma("unroll")                                                      \
        for (int mi = 0; mi < 2; mi++)                                         \
            _Pragma("unroll")                                                  \
            for (int nj = 0; nj < 4; nj++)                                     \
                mma_i8(acc1[mi][nj], f1[mi], &gB1[nj >> 1][(nj & 1) * 2]);     \
        _Pragma("unroll")                                                      \
        for (int mi = 0; mi < 2; mi++)                                         \
            _Pragma("unroll")                                                  \
            for (int nj = 0; nj < 4; nj++)                                     \
                mma_i8(accX[mi][nj], f1[mi], &gB2[nj >> 1][(nj & 1) * 2]);     \
        _Pragma("unroll")                                                      \
        for (int mi = 0; mi < 2; mi++)                                         \
            _Pragma("unroll")                                                  \
            for (int nj = 0; nj < 4; nj++)                                     \
                mma_i8(accX[mi][nj], f2[mi], &gB1[nj >> 1][(nj & 1) * 2]);     \
        _Pragma("unroll")                                                      \
        for (int mi = 0; mi < 2; mi++)                                         \
            _Pragma("unroll")                                                  \
            for (int nj = 0; nj < 4; nj++)                                     \
                mma_i8(acc2[mi][nj], f2[mi], &gB2[nj >> 1][(nj & 1) * 2]);     \
    }

#define RAW(mi, nj, e) \
    ((float)acc1[mi][nj][e] + (float)accX[mi][nj][e] * (1.0f / 254.0f) \
     + (float)acc2[mi][nj][e] * (1.0f / 64516.0f))

// QKV projection: per-row dequant + split bf16 head-major writeout
__global__ void __launch_bounds__(256) gemm_i8_qkv(
    const int8_t* __restrict__ A1p, const int8_t* __restrict__ A2p,
    const int8_t* __restrict__ B1p, const int8_t* __restrict__ B2p,
    const float* __restrict__ rsA, const float* __restrict__ rsB,
    __nv_bfloat16* __restrict__ Qh, __nv_bfloat16* __restrict__ Ql, int K)
{
    GEMM_I8_BODY(A1p, A2p, B1p, B2p, K)
    #pragma unroll
    for (int mi = 0; mi < 2; mi++) {
        const int m = bm + wm * 32 + mi * 16 + (lane >> 2);   // token
        const int bb = m >> 11, ll = m & 2047;
        const float sa0 = __ldg(rsA + m)     * (1.0f / 16129.0f);
        const float sa1 = __ldg(rsA + m + 8) * (1.0f / 16129.0f);
        #pragma unroll
        for (int nj = 0; nj < 4; nj++) {
            const int n = bn + wn * 32 + nj * 8 + (lane & 3) * 2;
            const float sb0 = __ldg(rsB + n), sb1 = __ldg(rsB + n + 1);
            const int part = n >> 10, rem = n & 1023, hh = rem >> 6, dd = rem & 63;
            const size_t off = (((size_t)(part * B_ + bb) * H_ + hh) * L_ + ll) * HD_ + dd;
            uint32_t hp, lp;
            split_pack2(sa0 * sb0 * RAW(mi, nj, 0), sa0 * sb1 * RAW(mi, nj, 1), hp, lp);
            *(uint32_t*)(Qh + off) = hp;
            *(uint32_t*)(Ql + off) = lp;
            split_pack2(sa1 * sb0 * RAW(mi, nj, 2), sa1 * sb1 * RAW(mi, nj, 3), hp, lp);
            *(uint32_t*)(Qh + off + (size_t)8 * HD_) = hp;
            *(uint32_t*)(Ql + off + (size_t)8 * HD_) = lp;
        }
    }
}

// Output projection: per-row dequant + fp32 row-major C[M,N]
__global__ void __launch_bounds__(256) gemm_i8_out(
    const int8_t* __restrict__ A1p, const int8_t* __restrict__ A2p,
    const int8_t* __restrict__ B1p, const int8_t* __restrict__ B2p,
    const float* __restrict__ rsA, const float* __restrict__ rsB,
    float* __restrict__ C, int N, int K)
{
    GEMM_I8_BODY(A1p, A2p, B1p, B2p, K)
    #pragma unroll
    for (int mi = 0; mi < 2; mi++) {
        const int m = bm + wm * 32 + mi * 16 + (lane >> 2);
        const float sa0 = __ldg(rsA + m)     * (1.0f / 16129.0f);
        const float sa1 = __ldg(rsA + m + 8) * (1.0f / 16129.0f);
        #pragma unroll
        for (int nj = 0; nj < 4; nj++) {
            const int n = bn + wn * 32 + nj * 8 + (lane & 3) * 2;
            const float sb0 = __ldg(rsB + n), sb1 = __ldg(rsB + n + 1);
            *(float2*)(C + (size_t)m * N + n) =
                make_float2(sa0 * sb0 * RAW(mi, nj, 0), sa0 * sb1 * RAW(mi, nj, 1));
            *(float2*)(C + (size_t)(m + 8) * N + n) =
                make_float2(sa1 * sb0 * RAW(mi, nj, 2), sa1 * sb1 * RAW(mi, nj, 3));
        }
    }
}

// ---------------------------------------------------------------------------
// Tensor-core causal flash attention (bf16 3-term, ldmatrix) — proven kernel,
// fp32 ctx epilogue. Unchanged from R10.
// ---------------------------------------------------------------------------
#define KSTR  72
#define AT_TILE  (64 * KSTR * 2)
#define AT_STAGE (4 * AT_TILE)
#define AT_SMEM  (2 * AT_STAGE)          // 73728 B

__global__ void __launch_bounds__(256, 2) attn_mma(
    const __nv_bfloat16* __restrict__ qkvh,
    const __nv_bfloat16* __restrict__ qkvl,
    float* __restrict__ ctx)
{
    extern __shared__ __align__(16) char smem[];
    const uint32_t sb = smem_u32(smem);
    const int tid = threadIdx.x, lane = tid & 31, warp = tid >> 5;
    const int qt = (int)gridDim.x - 1 - (int)blockIdx.x;
    const int bh = blockIdx.y, b = bh >> 4, h = bh & 15;
    const int q0 = qt * 128;
    const size_t PART = (size_t)TOK * D_;
    const size_t headoff = (size_t)bh * L_ * HD_;
    const __nv_bfloat16* Qh = qkvh + headoff;
    const __nv_bfloat16* Ql = qkvl + headoff;
    const __nv_bfloat16* Kh = qkvh + PART + headoff;
    const __nv_bfloat16* Kl = qkvl + PART + headoff;
    const __nv_bfloat16* Vh = qkvh + 2 * PART + headoff;
    const __nv_bfloat16* Vl = qkvl + 2 * PART + headoff;

    const int r0 = q0 + warp * 16 + (lane >> 2);

    uint32_t qfh[4][4], qfl[4][4];
    {
        const __nv_bfloat16* p0  = Qh + (size_t)r0 * HD_;
        const __nv_bfloat16* p8  = p0 + 8 * HD_;
        const __nv_bfloat16* p0l = Ql + (size_t)r0 * HD_;
        const __nv_bfloat16* p8l = p0l + 8 * HD_;
        #pragma unroll
        for (int t = 0; t < 4; t++) {
            const int d0 = t * 16 + 2 * (lane & 3);
            qfh[t][0] = *(const uint32_t*)(p0 + d0);
            qfh[t][1] = *(const uint32_t*)(p8 + d0);
            qfh[t][2] = *(const uint32_t*)(p0 + d0 + 8);
            qfh[t][3] = *(const uint32_t*)(p8 + d0 + 8);
            qfl[t][0] = *(const uint32_t*)(p0l + d0);
            qfl[t][1] = *(const uint32_t*)(p8l + d0);
            qfl[t][2] = *(const uint32_t*)(p0l + d0 + 8);
            qfl[t][3] = *(const uint32_t*)(p8l + d0 + 8);
        }
    }

    float Oa[8][4];
    #pragma unroll
    for (int j = 0; j < 8; j++)
        #pragma unroll
        for (int e = 0; e < 4; e++) Oa[j][e] = 0.0f;
    float m0 = -1e30f, m1 = -1e30f, l0 = 0.0f, l1 = 0.0f;

    const int ntiles = 2 * qt + 2;

    auto load_tile = [&](int kt, int stage) {
        const uint32_t dstbase = sb + stage * AT_STAGE;
        #pragma unroll
        for (int i = 0; i < 2; i++) {
            const int rem = tid + i * 256;
            const int row = rem >> 3, dch = rem & 7;
            const size_t g = (size_t)(kt * 64 + row) * HD_ + dch * 8;
            const uint32_t dof = dstbase + row * (KSTR * 2) + dch * 16;
            CP_ASYNC16(dof + 0 * AT_TILE, Kh + g);
            CP_ASYNC16(dof + 1 * AT_TILE, Kl + g);
            CP_ASYNC16(dof + 2 * AT_TILE, Vh + g);
            CP_ASYNC16(dof + 3 * AT_TILE, Vl + g);
        }
        CP_COMMIT();
    };

    load_tile(0, 0);

    for (int kt = 0; kt < ntiles; kt++) {
        const int stage = kt & 1;
        if (kt + 1 < ntiles) { load_tile(kt + 1, (kt + 1) & 1); CP_WAIT1(); }
        else                 { CP_WAIT0(); }
        __syncthreads();

        const int k0 = kt * 64;
        if (k0 <= q0 + warp * 16 + 15) {
            const uint32_t kbh = sb + stage * AT_STAGE;
            const uint32_t kbl = kbh + AT_TILE;
            const uint32_t vbh = kbh + 2 * AT_TILE;
            const uint32_t vbl = kbh + 3 * AT_TILE;

            float Sa[8][4];
            #pragma unroll
            for (int j = 0; j < 8; j++)
                #pragma unroll
                for (int e = 0; e < 4; e++) Sa[j][e] = 0.0f;

            const uint32_t k_lro =
                (uint32_t)((((lane >> 4) << 3) + (lane & 7)) * KSTR +
                           ((lane >> 3) & 1) * 8) * 2;
            #pragma unroll
            for (int jp = 0; jp < 4; jp++) {
                const uint32_t no = (uint32_t)(jp * 16 * KSTR) * 2;
                #pragma unroll
                for (int t = 0; t < 4; t++) {
                    const uint32_t co = (uint32_t)(t * 16) * 2;
                    uint32_t kb4h[4], kb4l[4];
                    ldsm4(kb4h, kbh + no + k_lro + co);
                    ldsm4(kb4l, kbl + no + k_lro + co);
                    mma16816(Sa[2 * jp],     qfh[t], &kb4h[0]);
                    mma16816(Sa[2 * jp],     qfh[t], &kb4l[0]);
                    mma16816(Sa[2 * jp],     qfl[t], &kb4h[0]);
                    mma16816(Sa[2 * jp + 1], qfh[t], &kb4h[2]);
                    mma16816(Sa[2 * jp + 1], qfh[t], &kb4l[2]);
                    mma16816(Sa[2 * jp + 1], qfl[t], &kb4h[2]);
                }
            }

            const bool needmask = (k0 + 63 > q0 + warp * 16);
            #pragma unroll
            for (int j = 0; j < 8; j++) {
                #pragma unroll
                for (int e = 0; e < 4; e++) Sa[j][e] *= 0.125f;
                if (needmask) {
                    const int key0 = k0 + j * 8 + 2 * (lane & 3);
                    if (key0     > r0)     Sa[j][0] = -1e30f;
                    if (key0 + 1 > r0)     Sa[j][1] = -1e30f;
                    if (key0     > r0 + 8) Sa[j][2] = -1e30f;
                    if (key0 + 1 > r0 + 8) Sa[j][3] = -1e30f;
                }
            }

            float mx0 = -1e30f, mx1 = -1e30f;
            #pragma unroll
            for (int j = 0; j < 8; j++) {
                mx0 = fmaxf(mx0, fmaxf(Sa[j][0], Sa[j][1]));
                mx1 = fmaxf(mx1, fmaxf(Sa[j][2], Sa[j][3]));
            }
            mx0 = fmaxf(mx0, __shfl_xor_sync(0xffffffffu, mx0, 1));
            mx0 = fmaxf(mx0, __shfl_xor_sync(0xffffffffu, mx0, 2));
            mx1 = fmaxf(mx1, __shfl_xor_sync(0xffffffffu, mx1, 1));
            mx1 = fmaxf(mx1, __shfl_xor_sync(0xffffffffu, mx1, 2));
            const float mn0 = fmaxf(m0, mx0), mn1 = fmaxf(m1, mx1);
            const float a0 = __expf(m0 - mn0), a1 = __expf(m1 - mn1);
            m0 = mn0; m1 = mn1;
            float rs0 = 0.0f, rs1 = 0.0f;
            #pragma unroll
            for (int j = 0; j < 8; j++) {
                Sa[j][0] = __expf(Sa[j][0] - mn0); rs0 += Sa[j][0];
                Sa[j][1] = __expf(Sa[j][1] - mn0); rs0 += Sa[j][1];
                Sa[j][2] = __expf(Sa[j][2] - mn1); rs1 += Sa[j][2];
                Sa[j][3] = __expf(Sa[j][3] - mn1); rs1 += Sa[j][3];
            }
            rs0 += __shfl_xor_sync(0xffffffffu, rs0, 1);
            rs0 += __shfl_xor_sync(0xffffffffu, rs0, 2);
            rs1 += __shfl_xor_sync(0xffffffffu, rs1, 1);
            rs1 += __shfl_xor_sync(0xffffffffu, rs1, 2);
            l0 = l0 * a0 + rs0;
            l1 = l1 * a1 + rs1;
            #pragma unroll
            for (int j = 0; j < 8; j++) {
                Oa[j][0] *= a0; Oa[j][1] *= a0;
                Oa[j][2] *= a1; Oa[j][3] *= a1;
            }

            const uint32_t v_lro =
                (uint32_t)((((lane >> 3) & 1) * 8 + (lane & 7)) * KSTR +
                           (lane >> 4) * 8) * 2;
            #pragma unroll
            for (int t = 0; t < 4; t++) {
                uint32_t ah[4], al[4];
                split_pack2(Sa[2 * t][0],     Sa[2 * t][1],     ah[0], al[0]);
                split_pack2(Sa[2 * t][2],     Sa[2 * t][3],     ah[1], al[1]);
                split_pack2(Sa[2 * t + 1][0], Sa[2 * t + 1][1], ah[2], al[2]);
                split_pack2(Sa[2 * t + 1][2], Sa[2 * t + 1][3], ah[3], al[3]);
                const uint32_t ro = (uint32_t)(t * 16 * KSTR) * 2;
                #pragma unroll
                for (int jp = 0; jp < 4; jp++) {
                    const uint32_t co = (uint32_t)(jp * 16) * 2;
                    uint32_t vh4[4], vl4[4];
                    ldsm4t(vh4, vbh + ro + v_lro + co);
                    ldsm4t(vl4, vbl + ro + v_lro + co);
                    mma16816(Oa[2 * jp],     ah, &vh4[0]);
                    mma16816(Oa[2 * jp],     ah, &vl4[0]);
                    mma16816(Oa[2 * jp],     al, &vh4[0]);
                    mma16816(Oa[2 * jp + 1], ah, &vh4[2]);
                    mma16816(Oa[2 * jp + 1], ah, &vl4[2]);
                    mma16816(Oa[2 * jp + 1], al, &vh4[2]);
                }
            }
        }
        __syncthreads();
    }

    // ---- finalize: write fp32 ctx [tok][1024] ----
    const float inv0 = 1.0f / l0, inv1 = 1.0f / l1;
    const size_t row_off = (size_t)(b * L_ + r0) * D_ + h * 64;
    #pragma unroll
    for (int j = 0; j < 8; j++) {
        const int n = j * 8 + 2 * (lane & 3);
        *(float2*)(ctx + row_off + n) =
            make_float2(Oa[j][0] * inv0, Oa[j][1] * inv0);
        *(float2*)(ctx + row_off + (size_t)8 * D_ + n) =
            make_float2(Oa[j][2] * inv1, Oa[j][3] * inv1);
    }
}

// ---------------------------------------------------------------------------
// kernel_launch — graph-capturable, allocation-free
// ---------------------------------------------------------------------------
extern "C" void kernel_launch(void* const* d_in, const int* in_sizes, int n_in,
                              void* d_out, int out_size)
{
    (void)in_sizes; (void)n_in; (void)out_size;
    const float* x     = (const float*)d_in[0];
    const float* w_qkv = (const float*)d_in[1];
    const float* w_out = (const float*)d_in[2];
    float* out = (float*)d_out;

    int8_t *x1, *x2, *wq1, *wq2, *wo1, *wo2, *c1, *c2;
    __nv_bfloat16 *qh, *ql;
    float *ctx, *rsx, *rswq, *rswo, *rsc;
    cudaGetSymbolAddress((void**)&x1, g_x1);
    cudaGetSymbolAddress((void**)&x2, g_x2);
    cudaGetSymbolAddress((void**)&wq1, g_wq1);
    cudaGetSymbolAddress((void**)&wq2, g_wq2);
    cudaGetSymbolAddress((void**)&wo1, g_wo1);
    cudaGetSymbolAddress((void**)&wo2, g_wo2);
    cudaGetSymbolAddress((void**)&c1, g_c1);
    cudaGetSymbolAddress((void**)&c2, g_c2);
    cudaGetSymbolAddress((void**)&qh, g_qkvh);
    cudaGetSymbolAddress((void**)&ql, g_qkvl);
    cudaGetSymbolAddress((void**)&ctx, g_ctx);
    cudaGetSymbolAddress((void**)&rsx, g_rsx);
    cudaGetSymbolAddress((void**)&rswq, g_rswq);
    cudaGetSymbolAddress((void**)&rswo, g_rswo);
    cudaGetSymbolAddress((void**)&rsc, g_rsc);

    cudaFuncSetAttribute(attn_mma,
                         cudaFuncAttributeMaxDynamicSharedMemorySize, AT_SMEM);
    cudaFuncSetAttribute(gemm_i8_qkv,
                         cudaFuncAttributeMaxDynamicSharedMemorySize, I_SMEM);
    cudaFuncSetAttribute(gemm_i8_out,
                         cudaFuncAttributeMaxDynamicSharedMemorySize, I_SMEM);

    // single-pass per-row quantization of inputs/weights
    rowquant_k<<<TOK, 256>>>((const float4*)x, (char4*)x1, (char4*)x2, rsx);
    rowquant_k<<<3 * D_, 256>>>((const float4*)w_qkv, (char4*)wq1, (char4*)wq2, rswq);
    rowquant_k<<<D_, 256>>>((const float4*)w_out, (char4*)wo1, (char4*)wo2, rswo);

    // 1) QKV projection (int8, exact 4-term) -> split bf16 head-major qkv
    {
        dim3 grid(3 * D_ / 128, TOK / 64);
        gemm_i8_qkv<<<grid, 256, I_SMEM>>>(x1, x2, wq1, wq2, rsx, rswq, qh, ql, D_);
    }
    // 2) tensor-core flash attention (bf16) -> fp32 ctx
    {
        dim3 grid(L_ / 128, B_ * H_);
        attn_mma<<<grid, 256, AT_SMEM>>>(qh, ql, ctx);
    }
    // 3) per-row quantize ctx, output projection (int8, exact 4-term)
    rowquant_k<<<TOK, 256>>>((const float4*)ctx, (char4*)c1, (char4*)c2, rsc);
    {
        dim3 grid(D_ / 128, TOK / 64);
        gemm_i8_out<<<grid, 256, I_SMEM>>>(c1, c2, wo1, wo2, rsc, rswo, out, D_, D_);
    }
}

// round 13
// speedup vs baseline: 1.3608x; 1.1059x over previous
#include <cuda_runtime.h>
#include <cuda_bf16.h>
#include <cstdint>
#include <cstddef>

// Problem constants
#define B_   2
#define L_   2048
#define D_   1024
#define H_   16
#define HD_  64
#define TOK  (B_ * L_)          // 4096 tokens

// ---------------------------------------------------------------------------
// Scratch (__device__ globals; no cudaMalloc allowed)
// ---------------------------------------------------------------------------
__device__ __align__(16) int8_t g_x1[(size_t)TOK * D_];
__device__ __align__(16) int8_t g_x2[(size_t)TOK * D_];
__device__ __align__(16) int8_t g_wq1[(size_t)3 * D_ * D_];
__device__ __align__(16) int8_t g_wq2[(size_t)3 * D_ * D_];
__device__ __align__(16) int8_t g_wo1[(size_t)D_ * D_];
__device__ __align__(16) int8_t g_wo2[(size_t)D_ * D_];
__device__ __align__(16) int8_t g_c1[(size_t)TOK * D_];
__device__ __align__(16) int8_t g_c2[(size_t)TOK * D_];
// per-row quantization scales
__device__ float g_rsx[TOK];
__device__ float g_rswq[3 * D_];
__device__ float g_rswo[D_];
__device__ float g_rsc[TOK];
// head-major split qkv for attention: [part(q/k/v)][b][h][l][64] bf16 hi/lo
__device__ __align__(16) __nv_bfloat16 g_qkvh[(size_t)3 * TOK * D_];
__device__ __align__(16) __nv_bfloat16 g_qkvl[(size_t)3 * TOK * D_];
// attention context fp32 [tok][1024]
__device__ __align__(16) float g_ctx[(size_t)TOK * D_];

// ---------------------------------------------------------------------------
// Helpers
// ---------------------------------------------------------------------------
__device__ __forceinline__ uint32_t smem_u32(const void* p) {
    uint32_t a;
    asm("{ .reg .u64 t; cvta.to.shared.u64 t, %1; cvt.u32.u64 %0, t; }" : "=r"(a) : "l"(p));
    return a;
}

__device__ __forceinline__ void mma16816(float* c, const uint32_t* a, const uint32_t* b) {
    asm volatile("mma.sync.aligned.m16n8k16.row.col.f32.bf16.bf16.f32 "
                 "{%0,%1,%2,%3}, {%4,%5,%6,%7}, {%8,%9}, {%0,%1,%2,%3};"
                 : "+f"(c[0]), "+f"(c[1]), "+f"(c[2]), "+f"(c[3])
                 : "r"(a[0]), "r"(a[1]), "r"(a[2]), "r"(a[3]),
                   "r"(b[0]), "r"(b[1]));
}

__device__ __forceinline__ void mma_i8(int* c, const uint32_t* a, const uint32_t* b) {
    asm volatile("mma.sync.aligned.m16n8k32.row.col.s32.s8.s8.s32 "
                 "{%0,%1,%2,%3}, {%4,%5,%6,%7}, {%8,%9}, {%0,%1,%2,%3};"
                 : "+r"(c[0]), "+r"(c[1]), "+r"(c[2]), "+r"(c[3])
                 : "r"(a[0]), "r"(a[1]), "r"(a[2]), "r"(a[3]),
                   "r"(b[0]), "r"(b[1]));
}

__device__ __forceinline__ void ldsm4(uint32_t* r, uint32_t addr) {
    asm volatile("ldmatrix.sync.aligned.m8n8.x4.shared.b16 {%0,%1,%2,%3}, [%4];"
                 : "=r"(r[0]), "=r"(r[1]), "=r"(r[2]), "=r"(r[3]) : "r"(addr));
}
__device__ __forceinline__ void ldsm4t(uint32_t* r, uint32_t addr) {
    asm volatile("ldmatrix.sync.aligned.m8n8.x4.trans.shared.b16 {%0,%1,%2,%3}, [%4];"
                 : "=r"(r[0]), "=r"(r[1]), "=r"(r[2]), "=r"(r[3]) : "r"(addr));
}

__device__ __forceinline__ uint32_t pack_bf(__nv_bfloat16 lo, __nv_bfloat16 hi) {
    return (uint32_t)__bfloat16_as_ushort(lo) | ((uint32_t)__bfloat16_as_ushort(hi) << 16);
}
__device__ __forceinline__ void split_pack2(float x, float y, uint32_t& hp, uint32_t& lp) {
    __nv_bfloat16 hx = __float2bfloat16(x), hy = __float2bfloat16(y);
    __nv_bfloat16 lx = __float2bfloat16(x - __bfloat162float(hx));
    __nv_bfloat16 ly = __float2bfloat16(y - __bfloat162float(hy));
    hp = pack_bf(hx, hy);
    lp = pack_bf(lx, ly);
}

#define CP_ASYNC16(dst, src) \
    asm volatile("cp.async.cg.shared.global [%0], [%1], 16;" :: "r"(dst), "l"(src) : "memory")
#define CP_COMMIT() asm volatile("cp.async.commit_group;" ::: "memory")
#define CP_WAIT2()  asm volatile("cp.async.wait_group 2;" ::: "memory")
#define CP_WAIT1()  asm volatile("cp.async.wait_group 1;" ::: "memory")
#define CP_WAIT0()  asm volatile("cp.async.wait_group 0;" ::: "memory")

// ---------------------------------------------------------------------------
// Fused per-row absmax + two-level int8 quantization.
// One block per 1024-float row: x = s/127*(Q1 + Q2/254), s = row absmax.
// ---------------------------------------------------------------------------
__global__ void __launch_bounds__(256) rowquant_k(
    const float4* __restrict__ in, char4* __restrict__ q1,
    char4* __restrict__ q2, float* __restrict__ rs)
{
    __shared__ float red[8];
    const int r = blockIdx.x;
    const int t = threadIdx.x;
    const size_t idx = (size_t)r * 256 + t;
    float4 v = in[idx];
    float m = fmaxf(fmaxf(fabsf(v.x), fabsf(v.y)),
                    fmaxf(fabsf(v.z), fabsf(v.w)));
    #pragma unroll
    for (int o = 16; o; o >>= 1) m = fmaxf(m, __shfl_xor_sync(0xffffffffu, m, o));
    if ((t & 31) == 0) red[t >> 5] = m;
    __syncthreads();
    if (t == 0) {
        float mm = red[0];
        #pragma unroll
        for (int i = 1; i < 8; i++) mm = fmaxf(mm, red[i]);
        red[0] = fmaxf(mm, 1e-20f);
    }
    __syncthreads();
    const float s = red[0];
    const float k = 127.0f / s;
    float u0 = v.x * k, u1 = v.y * k, u2 = v.z * k, u3 = v.w * k;
    float a0 = rintf(u0), a1 = rintf(u1), a2 = rintf(u2), a3 = rintf(u3);
    float b0 = rintf((u0 - a0) * 254.0f), b1 = rintf((u1 - a1) * 254.0f);
    float b2 = rintf((u2 - a2) * 254.0f), b3 = rintf((u3 - a3) * 254.0f);
    q1[idx] = make_char4((int)a0, (int)a1, (int)a2, (int)a3);
    q2[idx] = make_char4((int)b0, (int)b1, (int)b2, (int)b3);
    if (t == 0) rs[r] = s;
}

// ---------------------------------------------------------------------------
// int8 GEMM (3-term, per-row scales): C = sA[m]*sB[n]/127^2 *
//     (A1B1 + (A1B2 + A2B1)/254),   A[M,K] * B[N,K]^T.
// Dropped A2B2 term: with per-row scales the residual is ~2.4e-4 relative.
// CTA tile 64x128, BK=32 bytes, 256 threads (8 warps 2x4), warp tile 32x32,
// 4-stage cp.async pipeline, ldmatrix fragments.
// Smem row stride 48B: 12r mod 32 covers all banks -> conflict-free LDSM.
// ---------------------------------------------------------------------------
#define ISROW   48
#define IT_A    (64 * ISROW)             // 3072
#define IT_B    (128 * ISROW)            // 6144
#define I_STAGE (2 * IT_A + 2 * IT_B)    // 18432
#define I_SMEM  (4 * I_STAGE)            // 73728

#define GEMM_I8_BODY(A1p, A2p, B1p, B2p, K)                                    \
    extern __shared__ __align__(16) char smemraw[];                            \
    const uint32_t sb = smem_u32(smemraw);                                     \
    const int tid = threadIdx.x, lane = tid & 31, warp = tid >> 5;             \
    const int wm = warp >> 2, wn = warp & 3;                                   \
    const int bm = blockIdx.y * 64, bn = blockIdx.x * 128;                     \
    int acc1[2][4][4], accX[2][4][4];                                          \
    _Pragma("unroll")                                                          \
    for (int i = 0; i < 2; i++)                                                \
        _Pragma("unroll")                                                      \
        for (int j = 0; j < 4; j++)                                            \
            _Pragma("unroll")                                                  \
            for (int e = 0; e < 4; e++) { acc1[i][j][e] = 0; accX[i][j][e] = 0; } \
    const int nk = K / 32;                                                     \
    auto load_st = [&](int kt, int st) {                                       \
        const uint32_t base = sb + st * I_STAGE;                               \
        const int ko = kt * 32;                                                \
        _Pragma("unroll")                                                      \
        for (int i = 0; i < 3; i++) {                                          \
            const int idx = tid + i * 256;     /* 0..767 */                    \
            uint32_t dst; const int8_t* src;                                   \
            if (idx < 256) {                                                   \
                const int var = idx >> 7, rem = idx & 127;                     \
                const int row = rem >> 1, seg = rem & 1;                       \
                dst = base + var * IT_A + row * ISROW + seg * 16;              \
                src = (var == 0 ? A1p : A2p) +                                 \
                      (size_t)(bm + row) * K + ko + seg * 16;                  \
            } else {                                                           \
                const int j2 = idx - 256;                                      \
                const int var = j2 >> 8, rem = j2 & 255;                       \
                const int row = rem >> 1, seg = rem & 1;                       \
                dst = base + 2 * IT_A + var * IT_B + row * ISROW + seg * 16;   \
                src = (var == 0 ? B1p : B2p) +                                 \
                      (size_t)(bn + row) * K + ko + seg * 16;                  \
            }                                                                  \
            CP_ASYNC16(dst, src);                                              \
        }                                                                      \
        CP_COMMIT();                                                           \
    };                                                                         \
    load_st(0, 0); load_st(1, 1); load_st(2, 2);                               \
    for (int kt = 0; kt < nk; kt++) {                                          \
        const int st = kt & 3;                                                 \
        if (kt + 2 < nk)      { CP_WAIT2(); }                                  \
        else if (kt + 1 < nk) { CP_WAIT1(); }                                  \
        else                  { CP_WAIT0(); }                                  \
        __syncthreads();                                                       \
        if (kt + 3 < nk) load_st(kt + 3, (kt + 3) & 3);                        \
        const uint32_t aT = sb + st * I_STAGE;                                 \
        const uint32_t a_lro = (uint32_t)((lane & 15) * ISROW + (lane >> 4) * 16); \
        const uint32_t b_lro = (uint32_t)((((lane >> 4) << 3) + (lane & 7)) * ISROW + \
                                          ((lane >> 3) & 1) * 16);             \
        uint32_t f1[2][4], f2[2][4], gB1[2][4], gB2[2][4];                     \
        _Pragma("unroll")                                                      \
        for (int mi = 0; mi < 2; mi++) {                                       \
            const uint32_t mo = (uint32_t)((wm * 32 + mi * 16) * ISROW);       \
            ldsm4(f1[mi], aT + 0 * IT_A + mo + a_lro);                         \
            ldsm4(f2[mi], aT + 1 * IT_A + mo + a_lro);                         \
        }                                                                      \
        _Pragma("unroll")                                                      \
        for (int np = 0; np < 2; np++) {                                       \
            const uint32_t no = (uint32_t)((wn * 32 + np * 16) * ISROW);       \
            ldsm4(gB1[np], aT + 2 * IT_A + no + b_lro);                        \
            ldsm4(gB2[np], aT + 2 * IT_A + IT_B + no + b_lro);                 \
        }                                                                      \
        _Pragma("unroll")                                                      \
        for (int mi = 0; mi < 2; mi++)                                         \
            _Pragma("unroll")                                                  \
            for (int nj = 0; nj < 4; nj++)                                     \
                mma_i8(acc1[mi][nj], f1[mi], &gB1[nj >> 1][(nj & 1) * 2]);     \
        _Pragma("unroll")                                                      \
        for (int mi = 0; mi < 2; mi++)                                         \
            _Pragma("unroll")                                                  \
            for (int nj = 0; nj < 4; nj++)                                     \
                mma_i8(accX[mi][nj], f1[mi], &gB2[nj >> 1][(nj & 1) * 2]);     \
        _Pragma("unroll")                                                      \
        for (int mi = 0; mi < 2; mi++)                                         \
            _Pragma("unroll")                                                  \
            for (int nj = 0; nj < 4; nj++)                                     \
                mma_i8(accX[mi][nj], f2[mi], &gB1[nj >> 1][(nj & 1) * 2]);     \
    }

#define RAW(mi, nj, e) \
    ((float)acc1[mi][nj][e] + (float)accX[mi][nj][e] * (1.0f / 254.0f))

// QKV projection: per-row dequant + split bf16 head-major writeout
__global__ void __launch_bounds__(256) gemm_i8_qkv(
    const int8_t* __restrict__ A1p, const int8_t* __restrict__ A2p,
    const int8_t* __restrict__ B1p, const int8_t* __restrict__ B2p,
    const float* __restrict__ rsA, const float* __restrict__ rsB,
    __nv_bfloat16* __restrict__ Qh, __nv_bfloat16* __restrict__ Ql, int K)
{
    GEMM_I8_BODY(A1p, A2p, B1p, B2p, K)
    #pragma unroll
    for (int mi = 0; mi < 2; mi++) {
        const int m = bm + wm * 32 + mi * 16 + (lane >> 2);   // token
        const int bb = m >> 11, ll = m & 2047;
        const float sa0 = __ldg(rsA + m)     * (1.0f / 16129.0f);
        const float sa1 = __ldg(rsA + m + 8) * (1.0f / 16129.0f);
        #pragma unroll
        for (int nj = 0; nj < 4; nj++) {
            const int n = bn + wn * 32 + nj * 8 + (lane & 3) * 2;
            const float sb0 = __ldg(rsB + n), sb1 = __ldg(rsB + n + 1);
            const int part = n >> 10, rem = n & 1023, hh = rem >> 6, dd = rem & 63;
            const size_t off = (((size_t)(part * B_ + bb) * H_ + hh) * L_ + ll) * HD_ + dd;
            uint32_t hp, lp;
            split_pack2(sa0 * sb0 * RAW(mi, nj, 0), sa0 * sb1 * RAW(mi, nj, 1), hp, lp);
            *(uint32_t*)(Qh + off) = hp;
            *(uint32_t*)(Ql + off) = lp;
            split_pack2(sa1 * sb0 * RAW(mi, nj, 2), sa1 * sb1 * RAW(mi, nj, 3), hp, lp);
            *(uint32_t*)(Qh + off + (size_t)8 * HD_) = hp;
            *(uint32_t*)(Ql + off + (size_t)8 * HD_) = lp;
        }
    }
}

// Output projection: per-row dequant + fp32 row-major C[M,N]
__global__ void __launch_bounds__(256) gemm_i8_out(
    const int8_t* __restrict__ A1p, const int8_t* __restrict__ A2p,
    const int8_t* __restrict__ B1p, const int8_t* __restrict__ B2p,
    const float* __restrict__ rsA, const float* __restrict__ rsB,
    float* __restrict__ C, int N, int K)
{
    GEMM_I8_BODY(A1p, A2p, B1p, B2p, K)
    #pragma unroll
    for (int mi = 0; mi < 2; mi++) {
        const int m = bm + wm * 32 + mi * 16 + (lane >> 2);
        const float sa0 = __ldg(rsA + m)     * (1.0f / 16129.0f);
        const float sa1 = __ldg(rsA + m + 8) * (1.0f / 16129.0f);
        #pragma unroll
        for (int nj = 0; nj < 4; nj++) {
            const int n = bn + wn * 32 + nj * 8 + (lane & 3) * 2;
            const float sb0 = __ldg(rsB + n), sb1 = __ldg(rsB + n + 1);
            *(float2*)(C + (size_t)m * N + n) =
                make_float2(sa0 * sb0 * RAW(mi, nj, 0), sa0 * sb1 * RAW(mi, nj, 1));
            *(float2*)(C + (size_t)(m + 8) * N + n) =
                make_float2(sa1 * sb0 * RAW(mi, nj, 2), sa1 * sb1 * RAW(mi, nj, 3));
        }
    }
}

// ---------------------------------------------------------------------------
// Tensor-core causal flash attention (bf16 3-term, ldmatrix) — proven kernel,
// fp32 ctx epilogue. Unchanged from R11.
// ---------------------------------------------------------------------------
#define KSTR  72
#define AT_TILE  (64 * KSTR * 2)
#define AT_STAGE (4 * AT_TILE)
#define AT_SMEM  (2 * AT_STAGE)          // 73728 B

__global__ void __launch_bounds__(256, 2) attn_mma(
    const __nv_bfloat16* __restrict__ qkvh,
    const __nv_bfloat16* __restrict__ qkvl,
    float* __restrict__ ctx)
{
    extern __shared__ __align__(16) char smem[];
    const uint32_t sb = smem_u32(smem);
    const int tid = threadIdx.x, lane = tid & 31, warp = tid >> 5;
    const int qt = (int)gridDim.x - 1 - (int)blockIdx.x;
    const int bh = blockIdx.y, b = bh >> 4, h = bh & 15;
    const int q0 = qt * 128;
    const size_t PART = (size_t)TOK * D_;
    const size_t headoff = (size_t)bh * L_ * HD_;
    const __nv_bfloat16* Qh = qkvh + headoff;
    const __nv_bfloat16* Ql = qkvl + headoff;
    const __nv_bfloat16* Kh = qkvh + PART + headoff;
    const __nv_bfloat16* Kl = qkvl + PART + headoff;
    const __nv_bfloat16* Vh = qkvh + 2 * PART + headoff;
    const __nv_bfloat16* Vl = qkvl + 2 * PART + headoff;

    const int r0 = q0 + warp * 16 + (lane >> 2);

    uint32_t qfh[4][4], qfl[4][4];
    {
        const __nv_bfloat16* p0  = Qh + (size_t)r0 * HD_;
        const __nv_bfloat16* p8  = p0 + 8 * HD_;
        const __nv_bfloat16* p0l = Ql + (size_t)r0 * HD_;
        const __nv_bfloat16* p8l = p0l + 8 * HD_;
        #pragma unroll
        for (int t = 0; t < 4; t++) {
            const int d0 = t * 16 + 2 * (lane & 3);
            qfh[t][0] = *(const uint32_t*)(p0 + d0);
            qfh[t][1] = *(const uint32_t*)(p8 + d0);
            qfh[t][2] = *(const uint32_t*)(p0 + d0 + 8);
            qfh[t][3] = *(const uint32_t*)(p8 + d0 + 8);
            qfl[t][0] = *(const uint32_t*)(p0l + d0);
            qfl[t][1] = *(const uint32_t*)(p8l + d0);
            qfl[t][2] = *(const uint32_t*)(p0l + d0 + 8);
            qfl[t][3] = *(const uint32_t*)(p8l + d0 + 8);
        }
    }

    float Oa[8][4];
    #pragma unroll
    for (int j = 0; j < 8; j++)
        #pragma unroll
        for (int e = 0; e < 4; e++) Oa[j][e] = 0.0f;
    float m0 = -1e30f, m1 = -1e30f, l0 = 0.0f, l1 = 0.0f;

    const int ntiles = 2 * qt + 2;

    auto load_tile = [&](int kt, int stage) {
        const uint32_t dstbase = sb + stage * AT_STAGE;
        #pragma unroll
        for (int i = 0; i < 2; i++) {
            const int rem = tid + i * 256;
            const int row = rem >> 3, dch = rem & 7;
            const size_t g = (size_t)(kt * 64 + row) * HD_ + dch * 8;
            const uint32_t dof = dstbase + row * (KSTR * 2) + dch * 16;
            CP_ASYNC16(dof + 0 * AT_TILE, Kh + g);
            CP_ASYNC16(dof + 1 * AT_TILE, Kl + g);
            CP_ASYNC16(dof + 2 * AT_TILE, Vh + g);
            CP_ASYNC16(dof + 3 * AT_TILE, Vl + g);
        }
        CP_COMMIT();
    };

    load_tile(0, 0);

    for (int kt = 0; kt < ntiles; kt++) {
        const int stage = kt & 1;
        if (kt + 1 < ntiles) { load_tile(kt + 1, (kt + 1) & 1); CP_WAIT1(); }
        else                 { CP_WAIT0(); }
        __syncthreads();

        const int k0 = kt * 64;
        if (k0 <= q0 + warp * 16 + 15) {
            const uint32_t kbh = sb + stage * AT_STAGE;
            const uint32_t kbl = kbh + AT_TILE;
            const uint32_t vbh = kbh + 2 * AT_TILE;
            const uint32_t vbl = kbh + 3 * AT_TILE;

            float Sa[8][4];
            #pragma unroll
            for (int j = 0; j < 8; j++)
                #pragma unroll
                for (int e = 0; e < 4; e++) Sa[j][e] = 0.0f;

            const uint32_t k_lro =
                (uint32_t)((((lane >> 4) << 3) + (lane & 7)) * KSTR +
                           ((lane >> 3) & 1) * 8) * 2;
            #pragma unroll
            for (int jp = 0; jp < 4; jp++) {
                const uint32_t no = (uint32_t)(jp * 16 * KSTR) * 2;
                #pragma unroll
                for (int t = 0; t < 4; t++) {
                    const uint32_t co = (uint32_t)(t * 16) * 2;
                    uint32_t kb4h[4], kb4l[4];
                    ldsm4(kb4h, kbh + no + k_lro + co);
                    ldsm4(kb4l, kbl + no + k_lro + co);
                    mma16816(Sa[2 * jp],     qfh[t], &kb4h[0]);
                    mma16816(Sa[2 * jp],     qfh[t], &kb4l[0]);
                    mma16816(Sa[2 * jp],     qfl[t], &kb4h[0]);
                    mma16816(Sa[2 * jp + 1], qfh[t], &kb4h[2]);
                    mma16816(Sa[2 * jp + 1], qfh[t], &kb4l[2]);
                    mma16816(Sa[2 * jp + 1], qfl[t], &kb4h[2]);
                }
            }

            const bool needmask = (k0 + 63 > q0 + warp * 16);
            #pragma unroll
            for (int j = 0; j < 8; j++) {
                #pragma unroll
                for (int e = 0; e < 4; e++) Sa[j][e] *= 0.125f;
                if (needmask) {
                    const int key0 = k0 + j * 8 + 2 * (lane & 3);
                    if (key0     > r0)     Sa[j][0] = -1e30f;
                    if (key0 + 1 > r0)     Sa[j][1] = -1e30f;
                    if (key0     > r0 + 8) Sa[j][2] = -1e30f;
                    if (key0 + 1 > r0 + 8) Sa[j][3] = -1e30f;
                }
            }

            float mx0 = -1e30f, mx1 = -1e30f;
            #pragma unroll
            for (int j = 0; j < 8; j++) {
                mx0 = fmaxf(mx0, fmaxf(Sa[j][0], Sa[j][1]));
                mx1 = fmaxf(mx1, fmaxf(Sa[j][2], Sa[j][3]));
            }
            mx0 = fmaxf(mx0, __shfl_xor_sync(0xffffffffu, mx0, 1));
            mx0 = fmaxf(mx0, __shfl_xor_sync(0xffffffffu, mx0, 2));
            mx1 = fmaxf(mx1, __shfl_xor_sync(0xffffffffu, mx1, 1));
            mx1 = fmaxf(mx1, __shfl_xor_sync(0xffffffffu, mx1, 2));
            const float mn0 = fmaxf(m0, mx0), mn1 = fmaxf(m1, mx1);
            const float a0 = __expf(m0 - mn0), a1 = __expf(m1 - mn1);
            m0 = mn0; m1 = mn1;
            float rs0 = 0.0f, rs1 = 0.0f;
            #pragma unroll
            for (int j = 0; j < 8; j++) {
                Sa[j][0] = __expf(Sa[j][0] - mn0); rs0 += Sa[j][0];
                Sa[j][1] = __expf(Sa[j][1] - mn0); rs0 += Sa[j][1];
                Sa[j][2] = __expf(Sa[j][2] - mn1); rs1 += Sa[j][2];
                Sa[j][3] = __expf(Sa[j][3] - mn1); rs1 += Sa[j][3];
            }
            rs0 += __shfl_xor_sync(0xffffffffu, rs0, 1);
            rs0 += __shfl_xor_sync(0xffffffffu, rs0, 2);
            rs1 += __shfl_xor_sync(0xffffffffu, rs1, 1);
            rs1 += __shfl_xor_sync(0xffffffffu, rs1, 2);
            l0 = l0 * a0 + rs0;
            l1 = l1 * a1 + rs1;
            #pragma unroll
            for (int j = 0; j < 8; j++) {
                Oa[j][0] *= a0; Oa[j][1] *= a0;
                Oa[j][2] *= a1; Oa[j][3] *= a1;
            }

            const uint32_t v_lro =
                (uint32_t)((((lane >> 3) & 1) * 8 + (lane & 7)) * KSTR +
                           (lane >> 4) * 8) * 2;
            #pragma unroll
            for (int t = 0; t < 4; t++) {
                uint32_t ah[4], al[4];
                split_pack2(Sa[2 * t][0],     Sa[2 * t][1],     ah[0], al[0]);
                split_pack2(Sa[2 * t][2],     Sa[2 * t][3],     ah[1], al[1]);
                split_pack2(Sa[2 * t + 1][0], Sa[2 * t + 1][1], ah[2], al[2]);
                split_pack2(Sa[2 * t + 1][2], Sa[2 * t + 1][3], ah[3], al[3]);
                const uint32_t ro = (uint32_t)(t * 16 * KSTR) * 2;
                #pragma unroll
                for (int jp = 0; jp < 4; jp++) {
                    const uint32_t co = (uint32_t)(jp * 16) * 2;
                    uint32_t vh4[4], vl4[4];
                    ldsm4t(vh4, vbh + ro + v_lro + co);
                    ldsm4t(vl4, vbl + ro + v_lro + co);
                    mma16816(Oa[2 * jp],     ah, &vh4[0]);
                    mma16816(Oa[2 * jp],     ah, &vl4[0]);
                    mma16816(Oa[2 * jp],     al, &vh4[0]);
                    mma16816(Oa[2 * jp + 1], ah, &vh4[2]);
                    mma16816(Oa[2 * jp + 1], ah, &vl4[2]);
                    mma16816(Oa[2 * jp + 1], al, &vh4[2]);
                }
            }
        }
        __syncthreads();
    }

    // ---- finalize: write fp32 ctx [tok][1024] ----
    const float inv0 = 1.0f / l0, inv1 = 1.0f / l1;
    const size_t row_off = (size_t)(b * L_ + r0) * D_ + h * 64;
    #pragma unroll
    for (int j = 0; j < 8; j++) {
        const int n = j * 8 + 2 * (lane & 3);
        *(float2*)(ctx + row_off + n) =
            make_float2(Oa[j][0] * inv0, Oa[j][1] * inv0);
        *(float2*)(ctx + row_off + (size_t)8 * D_ + n) =
            make_float2(Oa[j][2] * inv1, Oa[j][3] * inv1);
    }
}

// ---------------------------------------------------------------------------
// kernel_launch — graph-capturable, allocation-free
// ---------------------------------------------------------------------------
extern "C" void kernel_launch(void* const* d_in, const int* in_sizes, int n_in,
                              void* d_out, int out_size)
{
    (void)in_sizes; (void)n_in; (void)out_size;
    const float* x     = (const float*)d_in[0];
    const float* w_qkv = (const float*)d_in[1];
    const float* w_out = (const float*)d_in[2];
    float* out = (float*)d_out;

    int8_t *x1, *x2, *wq1, *wq2, *wo1, *wo2, *c1, *c2;
    __nv_bfloat16 *qh, *ql;
    float *ctx, *rsx, *rswq, *rswo, *rsc;
    cudaGetSymbolAddress((void**)&x1, g_x1);
    cudaGetSymbolAddress((void**)&x2, g_x2);
    cudaGetSymbolAddress((void**)&wq1, g_wq1);
    cudaGetSymbolAddress((void**)&wq2, g_wq2);
    cudaGetSymbolAddress((void**)&wo1, g_wo1);
    cudaGetSymbolAddress((void**)&wo2, g_wo2);
    cudaGetSymbolAddress((void**)&c1, g_c1);
    cudaGetSymbolAddress((void**)&c2, g_c2);
    cudaGetSymbolAddress((void**)&qh, g_qkvh);
    cudaGetSymbolAddress((void**)&ql, g_qkvl);
    cudaGetSymbolAddress((void**)&ctx, g_ctx);
    cudaGetSymbolAddress((void**)&rsx, g_rsx);
    cudaGetSymbolAddress((void**)&rswq, g_rswq);
    cudaGetSymbolAddress((void**)&rswo, g_rswo);
    cudaGetSymbolAddress((void**)&rsc, g_rsc);

    cudaFuncSetAttribute(attn_mma,
                         cudaFuncAttributeMaxDynamicSharedMemorySize, AT_SMEM);
    cudaFuncSetAttribute(gemm_i8_qkv,
                         cudaFuncAttributeMaxDynamicSharedMemorySize, I_SMEM);
    cudaFuncSetAttribute(gemm_i8_out,
                         cudaFuncAttributeMaxDynamicSharedMemorySize, I_SMEM);

    // single-pass per-row quantization of inputs/weights
    rowquant_k<<<TOK, 256>>>((const float4*)x, (char4*)x1, (char4*)x2, rsx);
    rowquant_k<<<3 * D_, 256>>>((const float4*)w_qkv, (char4*)wq1, (char4*)wq2, rswq);
    rowquant_k<<<D_, 256>>>((const float4*)w_out, (char4*)wo1, (char4*)wo2, rswo);

    // 1) QKV projection (int8, 3-term) -> split bf16 head-major qkv
    {
        dim3 grid(3 * D_ / 128, TOK / 64);
        gemm_i8_qkv<<<grid, 256, I_SMEM>>>(x1, x2, wq1, wq2, rsx, rswq, qh, ql, D_);
    }
    // 2) tensor-core flash attention (bf16) -> fp32 ctx
    {
        dim3 grid(L_ / 128, B_ * H_);
        attn_mma<<<grid, 256, AT_SMEM>>>(qh, ql, ctx);
    }
    // 3) per-row quantize ctx, output projection (int8, 3-term)
    rowquant_k<<<TOK, 256>>>((const float4*)ctx, (char4*)c1, (char4*)c2, rsc);
    {
        dim3 grid(D_ / 128, TOK / 64);
        gemm_i8_out<<<grid, 256, I_SMEM>>>(c1, c2, wo1, wo2, rsc, rswo, out, D_, D_);
    }
}

// round 14
// speedup vs baseline: 1.3665x; 1.0042x over previous
#include <cuda_runtime.h>
#include <cuda_bf16.h>
#include <cstdint>
#include <cstddef>

// Problem constants
#define B_   2
#define L_   2048
#define D_   1024
#define H_   16
#define HD_  64
#define TOK  (B_ * L_)          // 4096 tokens

// ---------------------------------------------------------------------------
// Scratch (__device__ globals; no cudaMalloc allowed)
// ---------------------------------------------------------------------------
__device__ __align__(16) int8_t g_x1[(size_t)TOK * D_];
__device__ __align__(16) int8_t g_x2[(size_t)TOK * D_];
__device__ __align__(16) int8_t g_wq1[(size_t)3 * D_ * D_];
__device__ __align__(16) int8_t g_wq2[(size_t)3 * D_ * D_];
__device__ __align__(16) int8_t g_wo1[(size_t)D_ * D_];
__device__ __align__(16) int8_t g_wo2[(size_t)D_ * D_];
__device__ __align__(16) int8_t g_c1[(size_t)TOK * D_];
__device__ __align__(16) int8_t g_c2[(size_t)TOK * D_];
// per-row quantization scales
__device__ float g_rsx[TOK];
__device__ float g_rswq[3 * D_];
__device__ float g_rswo[D_];
__device__ float g_rsc[TOK];
// head-major split qkv: [part(q/k/v)][b][h][l][64] bf16 hi/lo
__device__ __align__(16) __nv_bfloat16 g_qkvh[(size_t)3 * TOK * D_];
__device__ __align__(16) __nv_bfloat16 g_qkvl[(size_t)3 * TOK * D_];
// int8 2-level Q/K for attention: [part(q/k)][b][h][l][64]
#define QKROWS (2 * B_ * H_ * L_)        // 131072 rows of 64
__device__ __align__(16) int8_t g_qk1[(size_t)QKROWS * 64];
__device__ __align__(16) int8_t g_qk2[(size_t)QKROWS * 64];
__device__ float g_rsqk[QKROWS];
// attention context fp32 [tok][1024]
__device__ __align__(16) float g_ctx[(size_t)TOK * D_];

// ---------------------------------------------------------------------------
// Helpers
// ---------------------------------------------------------------------------
__device__ __forceinline__ uint32_t smem_u32(const void* p) {
    uint32_t a;
    asm("{ .reg .u64 t; cvta.to.shared.u64 t, %1; cvt.u32.u64 %0, t; }" : "=r"(a) : "l"(p));
    return a;
}

__device__ __forceinline__ void mma16816(float* c, const uint32_t* a, const uint32_t* b) {
    asm volatile("mma.sync.aligned.m16n8k16.row.col.f32.bf16.bf16.f32 "
                 "{%0,%1,%2,%3}, {%4,%5,%6,%7}, {%8,%9}, {%0,%1,%2,%3};"
                 : "+f"(c[0]), "+f"(c[1]), "+f"(c[2]), "+f"(c[3])
                 : "r"(a[0]), "r"(a[1]), "r"(a[2]), "r"(a[3]),
                   "r"(b[0]), "r"(b[1]));
}

__device__ __forceinline__ void mma_i8(int* c, const uint32_t* a, const uint32_t* b) {
    asm volatile("mma.sync.aligned.m16n8k32.row.col.s32.s8.s8.s32 "
                 "{%0,%1,%2,%3}, {%4,%5,%6,%7}, {%8,%9}, {%0,%1,%2,%3};"
                 : "+r"(c[0]), "+r"(c[1]), "+r"(c[2]), "+r"(c[3])
                 : "r"(a[0]), "r"(a[1]), "r"(a[2]), "r"(a[3]),
                   "r"(b[0]), "r"(b[1]));
}

__device__ __forceinline__ void ldsm4(uint32_t* r, uint32_t addr) {
    asm volatile("ldmatrix.sync.aligned.m8n8.x4.shared.b16 {%0,%1,%2,%3}, [%4];"
                 : "=r"(r[0]), "=r"(r[1]), "=r"(r[2]), "=r"(r[3]) : "r"(addr));
}
__device__ __forceinline__ void ldsm4t(uint32_t* r, uint32_t addr) {
    asm volatile("ldmatrix.sync.aligned.m8n8.x4.trans.shared.b16 {%0,%1,%2,%3}, [%4];"
                 : "=r"(r[0]), "=r"(r[1]), "=r"(r[2]), "=r"(r[3]) : "r"(addr));
}

__device__ __forceinline__ uint32_t pack_bf(__nv_bfloat16 lo, __nv_bfloat16 hi) {
    return (uint32_t)__bfloat16_as_ushort(lo) | ((uint32_t)__bfloat16_as_ushort(hi) << 16);
}
__device__ __forceinline__ void split_pack2(float x, float y, uint32_t& hp, uint32_t& lp) {
    __nv_bfloat16 hx = __float2bfloat16(x), hy = __float2bfloat16(y);
    __nv_bfloat16 lx = __float2bfloat16(x - __bfloat162float(hx));
    __nv_bfloat16 ly = __float2bfloat16(y - __bfloat162float(hy));
    hp = pack_bf(hx, hy);
    lp = pack_bf(lx, ly);
}

#define CP_ASYNC16(dst, src) \
    asm volatile("cp.async.cg.shared.global [%0], [%1], 16;" :: "r"(dst), "l"(src) : "memory")
#define CP_COMMIT() asm volatile("cp.async.commit_group;" ::: "memory")
#define CP_WAIT2()  asm volatile("cp.async.wait_group 2;" ::: "memory")
#define CP_WAIT1()  asm volatile("cp.async.wait_group 1;" ::: "memory")
#define CP_WAIT0()  asm volatile("cp.async.wait_group 0;" ::: "memory")

// ---------------------------------------------------------------------------
// Fused per-row absmax + two-level int8 quantization (1024-float rows).
// ---------------------------------------------------------------------------
__global__ void __launch_bounds__(256) rowquant_k(
    const float4* __restrict__ in, char4* __restrict__ q1,
    char4* __restrict__ q2, float* __restrict__ rs)
{
    __shared__ float red[8];
    const int r = blockIdx.x;
    const int t = threadIdx.x;
    const size_t idx = (size_t)r * 256 + t;
    float4 v = in[idx];
    float m = fmaxf(fmaxf(fabsf(v.x), fabsf(v.y)),
                    fmaxf(fabsf(v.z), fabsf(v.w)));
    #pragma unroll
    for (int o = 16; o; o >>= 1) m = fmaxf(m, __shfl_xor_sync(0xffffffffu, m, o));
    if ((t & 31) == 0) red[t >> 5] = m;
    __syncthreads();
    if (t == 0) {
        float mm = red[0];
        #pragma unroll
        for (int i = 1; i < 8; i++) mm = fmaxf(mm, red[i]);
        red[0] = fmaxf(mm, 1e-20f);
    }
    __syncthreads();
    const float s = red[0];
    const float k = 127.0f / s;
    float u0 = v.x * k, u1 = v.y * k, u2 = v.z * k, u3 = v.w * k;
    float a0 = rintf(u0), a1 = rintf(u1), a2 = rintf(u2), a3 = rintf(u3);
    float b0 = rintf((u0 - a0) * 254.0f), b1 = rintf((u1 - a1) * 254.0f);
    float b2 = rintf((u2 - a2) * 254.0f), b3 = rintf((u3 - a3) * 254.0f);
    q1[idx] = make_char4((int)a0, (int)a1, (int)a2, (int)a3);
    q2[idx] = make_char4((int)b0, (int)b1, (int)b2, (int)b3);
    if (t == 0) rs[r] = s;
}

// ---------------------------------------------------------------------------
// Q/K head-row quantization: one warp per 64-elem row (value = hi + lo bf16).
// rows: [part(q/k)][b][h][l]; x = s/127*(Q1 + Q2/254).
// ---------------------------------------------------------------------------
__global__ void __launch_bounds__(256) qk_quant_k(
    const __nv_bfloat16* __restrict__ qkvh,
    const __nv_bfloat16* __restrict__ qkvl,
    int8_t* __restrict__ q1, int8_t* __restrict__ q2,
    float* __restrict__ rs)
{
    const int warp = threadIdx.x >> 5, lane = threadIdx.x & 31;
    const int row = blockIdx.x * 8 + warp;           // 0 .. QKROWS-1
    // source: parts 0,1 of qkvh/qkvl (part stride TOK*D_), row*64 within
    const size_t soff = (size_t)row * 64 + (size_t)lane * 2;
    const uint32_t ph = *(const uint32_t*)(qkvh + soff);
    const uint32_t pl = *(const uint32_t*)(qkvl + soff);
    float f0 = __bfloat162float(__ushort_as_bfloat16((uint16_t)ph)) +
               __bfloat162float(__ushort_as_bfloat16((uint16_t)pl));
    float f1 = __bfloat162float(__ushort_as_bfloat16((uint16_t)(ph >> 16))) +
               __bfloat162float(__ushort_as_bfloat16((uint16_t)(pl >> 16)));
    float m = fmaxf(fabsf(f0), fabsf(f1));
    #pragma unroll
    for (int o = 16; o; o >>= 1) m = fmaxf(m, __shfl_xor_sync(0xffffffffu, m, o));
    const float s = fmaxf(m, 1e-20f);
    const float k = 127.0f / s;
    float u0 = f0 * k, u1 = f1 * k;
    float a0 = rintf(u0), a1 = rintf(u1);
    float b0 = rintf((u0 - a0) * 254.0f), b1 = rintf((u1 - a1) * 254.0f);
    char2 c1; c1.x = (char)(int)a0; c1.y = (char)(int)a1;
    char2 c2; c2.x = (char)(int)b0; c2.y = (char)(int)b1;
    *(char2*)(q1 + soff) = c1;
    *(char2*)(q2 + soff) = c2;
    if (lane == 0) rs[row] = s;
}

// ---------------------------------------------------------------------------
// int8 GEMM (3-term, per-row scales) — proven R13 kernel, unchanged.
// ---------------------------------------------------------------------------
#define ISROW   48
#define IT_A    (64 * ISROW)
#define IT_B    (128 * ISROW)
#define I_STAGE (2 * IT_A + 2 * IT_B)
#define I_SMEM  (4 * I_STAGE)

#define GEMM_I8_BODY(A1p, A2p, B1p, B2p, K)                                    \
    extern __shared__ __align__(16) char smemraw[];                            \
    const uint32_t sb = smem_u32(smemraw);                                     \
    const int tid = threadIdx.x, lane = tid & 31, warp = tid >> 5;             \
    const int wm = warp >> 2, wn = warp & 3;                                   \
    const int bm = blockIdx.y * 64, bn = blockIdx.x * 128;                     \
    int acc1[2][4][4], accX[2][4][4];                                          \
    _Pragma("unroll")                                                          \
    for (int i = 0; i < 2; i++)                                                \
        _Pragma("unroll")                                                      \
        for (int j = 0; j < 4; j++)                                            \
            _Pragma("unroll")                                                  \
            for (int e = 0; e < 4; e++) { acc1[i][j][e] = 0; accX[i][j][e] = 0; } \
    const int nk = K / 32;                                                     \
    auto load_st = [&](int kt, int st) {                                       \
        const uint32_t base = sb + st * I_STAGE;                               \
        const int ko = kt * 32;                                                \
        _Pragma("unroll")                                                      \
        for (int i = 0; i < 3; i++) {                                          \
            const int idx = tid + i * 256;                                     \
            uint32_t dst; const int8_t* src;                                   \
            if (idx < 256) {                                                   \
                const int var = idx >> 7, rem = idx & 127;                     \
                const int row = rem >> 1, seg = rem & 1;                       \
                dst = base + var * IT_A + row * ISROW + seg * 16;              \
                src = (var == 0 ? A1p : A2p) +                                 \
                      (size_t)(bm + row) * K + ko + seg * 16;                  \
            } else {                                                           \
                const int j2 = idx - 256;                                      \
                const int var = j2 >> 8, rem = j2 & 255;                       \
                const int row = rem >> 1, seg = rem & 1;                       \
                dst = base + 2 * IT_A + var * IT_B + row * ISROW + seg * 16;   \
                src = (var == 0 ? B1p : B2p) +                                 \
                      (size_t)(bn + row) * K + ko + seg * 16;                  \
            }                                                                  \
            CP_ASYNC16(dst, src);                                              \
        }                                                                      \
        CP_COMMIT();                                                           \
    };                                                                         \
    load_st(0, 0); load_st(1, 1); load_st(2, 2);                               \
    for (int kt = 0; kt < nk; kt++) {                                          \
        const int st = kt & 3;                                                 \
        if (kt + 2 < nk)      { CP_WAIT2(); }                                  \
        else if (kt + 1 < nk) { CP_WAIT1(); }                                  \
        else                  { CP_WAIT0(); }                                  \
        __syncthreads();                                                       \
        if (kt + 3 < nk) load_st(kt + 3, (kt + 3) & 3);                        \
        const uint32_t aT = sb + st * I_STAGE;                                 \
        const uint32_t a_lro = (uint32_t)((lane & 15) * ISROW + (lane >> 4) * 16); \
        const uint32_t b_lro = (uint32_t)((((lane >> 4) << 3) + (lane & 7)) * ISROW + \
                                          ((lane >> 3) & 1) * 16);             \
        uint32_t f1[2][4], f2[2][4], gB1[2][4], gB2[2][4];                     \
        _Pragma("unroll")                                                      \
        for (int mi = 0; mi < 2; mi++) {                                       \
            const uint32_t mo = (uint32_t)((wm * 32 + mi * 16) * ISROW);       \
            ldsm4(f1[mi], aT + 0 * IT_A + mo + a_lro);                         \
            ldsm4(f2[mi], aT + 1 * IT_A + mo + a_lro);                         \
        }                                                                      \
        _Pragma("unroll")                                                      \
        for (int np = 0; np < 2; np++) {                                       \
            const uint32_t no = (uint32_t)((wn * 32 + np * 16) * ISROW);       \
            ldsm4(gB1[np], aT + 2 * IT_A + no + b_lro);                        \
            ldsm4(gB2[np], aT + 2 * IT_A + IT_B + no + b_lro);                 \
        }                                                                      \
        _Pragma("unroll")                                                      \
        for (int mi = 0; mi < 2; mi++)                                         \
            _Pragma("unroll")                                                  \
            for (int nj = 0; nj < 4; nj++)                                     \
                mma_i8(acc1[mi][nj], f1[mi], &gB1[nj >> 1][(nj & 1) * 2]);     \
        _Pragma("unroll")                                                      \
        for (int mi = 0; mi < 2; mi++)                                         \
            _Pragma("unroll")                                                  \
            for (int nj = 0; nj < 4; nj++)                                     \
                mma_i8(accX[mi][nj], f1[mi], &gB2[nj >> 1][(nj & 1) * 2]);     \
        _Pragma("unroll")                                                      \
        for (int mi = 0; mi < 2; mi++)                                         \
            _Pragma("unroll")                                                  \
            for (int nj = 0; nj < 4; nj++)                                     \
                mma_i8(accX[mi][nj], f2[mi], &gB1[nj >> 1][(nj & 1) * 2]);     \
    }

#define RAW(mi, nj, e) \
    ((float)acc1[mi][nj][e] + (float)accX[mi][nj][e] * (1.0f / 254.0f))

// QKV projection: per-row dequant + split bf16 head-major writeout
__global__ void __launch_bounds__(256) gemm_i8_qkv(
    const int8_t* __restrict__ A1p, const int8_t* __restrict__ A2p,
    const int8_t* __restrict__ B1p, const int8_t* __restrict__ B2p,
    const float* __restrict__ rsA, const float* __restrict__ rsB,
    __nv_bfloat16* __restrict__ Qh, __nv_bfloat16* __restrict__ Ql, int K)
{
    GEMM_I8_BODY(A1p, A2p, B1p, B2p, K)
    #pragma unroll
    for (int mi = 0; mi < 2; mi++) {
        const int m = bm + wm * 32 + mi * 16 + (lane >> 2);   // token
        const int bb = m >> 11, ll = m & 2047;
        const float sa0 = __ldg(rsA + m)     * (1.0f / 16129.0f);
        const float sa1 = __ldg(rsA + m + 8) * (1.0f / 16129.0f);
        #pragma unroll
        for (int nj = 0; nj < 4; nj++) {
            const int n = bn + wn * 32 + nj * 8 + (lane & 3) * 2;
            const float sb0 = __ldg(rsB + n), sb1 = __ldg(rsB + n + 1);
            const int part = n >> 10, rem = n & 1023, hh = rem >> 6, dd = rem & 63;
            const size_t off = (((size_t)(part * B_ + bb) * H_ + hh) * L_ + ll) * HD_ + dd;
            uint32_t hp, lp;
            split_pack2(sa0 * sb0 * RAW(mi, nj, 0), sa0 * sb1 * RAW(mi, nj, 1), hp, lp);
            *(uint32_t*)(Qh + off) = hp;
            *(uint32_t*)(Ql + off) = lp;
            split_pack2(sa1 * sb0 * RAW(mi, nj, 2), sa1 * sb1 * RAW(mi, nj, 3), hp, lp);
            *(uint32_t*)(Qh + off + (size_t)8 * HD_) = hp;
            *(uint32_t*)(Ql + off + (size_t)8 * HD_) = lp;
        }
    }
}

// Output projection: per-row dequant + fp32 row-major C[M,N]
__global__ void __launch_bounds__(256) gemm_i8_out(
    const int8_t* __restrict__ A1p, const int8_t* __restrict__ A2p,
    const int8_t* __restrict__ B1p, const int8_t* __restrict__ B2p,
    const float* __restrict__ rsA, const float* __restrict__ rsB,
    float* __restrict__ C, int N, int K)
{
    GEMM_I8_BODY(A1p, A2p, B1p, B2p, K)
    #pragma unroll
    for (int mi = 0; mi < 2; mi++) {
        const int m = bm + wm * 32 + mi * 16 + (lane >> 2);
        const float sa0 = __ldg(rsA + m)     * (1.0f / 16129.0f);
        const float sa1 = __ldg(rsA + m + 8) * (1.0f / 16129.0f);
        #pragma unroll
        for (int nj = 0; nj < 4; nj++) {
            const int n = bn + wn * 32 + nj * 8 + (lane & 3) * 2;
            const float sb0 = __ldg(rsB + n), sb1 = __ldg(rsB + n + 1);
            *(float2*)(C + (size_t)m * N + n) =
                make_float2(sa0 * sb0 * RAW(mi, nj, 0), sa0 * sb1 * RAW(mi, nj, 1));
            *(float2*)(C + (size_t)(m + 8) * N + n) =
                make_float2(sa1 * sb0 * RAW(mi, nj, 2), sa1 * sb1 * RAW(mi, nj, 3));
        }
    }
}

// ---------------------------------------------------------------------------
// Causal flash attention: int8 3-term QK^T (per-row scales), bf16 3-term PV.
// Block = (b,h) x 128-row Q tile; 256 threads, 8 warps; warp owns 16 rows.
// Smem per stage: K1(64x80) K2(64x80) Vh(64x144) Vl(64x144) sK(64 f32).
// ---------------------------------------------------------------------------
#define KROW8 80                          // int8 K tile row stride (bytes)
#define AK_TILE (64 * KROW8)              // 5120
#define KSTR  72                          // V bf16 row stride (elems)
#define AV_TILE (64 * KSTR * 2)           // 9216
#define AT_STAGE (2 * AK_TILE + 2 * AV_TILE + 256)   // 28928
#define AT_SMEM  (2 * AT_STAGE)           // 57856

__global__ void __launch_bounds__(256, 2) attn_mma(
    const int8_t* __restrict__ qk1, const int8_t* __restrict__ qk2,
    const float* __restrict__ rsqk,
    const __nv_bfloat16* __restrict__ qkvh,
    const __nv_bfloat16* __restrict__ qkvl,
    float* __restrict__ ctx)
{
    extern __shared__ __align__(16) char smem[];
    const uint32_t sb = smem_u32(smem);
    const int tid = threadIdx.x, lane = tid & 31, warp = tid >> 5;
    const int qt = (int)gridDim.x - 1 - (int)blockIdx.x;
    const int bh = blockIdx.y, b = bh >> 4, h = bh & 15;
    const int q0 = qt * 128;
    const size_t PART = (size_t)TOK * D_;
    const size_t headoff = (size_t)bh * L_ * HD_;
    const int8_t* Q8a = qk1 + headoff;                    // Q part
    const int8_t* Q8b = qk2 + headoff;
    const int8_t* K8a = qk1 + (size_t)B_ * H_ * L_ * 64 + headoff;   // K part
    const int8_t* K8b = qk2 + (size_t)B_ * H_ * L_ * 64 + headoff;
    const float* rsQ = rsqk + (size_t)bh * L_;
    const float* rsK = rsqk + (size_t)B_ * H_ * L_ + (size_t)bh * L_;
    const __nv_bfloat16* Vh = qkvh + 2 * PART + headoff;
    const __nv_bfloat16* Vl = qkvl + 2 * PART + headoff;

    const int r0 = q0 + warp * 16 + (lane >> 2);

    // Q int8 fragments from global: m16k32 a-frag layout, 2 k-chunks, 2 levels
    uint32_t qf1[2][4], qf2[2][4];
    {
        const int8_t* p1 = Q8a + (size_t)r0 * 64 + 4 * (lane & 3);
        const int8_t* p2 = Q8b + (size_t)r0 * 64 + 4 * (lane & 3);
        #pragma unroll
        for (int c = 0; c < 2; c++) {
            qf1[c][0] = *(const uint32_t*)(p1 + c * 32);
            qf1[c][1] = *(const uint32_t*)(p1 + 8 * 64 + c * 32);
            qf1[c][2] = *(const uint32_t*)(p1 + c * 32 + 16);
            qf1[c][3] = *(const uint32_t*)(p1 + 8 * 64 + c * 32 + 16);
            qf2[c][0] = *(const uint32_t*)(p2 + c * 32);
            qf2[c][1] = *(const uint32_t*)(p2 + 8 * 64 + c * 32);
            qf2[c][2] = *(const uint32_t*)(p2 + c * 32 + 16);
            qf2[c][3] = *(const uint32_t*)(p2 + 8 * 64 + c * 32 + 16);
        }
    }
    // folded dequant scales for the two rows (0.125 logit scale included)
    const float sQ0 = __ldg(rsQ + r0)     * (0.125f / 16129.0f);
    const float sQ1 = __ldg(rsQ + r0 + 8) * (0.125f / 16129.0f);

    float Oa[8][4];
    #pragma unroll
    for (int j = 0; j < 8; j++)
        #pragma unroll
        for (int e = 0; e < 4; e++) Oa[j][e] = 0.0f;
    float m0 = -1e30f, m1 = -1e30f, l0 = 0.0f, l1 = 0.0f;

    const int ntiles = 2 * qt + 2;

    auto load_tile = [&](int kt, int stage) {
        const uint32_t dstbase = sb + stage * AT_STAGE;
        const int k0 = kt * 64;
        // K int8: 64 rows x 4 segs, two levels
        {
            const int row = tid >> 2, seg = tid & 3;
            const size_t g = (size_t)(k0 + row) * 64 + seg * 16;
            const uint32_t dof = dstbase + row * KROW8 + seg * 16;
            CP_ASYNC16(dof, K8a + g);
            CP_ASYNC16(dof + AK_TILE, K8b + g);
        }
        // V bf16: 64 rows x 8 segs, two levels
        #pragma unroll
        for (int i = 0; i < 2; i++) {
            const int rem = tid + i * 256;
            const int row = rem >> 3, dch = rem & 7;
            const size_t g = (size_t)(k0 + row) * HD_ + dch * 8;
            const uint32_t dof = dstbase + 2 * AK_TILE + row * (KSTR * 2) + dch * 16;
            CP_ASYNC16(dof, Vh + g);
            CP_ASYNC16(dof + AV_TILE, Vl + g);
        }
        // sK: 64 floats = 16 segs
        if (tid < 16) {
            CP_ASYNC16(dstbase + 2 * AK_TILE + 2 * AV_TILE + tid * 16,
                       (const int8_t*)(rsK + k0) + tid * 16);
        }
        CP_COMMIT();
    };

    load_tile(0, 0);

    for (int kt = 0; kt < ntiles; kt++) {
        const int stage = kt & 1;
        if (kt + 1 < ntiles) { load_tile(kt + 1, (kt + 1) & 1); CP_WAIT1(); }
        else                 { CP_WAIT0(); }
        __syncthreads();

        const int k0 = kt * 64;
        if (k0 <= q0 + warp * 16 + 15) {
            const uint32_t kb1 = sb + stage * AT_STAGE;
            const uint32_t kb2 = kb1 + AK_TILE;
            const uint32_t vbh = kb1 + 2 * AK_TILE;
            const uint32_t vbl = vbh + AV_TILE;
            const float* skp = (const float*)(smem + stage * AT_STAGE +
                                              2 * AK_TILE + 2 * AV_TILE);

            // ---- S = Q K^T (int8, 3-term) ----
            float Sa[8][4];
            const uint32_t k_lro =
                (uint32_t)((((lane >> 4) << 3) + (lane & 7)) * KROW8 +
                           ((lane >> 3) & 1) * 16);
            #pragma unroll
            for (int jp = 0; jp < 4; jp++) {
                int c1a[4] = {0, 0, 0, 0}, cXa[4] = {0, 0, 0, 0};
                int c1b[4] = {0, 0, 0, 0}, cXb[4] = {0, 0, 0, 0};
                const uint32_t no = (uint32_t)(jp * 16 * KROW8);
                #pragma unroll
                for (int c = 0; c < 2; c++) {
                    uint32_t k4a[4], k4b[4];
                    ldsm4(k4a, kb1 + no + k_lro + c * 32);
                    ldsm4(k4b, kb2 + no + k_lro + c * 32);
                    mma_i8(c1a, qf1[c], &k4a[0]);
                    mma_i8(cXa, qf1[c], &k4b[0]);
                    mma_i8(cXa, qf2[c], &k4a[0]);
                    mma_i8(c1b, qf1[c], &k4a[2]);
                    mma_i8(cXb, qf1[c], &k4b[2]);
                    mma_i8(cXb, qf2[c], &k4a[2]);
                }
                const int kloc = jp * 16 + 2 * (lane & 3);
                const float skA0 = skp[kloc],     skA1 = skp[kloc + 1];
                const float skB0 = skp[kloc + 8], skB1 = skp[kloc + 9];
                Sa[2 * jp][0] = sQ0 * skA0 * ((float)c1a[0] + (float)cXa[0] * (1.0f / 254.0f));
                Sa[2 * jp][1] = sQ0 * skA1 * ((float)c1a[1] + (float)cXa[1] * (1.0f / 254.0f));
                Sa[2 * jp][2] = sQ1 * skA0 * ((float)c1a[2] + (float)cXa[2] * (1.0f / 254.0f));
                Sa[2 * jp][3] = sQ1 * skA1 * ((float)c1a[3] + (float)cXa[3] * (1.0f / 254.0f));
                Sa[2 * jp + 1][0] = sQ0 * skB0 * ((float)c1b[0] + (float)cXb[0] * (1.0f / 254.0f));
                Sa[2 * jp + 1][1] = sQ0 * skB1 * ((float)c1b[1] + (float)cXb[1] * (1.0f / 254.0f));
                Sa[2 * jp + 1][2] = sQ1 * skB0 * ((float)c1b[2] + (float)cXb[2] * (1.0f / 254.0f));
                Sa[2 * jp + 1][3] = sQ1 * skB1 * ((float)c1b[3] + (float)cXb[3] * (1.0f / 254.0f));
            }

            // ---- causal mask (logit scale already folded) ----
            const bool needmask = (k0 + 63 > q0 + warp * 16);
            if (needmask) {
                #pragma unroll
                for (int j = 0; j < 8; j++) {
                    const int key0 = k0 + j * 8 + 2 * (lane & 3);
                    if (key0     > r0)     Sa[j][0] = -1e30f;
                    if (key0 + 1 > r0)     Sa[j][1] = -1e30f;
                    if (key0     > r0 + 8) Sa[j][2] = -1e30f;
                    if (key0 + 1 > r0 + 8) Sa[j][3] = -1e30f;
                }
            }

            // ---- online softmax ----
            float mx0 = -1e30f, mx1 = -1e30f;
            #pragma unroll
            for (int j = 0; j < 8; j++) {
                mx0 = fmaxf(mx0, fmaxf(Sa[j][0], Sa[j][1]));
                mx1 = fmaxf(mx1, fmaxf(Sa[j][2], Sa[j][3]));
            }
            mx0 = fmaxf(mx0, __shfl_xor_sync(0xffffffffu, mx0, 1));
            mx0 = fmaxf(mx0, __shfl_xor_sync(0xffffffffu, mx0, 2));
            mx1 = fmaxf(mx1, __shfl_xor_sync(0xffffffffu, mx1, 1));
            mx1 = fmaxf(mx1, __shfl_xor_sync(0xffffffffu, mx1, 2));
            const float mn0 = fmaxf(m0, mx0), mn1 = fmaxf(m1, mx1);
            const float a0 = __expf(m0 - mn0), a1 = __expf(m1 - mn1);
            m0 = mn0; m1 = mn1;
            float rs0 = 0.0f, rs1 = 0.0f;
            #pragma unroll
            for (int j = 0; j < 8; j++) {
                Sa[j][0] = __expf(Sa[j][0] - mn0); rs0 += Sa[j][0];
                Sa[j][1] = __expf(Sa[j][1] - mn0); rs0 += Sa[j][1];
                Sa[j][2] = __expf(Sa[j][2] - mn1); rs1 += Sa[j][2];
                Sa[j][3] = __expf(Sa[j][3] - mn1); rs1 += Sa[j][3];
            }
            rs0 += __shfl_xor_sync(0xffffffffu, rs0, 1);
            rs0 += __shfl_xor_sync(0xffffffffu, rs0, 2);
            rs1 += __shfl_xor_sync(0xffffffffu, rs1, 1);
            rs1 += __shfl_xor_sync(0xffffffffu, rs1, 2);
            l0 = l0 * a0 + rs0;
            l1 = l1 * a1 + rs1;
            #pragma unroll
            for (int j = 0; j < 8; j++) {
                Oa[j][0] *= a0; Oa[j][1] *= a0;
                Oa[j][2] *= a1; Oa[j][3] *= a1;
            }

            // ---- O += P V (bf16 3-term; V frags via ldmatrix.trans) ----
            const uint32_t v_lro =
                (uint32_t)((((lane >> 3) & 1) * 8 + (lane & 7)) * KSTR +
                           (lane >> 4) * 8) * 2;
            #pragma unroll
            for (int t = 0; t < 4; t++) {
                uint32_t ah[4], al[4];
                split_pack2(Sa[2 * t][0],     Sa[2 * t][1],     ah[0], al[0]);
                split_pack2(Sa[2 * t][2],     Sa[2 * t][3],     ah[1], al[1]);
                split_pack2(Sa[2 * t + 1][0], Sa[2 * t + 1][1], ah[2], al[2]);
                split_pack2(Sa[2 * t + 1][2], Sa[2 * t + 1][3], ah[3], al[3]);
                const uint32_t ro = (uint32_t)(t * 16 * KSTR) * 2;
                #pragma unroll
                for (int jp = 0; jp < 4; jp++) {
                    const uint32_t co = (uint32_t)(jp * 16) * 2;
                    uint32_t vh4[4], vl4[4];
                    ldsm4t(vh4, vbh + ro + v_lro + co);
                    ldsm4t(vl4, vbl + ro + v_lro + co);
                    mma16816(Oa[2 * jp],     ah, &vh4[0]);
                    mma16816(Oa[2 * jp],     ah, &vl4[0]);
                    mma16816(Oa[2 * jp],     al, &vh4[0]);
                    mma16816(Oa[2 * jp + 1], ah, &vh4[2]);
                    mma16816(Oa[2 * jp + 1], ah, &vl4[2]);
                    mma16816(Oa[2 * jp + 1], al, &vh4[2]);
                }
            }
        }
        __syncthreads();
    }

    // ---- finalize: write fp32 ctx [tok][1024] ----
    const float inv0 = 1.0f / l0, inv1 = 1.0f / l1;
    const size_t row_off = (size_t)(b * L_ + r0) * D_ + h * 64;
    #pragma unroll
    for (int j = 0; j < 8; j++) {
        const int n = j * 8 + 2 * (lane & 3);
        *(float2*)(ctx + row_off + n) =
            make_float2(Oa[j][0] * inv0, Oa[j][1] * inv0);
        *(float2*)(ctx + row_off + (size_t)8 * D_ + n) =
            make_float2(Oa[j][2] * inv1, Oa[j][3] * inv1);
    }
}

// ---------------------------------------------------------------------------
// kernel_launch — graph-capturable, allocation-free
// ---------------------------------------------------------------------------
extern "C" void kernel_launch(void* const* d_in, const int* in_sizes, int n_in,
                              void* d_out, int out_size)
{
    (void)in_sizes; (void)n_in; (void)out_size;
    const float* x     = (const float*)d_in[0];
    const float* w_qkv = (const float*)d_in[1];
    const float* w_out = (const float*)d_in[2];
    float* out = (float*)d_out;

    int8_t *x1, *x2, *wq1, *wq2, *wo1, *wo2, *c1, *c2, *qk1, *qk2;
    __nv_bfloat16 *qh, *ql;
    float *ctx, *rsx, *rswq, *rswo, *rsc, *rsqk;
    cudaGetSymbolAddress((void**)&x1, g_x1);
    cudaGetSymbolAddress((void**)&x2, g_x2);
    cudaGetSymbolAddress((void**)&wq1, g_wq1);
    cudaGetSymbolAddress((void**)&wq2, g_wq2);
    cudaGetSymbolAddress((void**)&wo1, g_wo1);
    cudaGetSymbolAddress((void**)&wo2, g_wo2);
    cudaGetSymbolAddress((void**)&c1, g_c1);
    cudaGetSymbolAddress((void**)&c2, g_c2);
    cudaGetSymbolAddress((void**)&qk1, g_qk1);
    cudaGetSymbolAddress((void**)&qk2, g_qk2);
    cudaGetSymbolAddress((void**)&qh, g_qkvh);
    cudaGetSymbolAddress((void**)&ql, g_qkvl);
    cudaGetSymbolAddress((void**)&ctx, g_ctx);
    cudaGetSymbolAddress((void**)&rsx, g_rsx);
    cudaGetSymbolAddress((void**)&rswq, g_rswq);
    cudaGetSymbolAddress((void**)&rswo, g_rswo);
    cudaGetSymbolAddress((void**)&rsc, g_rsc);
    cudaGetSymbolAddress((void**)&rsqk, g_rsqk);

    cudaFuncSetAttribute(attn_mma,
                         cudaFuncAttributeMaxDynamicSharedMemorySize, AT_SMEM);
    cudaFuncSetAttribute(gemm_i8_qkv,
                         cudaFuncAttributeMaxDynamicSharedMemorySize, I_SMEM);
    cudaFuncSetAttribute(gemm_i8_out,
                         cudaFuncAttributeMaxDynamicSharedMemorySize, I_SMEM);

    // single-pass per-row quantization of inputs/weights
    rowquant_k<<<TOK, 256>>>((const float4*)x, (char4*)x1, (char4*)x2, rsx);
    rowquant_k<<<3 * D_, 256>>>((const float4*)w_qkv, (char4*)wq1, (char4*)wq2, rswq);
    rowquant_k<<<D_, 256>>>((const float4*)w_out, (char4*)wo1, (char4*)wo2, rswo);

    // 1) QKV projection (int8, 3-term) -> split bf16 head-major qkv
    {
        dim3 grid(3 * D_ / 128, TOK / 64);
        gemm_i8_qkv<<<grid, 256, I_SMEM>>>(x1, x2, wq1, wq2, rsx, rswq, qh, ql, D_);
    }
    // 1b) quantize Q,K head-rows to 2-level int8
    qk_quant_k<<<QKROWS / 8, 256>>>(qh, ql, qk1, qk2, rsqk);

    // 2) flash attention (int8 QK^T + bf16 PV) -> fp32 ctx
    {
        dim3 grid(L_ / 128, B_ * H_);
        attn_mma<<<grid, 256, AT_SMEM>>>(qk1, qk2, rsqk, qh, ql, ctx);
    }
    // 3) per-row quantize ctx, output projection (int8, 3-term)
    rowquant_k<<<TOK, 256>>>((const float4*)ctx, (char4*)c1, (char4*)c2, rsc);
    {
        dim3 grid(D_ / 128, TOK / 64);
        gemm_i8_out<<<grid, 256, I_SMEM>>>(c1, c2, wo1, wo2, rsc, rswo, out, D_, D_);
    }
}

// round 15
// speedup vs baseline: 1.5114x; 1.1060x over previous
#include <cuda_runtime.h>
#include <cuda_bf16.h>
#include <cstdint>
#include <cstddef>

// Problem constants
#define B_   2
#define L_   2048
#define D_   1024
#define H_   16
#define HD_  64
#define TOK  (B_ * L_)          // 4096 tokens

// ---------------------------------------------------------------------------
// Scratch (__device__ globals; no cudaMalloc allowed)
// ---------------------------------------------------------------------------
__device__ __align__(16) int8_t g_x1[(size_t)TOK * D_];
__device__ __align__(16) int8_t g_x2[(size_t)TOK * D_];
__device__ __align__(16) int8_t g_wq1[(size_t)3 * D_ * D_];
__device__ __align__(16) int8_t g_wq2[(size_t)3 * D_ * D_];
__device__ __align__(16) int8_t g_wo1[(size_t)D_ * D_];
__device__ __align__(16) int8_t g_wo2[(size_t)D_ * D_];
__device__ __align__(16) int8_t g_c1[(size_t)TOK * D_];
__device__ __align__(16) int8_t g_c2[(size_t)TOK * D_];
// per-row quantization scales
__device__ float g_rsx[TOK];
__device__ float g_rswq[3 * D_];
__device__ float g_rswo[D_];
__device__ float g_rsc[TOK];
// head-major split qkv: [part(q/k/v)][b][h][l][64] bf16 hi/lo
__device__ __align__(16) __nv_bfloat16 g_qkvh[(size_t)3 * TOK * D_];
__device__ __align__(16) __nv_bfloat16 g_qkvl[(size_t)3 * TOK * D_];
// int8 2-level Q/K for attention: [part(q/k)][b][h][l][64]
#define QKROWS (2 * B_ * H_ * L_)        // 131072 rows of 64
__device__ __align__(16) int8_t g_qk1[(size_t)QKROWS * 64];
__device__ __align__(16) int8_t g_qk2[(size_t)QKROWS * 64];
__device__ float g_rsqk[QKROWS];
// attention context fp32 [tok][1024]
__device__ __align__(16) float g_ctx[(size_t)TOK * D_];

// ---------------------------------------------------------------------------
// Helpers
// ---------------------------------------------------------------------------
__device__ __forceinline__ uint32_t smem_u32(const void* p) {
    uint32_t a;
    asm("{ .reg .u64 t; cvta.to.shared.u64 t, %1; cvt.u32.u64 %0, t; }" : "=r"(a) : "l"(p));
    return a;
}

__device__ __forceinline__ void mma16816(float* c, const uint32_t* a, const uint32_t* b) {
    asm volatile("mma.sync.aligned.m16n8k16.row.col.f32.bf16.bf16.f32 "
                 "{%0,%1,%2,%3}, {%4,%5,%6,%7}, {%8,%9}, {%0,%1,%2,%3};"
                 : "+f"(c[0]), "+f"(c[1]), "+f"(c[2]), "+f"(c[3])
                 : "r"(a[0]), "r"(a[1]), "r"(a[2]), "r"(a[3]),
                   "r"(b[0]), "r"(b[1]));
}

__device__ __forceinline__ void mma_i8(int* c, const uint32_t* a, const uint32_t* b) {
    asm volatile("mma.sync.aligned.m16n8k32.row.col.s32.s8.s8.s32 "
                 "{%0,%1,%2,%3}, {%4,%5,%6,%7}, {%8,%9}, {%0,%1,%2,%3};"
                 : "+r"(c[0]), "+r"(c[1]), "+r"(c[2]), "+r"(c[3])
                 : "r"(a[0]), "r"(a[1]), "r"(a[2]), "r"(a[3]),
                   "r"(b[0]), "r"(b[1]));
}

__device__ __forceinline__ void ldsm4(uint32_t* r, uint32_t addr) {
    asm volatile("ldmatrix.sync.aligned.m8n8.x4.shared.b16 {%0,%1,%2,%3}, [%4];"
                 : "=r"(r[0]), "=r"(r[1]), "=r"(r[2]), "=r"(r[3]) : "r"(addr));
}
__device__ __forceinline__ void ldsm4t(uint32_t* r, uint32_t addr) {
    asm volatile("ldmatrix.sync.aligned.m8n8.x4.trans.shared.b16 {%0,%1,%2,%3}, [%4];"
                 : "=r"(r[0]), "=r"(r[1]), "=r"(r[2]), "=r"(r[3]) : "r"(addr));
}

// fast split: pack (x,y) to bf16x2 hi pair + bf16x2 lo (residual) pair
__device__ __forceinline__ void split_pack2(float x, float y, uint32_t& hp, uint32_t& lp) {
    asm("cvt.rn.satfinite.bf16x2.f32 %0, %1, %2;" : "=r"(hp) : "f"(y), "f"(x));
    const float hx = __bfloat162float(__ushort_as_bfloat16((uint16_t)hp));
    const float hy = __bfloat162float(__ushort_as_bfloat16((uint16_t)(hp >> 16)));
    asm("cvt.rn.satfinite.bf16x2.f32 %0, %1, %2;" : "=r"(lp) : "f"(y - hy), "f"(x - hx));
}

#define CP_ASYNC16(dst, src) \
    asm volatile("cp.async.cg.shared.global [%0], [%1], 16;" :: "r"(dst), "l"(src) : "memory")
#define CP_COMMIT() asm volatile("cp.async.commit_group;" ::: "memory")
#define CP_WAIT1()  asm volatile("cp.async.wait_group 1;" ::: "memory")
#define CP_WAIT0()  asm volatile("cp.async.wait_group 0;" ::: "memory")

// ---------------------------------------------------------------------------
// Per-row absmax + two-level int8 quantization: one WARP per 1024-float row,
// no block barriers (shfl-only reduction), 8 rows per 256-thread block.
// ---------------------------------------------------------------------------
__global__ void __launch_bounds__(256) rowquant_k(
    const float4* __restrict__ in, char4* __restrict__ q1,
    char4* __restrict__ q2, float* __restrict__ rs)
{
    const int warp = threadIdx.x >> 5, lane = threadIdx.x & 31;
    const int r = blockIdx.x * 8 + warp;
    const float4* rowp = in + (size_t)r * 256;
    float4 v[8];
    float m = 0.0f;
    #pragma unroll
    for (int i = 0; i < 8; i++) {
        v[i] = rowp[lane + i * 32];
        m = fmaxf(m, fmaxf(fmaxf(fabsf(v[i].x), fabsf(v[i].y)),
                           fmaxf(fabsf(v[i].z), fabsf(v[i].w))));
    }
    #pragma unroll
    for (int o = 16; o; o >>= 1) m = fmaxf(m, __shfl_xor_sync(0xffffffffu, m, o));
    const float s = fmaxf(m, 1e-20f);
    const float k = 127.0f / s;
    #pragma unroll
    for (int i = 0; i < 8; i++) {
        float u0 = v[i].x * k, u1 = v[i].y * k, u2 = v[i].z * k, u3 = v[i].w * k;
        float a0 = rintf(u0), a1 = rintf(u1), a2 = rintf(u2), a3 = rintf(u3);
        float b0 = rintf((u0 - a0) * 254.0f), b1 = rintf((u1 - a1) * 254.0f);
        float b2 = rintf((u2 - a2) * 254.0f), b3 = rintf((u3 - a3) * 254.0f);
        const size_t idx = (size_t)r * 256 + lane + i * 32;
        q1[idx] = make_char4((int)a0, (int)a1, (int)a2, (int)a3);
        q2[idx] = make_char4((int)b0, (int)b1, (int)b2, (int)b3);
    }
    if (lane == 0) rs[r] = s;
}

// ---------------------------------------------------------------------------
// Q/K head-row quantization: one warp per 64-elem row (value = hi + lo bf16).
// ---------------------------------------------------------------------------
__global__ void __launch_bounds__(256) qk_quant_k(
    const __nv_bfloat16* __restrict__ qkvh,
    const __nv_bfloat16* __restrict__ qkvl,
    int8_t* __restrict__ q1, int8_t* __restrict__ q2,
    float* __restrict__ rs)
{
    const int warp = threadIdx.x >> 5, lane = threadIdx.x & 31;
    const int row = blockIdx.x * 8 + warp;
    const size_t soff = (size_t)row * 64 + (size_t)lane * 2;
    const uint32_t ph = *(const uint32_t*)(qkvh + soff);
    const uint32_t pl = *(const uint32_t*)(qkvl + soff);
    float f0 = __bfloat162float(__ushort_as_bfloat16((uint16_t)ph)) +
               __bfloat162float(__ushort_as_bfloat16((uint16_t)pl));
    float f1 = __bfloat162float(__ushort_as_bfloat16((uint16_t)(ph >> 16))) +
               __bfloat162float(__ushort_as_bfloat16((uint16_t)(pl >> 16)));
    float m = fmaxf(fabsf(f0), fabsf(f1));
    #pragma unroll
    for (int o = 16; o; o >>= 1) m = fmaxf(m, __shfl_xor_sync(0xffffffffu, m, o));
    const float s = fmaxf(m, 1e-20f);
    const float k = 127.0f / s;
    float u0 = f0 * k, u1 = f1 * k;
    float a0 = rintf(u0), a1 = rintf(u1);
    float b0 = rintf((u0 - a0) * 254.0f), b1 = rintf((u1 - a1) * 254.0f);
    char2 c1; c1.x = (char)(int)a0; c1.y = (char)(int)a1;
    char2 c2; c2.x = (char)(int)b0; c2.y = (char)(int)b1;
    *(char2*)(q1 + soff) = c1;
    *(char2*)(q2 + soff) = c2;
    if (lane == 0) rs[row] = s;
}

// ---------------------------------------------------------------------------
// int8 GEMM (3-term, per-row scales): C = sA[m]*sB[n]/127^2 *
//     (A1B1 + (A1B2 + A2B1)/254),   A[M,K] * B[N,K]^T.
// CTA tile 64x128, BK=64 bytes (2 k-chunks per stage -> 1 barrier per 64-K),
// 256 threads (8 warps 2x4), warp tile 32x32, 3-stage cp.async pipeline.
// Smem row stride 80B: 80r mod 128 covers 8 distinct 16B slots -> LDSM clean.
// ---------------------------------------------------------------------------
#define ISROW   80
#define IT_A    (64 * ISROW)             // 5120
#define IT_B    (128 * ISROW)            // 10240
#define I_STAGE (2 * IT_A + 2 * IT_B)    // 30720
#define I_SMEM  (3 * I_STAGE)            // 92160

#define GEMM_I8_BODY(A1p, A2p, B1p, B2p, K)                                    \
    extern __shared__ __align__(16) char smemraw[];                            \
    const uint32_t sb = smem_u32(smemraw);                                     \
    const int tid = threadIdx.x, lane = tid & 31, warp = tid >> 5;             \
    const int wm = warp >> 2, wn = warp & 3;                                   \
    const int bm = blockIdx.y * 64, bn = blockIdx.x * 128;                     \
    int acc1[2][4][4], accX[2][4][4];                                          \
    _Pragma("unroll")                                                          \
    for (int i = 0; i < 2; i++)                                                \
        _Pragma("unroll")                                                      \
        for (int j = 0; j < 4; j++)                                            \
            _Pragma("unroll")                                                  \
            for (int e = 0; e < 4; e++) { acc1[i][j][e] = 0; accX[i][j][e] = 0; } \
    const int nk = K / 64;                                                     \
    auto load_st = [&](int kt, int st) {                                       \
        const uint32_t base = sb + st * I_STAGE;                               \
        const int ko = kt * 64;                                                \
        _Pragma("unroll")                                                      \
        for (int i = 0; i < 6; i++) {                                          \
            const int idx = tid + i * 256;     /* 0..1535 */                   \
            uint32_t dst; const int8_t* src;                                   \
            if (idx < 512) {                                                   \
                const int var = idx >> 8, rem = idx & 255;                     \
                const int row = rem >> 2, seg = rem & 3;                       \
                dst = base + var * IT_A + row * ISROW + seg * 16;              \
                src = (var == 0 ? A1p : A2p) +                                 \
                      (size_t)(bm + row) * K + ko + seg * 16;                  \
            } else {                                                           \
                const int j2 = idx - 512;                                      \
                const int var = j2 >> 9, rem = j2 & 511;                       \
                const int row = rem >> 2, seg = rem & 3;                       \
                dst = base + 2 * IT_A + var * IT_B + row * ISROW + seg * 16;   \
                src = (var == 0 ? B1p : B2p) +                                 \
                      (size_t)(bn + row) * K + ko + seg * 16;                  \
            }                                                                  \
            CP_ASYNC16(dst, src);                                              \
        }                                                                      \
        CP_COMMIT();                                                           \
    };                                                                         \
    load_st(0, 0); load_st(1, 1);                                              \
    for (int kt = 0; kt < nk; kt++) {                                          \
        const int st = kt % 3;                                                 \
        if (kt + 1 < nk) { CP_WAIT1(); } else { CP_WAIT0(); }                  \
        __syncthreads();                                                       \
        if (kt + 2 < nk) load_st(kt + 2, (kt + 2) % 3);                        \
        const uint32_t aT = sb + st * I_STAGE;                                 \
        _Pragma("unroll")                                                      \
        for (int c = 0; c < 2; c++) {                                          \
            const uint32_t a_lro = (uint32_t)((lane & 15) * ISROW +            \
                                              (lane >> 4) * 16 + c * 32);      \
            const uint32_t b_lro = (uint32_t)((((lane >> 4) << 3) +            \
                                               (lane & 7)) * ISROW +           \
                                              ((lane >> 3) & 1) * 16 + c * 32);\
            uint32_t f1[2][4], f2[2][4], gB1[2][4], gB2[2][4];                 \
            _Pragma("unroll")                                                  \
            for (int mi = 0; mi < 2; mi++) {                                   \
                const uint32_t mo = (uint32_t)((wm * 32 + mi * 16) * ISROW);   \
                ldsm4(f1[mi], aT + 0 * IT_A + mo + a_lro);                     \
                ldsm4(f2[mi], aT + 1 * IT_A + mo + a_lro);                     \
            }                                                                  \
            _Pragma("unroll")                                                  \
            for (int np = 0; np < 2; np++) {                                   \
                const uint32_t no = (uint32_t)((wn * 32 + np * 16) * ISROW);   \
                ldsm4(gB1[np], aT + 2 * IT_A + no + b_lro);                    \
                ldsm4(gB2[np], aT + 2 * IT_A + IT_B + no + b_lro);             \
            }                                                                  \
            _Pragma("unroll")                                                  \
            for (int mi = 0; mi < 2; mi++)                                     \
                _Pragma("unroll")                                              \
                for (int nj = 0; nj < 4; nj++)                                 \
                    mma_i8(acc1[mi][nj], f1[mi], &gB1[nj >> 1][(nj & 1) * 2]); \
            _Pragma("unroll")                                                  \
            for (int mi = 0; mi < 2; mi++)                                     \
                _Pragma("unroll")                                              \
                for (int nj = 0; nj < 4; nj++)                                 \
                    mma_i8(accX[mi][nj], f1[mi], &gB2[nj >> 1][(nj & 1) * 2]); \
            _Pragma("unroll")                                                  \
            for (int mi = 0; mi < 2; mi++)                                     \
                _Pragma("unroll")                                              \
                for (int nj = 0; nj < 4; nj++)                                 \
                    mma_i8(accX[mi][nj], f2[mi], &gB1[nj >> 1][(nj & 1) * 2]); \
        }                                                                      \
    }

#define RAW(mi, nj, e) \
    ((float)acc1[mi][nj][e] + (float)accX[mi][nj][e] * (1.0f / 254.0f))

// QKV projection: per-row dequant + split bf16 head-major writeout
__global__ void __launch_bounds__(256) gemm_i8_qkv(
    const int8_t* __restrict__ A1p, const int8_t* __restrict__ A2p,
    const int8_t* __restrict__ B1p, const int8_t* __restrict__ B2p,
    const float* __restrict__ rsA, const float* __restrict__ rsB,
    __nv_bfloat16* __restrict__ Qh, __nv_bfloat16* __restrict__ Ql, int K)
{
    GEMM_I8_BODY(A1p, A2p, B1p, B2p, K)
    #pragma unroll
    for (int mi = 0; mi < 2; mi++) {
        const int m = bm + wm * 32 + mi * 16 + (lane >> 2);   // token
        const int bb = m >> 11, ll = m & 2047;
        const float sa0 = __ldg(rsA + m)     * (1.0f / 16129.0f);
        const float sa1 = __ldg(rsA + m + 8) * (1.0f / 16129.0f);
        #pragma unroll
        for (int nj = 0; nj < 4; nj++) {
            const int n = bn + wn * 32 + nj * 8 + (lane & 3) * 2;
            const float sb0 = __ldg(rsB + n), sb1 = __ldg(rsB + n + 1);
            const int part = n >> 10, rem = n & 1023, hh = rem >> 6, dd = rem & 63;
            const size_t off = (((size_t)(part * B_ + bb) * H_ + hh) * L_ + ll) * HD_ + dd;
            uint32_t hp, lp;
            split_pack2(sa0 * sb0 * RAW(mi, nj, 0), sa0 * sb1 * RAW(mi, nj, 1), hp, lp);
            *(uint32_t*)(Qh + off) = hp;
            *(uint32_t*)(Ql + off) = lp;
            split_pack2(sa1 * sb0 * RAW(mi, nj, 2), sa1 * sb1 * RAW(mi, nj, 3), hp, lp);
            *(uint32_t*)(Qh + off + (size_t)8 * HD_) = hp;
            *(uint32_t*)(Ql + off + (size_t)8 * HD_) = lp;
        }
    }
}

// Output projection: per-row dequant + fp32 row-major C[M,N]
__global__ void __launch_bounds__(256) gemm_i8_out(
    const int8_t* __restrict__ A1p, const int8_t* __restrict__ A2p,
    const int8_t* __restrict__ B1p, const int8_t* __restrict__ B2p,
    const float* __restrict__ rsA, const float* __restrict__ rsB,
    float* __restrict__ C, int N, int K)
{
    GEMM_I8_BODY(A1p, A2p, B1p, B2p, K)
    #pragma unroll
    for (int mi = 0; mi < 2; mi++) {
        const int m = bm + wm * 32 + mi * 16 + (lane >> 2);
        const float sa0 = __ldg(rsA + m)     * (1.0f / 16129.0f);
        const float sa1 = __ldg(rsA + m + 8) * (1.0f / 16129.0f);
        #pragma unroll
        for (int nj = 0; nj < 4; nj++) {
            const int n = bn + wn * 32 + nj * 8 + (lane & 3) * 2;
            const float sb0 = __ldg(rsB + n), sb1 = __ldg(rsB + n + 1);
            *(float2*)(C + (size_t)m * N + n) =
                make_float2(sa0 * sb0 * RAW(mi, nj, 0), sa0 * sb1 * RAW(mi, nj, 1));
            *(float2*)(C + (size_t)(m + 8) * N + n) =
                make_float2(sa1 * sb0 * RAW(mi, nj, 2), sa1 * sb1 * RAW(mi, nj, 3));
        }
    }
}

// ---------------------------------------------------------------------------
// Causal flash attention: int8 3-term QK^T (per-row scales), bf16 3-term PV.
// Unchanged from R14 except the faster split_pack2 helper.
// ---------------------------------------------------------------------------
#define KROW8 80
#define AK_TILE (64 * KROW8)
#define KSTR  72
#define AV_TILE (64 * KSTR * 2)
#define AT_STAGE (2 * AK_TILE + 2 * AV_TILE + 256)   // 28928
#define AT_SMEM  (2 * AT_STAGE)                      // 57856

__global__ void __launch_bounds__(256, 2) attn_mma(
    const int8_t* __restrict__ qk1, const int8_t* __restrict__ qk2,
    const float* __restrict__ rsqk,
    const __nv_bfloat16* __restrict__ qkvh,
    const __nv_bfloat16* __restrict__ qkvl,
    float* __restrict__ ctx)
{
    extern __shared__ __align__(16) char smem[];
    const uint32_t sb = smem_u32(smem);
    const int tid = threadIdx.x, lane = tid & 31, warp = tid >> 5;
    const int qt = (int)gridDim.x - 1 - (int)blockIdx.x;
    const int bh = blockIdx.y, b = bh >> 4, h = bh & 15;
    const int q0 = qt * 128;
    const size_t PART = (size_t)TOK * D_;
    const size_t headoff = (size_t)bh * L_ * HD_;
    const int8_t* Q8a = qk1 + headoff;
    const int8_t* Q8b = qk2 + headoff;
    const int8_t* K8a = qk1 + (size_t)B_ * H_ * L_ * 64 + headoff;
    const int8_t* K8b = qk2 + (size_t)B_ * H_ * L_ * 64 + headoff;
    const float* rsQ = rsqk + (size_t)bh * L_;
    const float* rsK = rsqk + (size_t)B_ * H_ * L_ + (size_t)bh * L_;
    const __nv_bfloat16* Vh = qkvh + 2 * PART + headoff;
    const __nv_bfloat16* Vl = qkvl + 2 * PART + headoff;

    const int r0 = q0 + warp * 16 + (lane >> 2);

    uint32_t qf1[2][4], qf2[2][4];
    {
        const int8_t* p1 = Q8a + (size_t)r0 * 64 + 4 * (lane & 3);
        const int8_t* p2 = Q8b + (size_t)r0 * 64 + 4 * (lane & 3);
        #pragma unroll
        for (int c = 0; c < 2; c++) {
            qf1[c][0] = *(const uint32_t*)(p1 + c * 32);
            qf1[c][1] = *(const uint32_t*)(p1 + 8 * 64 + c * 32);
            qf1[c][2] = *(const uint32_t*)(p1 + c * 32 + 16);
            qf1[c][3] = *(const uint32_t*)(p1 + 8 * 64 + c * 32 + 16);
            qf2[c][0] = *(const uint32_t*)(p2 + c * 32);
            qf2[c][1] = *(const uint32_t*)(p2 + 8 * 64 + c * 32);
            qf2[c][2] = *(const uint32_t*)(p2 + c * 32 + 16);
            qf2[c][3] = *(const uint32_t*)(p2 + 8 * 64 + c * 32 + 16);
        }
    }
    const float sQ0 = __ldg(rsQ + r0)     * (0.125f / 16129.0f);
    const float sQ1 = __ldg(rsQ + r0 + 8) * (0.125f / 16129.0f);

    float Oa[8][4];
    #pragma unroll
    for (int j = 0; j < 8; j++)
        #pragma unroll
        for (int e = 0; e < 4; e++) Oa[j][e] = 0.0f;
    float m0 = -1e30f, m1 = -1e30f, l0 = 0.0f, l1 = 0.0f;

    const int ntiles = 2 * qt + 2;

    auto load_tile = [&](int kt, int stage) {
        const uint32_t dstbase = sb + stage * AT_STAGE;
        const int k0 = kt * 64;
        {
            const int row = tid >> 2, seg = tid & 3;
            const size_t g = (size_t)(k0 + row) * 64 + seg * 16;
            const uint32_t dof = dstbase + row * KROW8 + seg * 16;
            CP_ASYNC16(dof, K8a + g);
            CP_ASYNC16(dof + AK_TILE, K8b + g);
        }
        #pragma unroll
        for (int i = 0; i < 2; i++) {
            const int rem = tid + i * 256;
            const int row = rem >> 3, dch = rem & 7;
            const size_t g = (size_t)(k0 + row) * HD_ + dch * 8;
            const uint32_t dof = dstbase + 2 * AK_TILE + row * (KSTR * 2) + dch * 16;
            CP_ASYNC16(dof, Vh + g);
            CP_ASYNC16(dof + AV_TILE, Vl + g);
        }
        if (tid < 16) {
            CP_ASYNC16(dstbase + 2 * AK_TILE + 2 * AV_TILE + tid * 16,
                       (const int8_t*)(rsK + k0) + tid * 16);
        }
        CP_COMMIT();
    };

    load_tile(0, 0);

    for (int kt = 0; kt < ntiles; kt++) {
        const int stage = kt & 1;
        if (kt + 1 < ntiles) { load_tile(kt + 1, (kt + 1) & 1); CP_WAIT1(); }
        else                 { CP_WAIT0(); }
        __syncthreads();

        const int k0 = kt * 64;
        if (k0 <= q0 + warp * 16 + 15) {
            const uint32_t kb1 = sb + stage * AT_STAGE;
            const uint32_t kb2 = kb1 + AK_TILE;
            const uint32_t vbh = kb1 + 2 * AK_TILE;
            const uint32_t vbl = vbh + AV_TILE;
            const float* skp = (const float*)(smem + stage * AT_STAGE +
                                              2 * AK_TILE + 2 * AV_TILE);

            float Sa[8][4];
            const uint32_t k_lro =
                (uint32_t)((((lane >> 4) << 3) + (lane & 7)) * KROW8 +
                           ((lane >> 3) & 1) * 16);
            #pragma unroll
            for (int jp = 0; jp < 4; jp++) {
                int c1a[4] = {0, 0, 0, 0}, cXa[4] = {0, 0, 0, 0};
                int c1b[4] = {0, 0, 0, 0}, cXb[4] = {0, 0, 0, 0};
                const uint32_t no = (uint32_t)(jp * 16 * KROW8);
                #pragma unroll
                for (int c = 0; c < 2; c++) {
                    uint32_t k4a[4], k4b[4];
                    ldsm4(k4a, kb1 + no + k_lro + c * 32);
                    ldsm4(k4b, kb2 + no + k_lro + c * 32);
                    mma_i8(c1a, qf1[c], &k4a[0]);
                    mma_i8(cXa, qf1[c], &k4b[0]);
                    mma_i8(cXa, qf2[c], &k4a[0]);
                    mma_i8(c1b, qf1[c], &k4a[2]);
                    mma_i8(cXb, qf1[c], &k4b[2]);
                    mma_i8(cXb, qf2[c], &k4a[2]);
                }
                const int kloc = jp * 16 + 2 * (lane & 3);
                const float skA0 = skp[kloc],     skA1 = skp[kloc + 1];
                const float skB0 = skp[kloc + 8], skB1 = skp[kloc + 9];
                Sa[2 * jp][0] = sQ0 * skA0 * ((float)c1a[0] + (float)cXa[0] * (1.0f / 254.0f));
                Sa[2 * jp][1] = sQ0 * skA1 * ((float)c1a[1] + (float)cXa[1] * (1.0f / 254.0f));
                Sa[2 * jp][2] = sQ1 * skA0 * ((float)c1a[2] + (float)cXa[2] * (1.0f / 254.0f));
                Sa[2 * jp][3] = sQ1 * skA1 * ((float)c1a[3] + (float)cXa[3] * (1.0f / 254.0f));
                Sa[2 * jp + 1][0] = sQ0 * skB0 * ((float)c1b[0] + (float)cXb[0] * (1.0f / 254.0f));
                Sa[2 * jp + 1][1] = sQ0 * skB1 * ((float)c1b[1] + (float)cXb[1] * (1.0f / 254.0f));
                Sa[2 * jp + 1][2] = sQ1 * skB0 * ((float)c1b[2] + (float)cXb[2] * (1.0f / 254.0f));
                Sa[2 * jp + 1][3] = sQ1 * skB1 * ((float)c1b[3] + (float)cXb[3] * (1.0f / 254.0f));
            }

            const bool needmask = (k0 + 63 > q0 + warp * 16);
            if (needmask) {
                #pragma unroll
                for (int j = 0; j < 8; j++) {
                    const int key0 = k0 + j * 8 + 2 * (lane & 3);
                    if (key0     > r0)     Sa[j][0] = -1e30f;
                    if (key0 + 1 > r0)     Sa[j][1] = -1e30f;
                    if (key0     > r0 + 8) Sa[j][2] = -1e30f;
                    if (key0 + 1 > r0 + 8) Sa[j][3] = -1e30f;
                }
            }

            float mx0 = -1e30f, mx1 = -1e30f;
            #pragma unroll
            for (int j = 0; j < 8; j++) {
                mx0 = fmaxf(mx0, fmaxf(Sa[j][0], Sa[j][1]));
                mx1 = fmaxf(mx1, fmaxf(Sa[j][2], Sa[j][3]));
            }
            mx0 = fmaxf(mx0, __shfl_xor_sync(0xffffffffu, mx0, 1));
            mx0 = fmaxf(mx0, __shfl_xor_sync(0xffffffffu, mx0, 2));
            mx1 = fmaxf(mx1, __shfl_xor_sync(0xffffffffu, mx1, 1));
            mx1 = fmaxf(mx1, __shfl_xor_sync(0xffffffffu, mx1, 2));
            const float mn0 = fmaxf(m0, mx0), mn1 = fmaxf(m1, mx1);
            const float a0 = __expf(m0 - mn0), a1 = __expf(m1 - mn1);
            m0 = mn0; m1 = mn1;
            float rs0 = 0.0f, rs1 = 0.0f;
            #pragma unroll
            for (int j = 0; j < 8; j++) {
                Sa[j][0] = __expf(Sa[j][0] - mn0); rs0 += Sa[j][0];
                Sa[j][1] = __expf(Sa[j][1] - mn0); rs0 += Sa[j][1];
                Sa[j][2] = __expf(Sa[j][2] - mn1); rs1 += Sa[j][2];
                Sa[j][3] = __expf(Sa[j][3] - mn1); rs1 += Sa[j][3];
            }
            rs0 += __shfl_xor_sync(0xffffffffu, rs0, 1);
            rs0 += __shfl_xor_sync(0xffffffffu, rs0, 2);
            rs1 += __shfl_xor_sync(0xffffffffu, rs1, 1);
            rs1 += __shfl_xor_sync(0xffffffffu, rs1, 2);
            l0 = l0 * a0 + rs0;
            l1 = l1 * a1 + rs1;
            #pragma unroll
            for (int j = 0; j < 8; j++) {
                Oa[j][0] *= a0; Oa[j][1] *= a0;
                Oa[j][2] *= a1; Oa[j][3] *= a1;
            }

            const uint32_t v_lro =
                (uint32_t)((((lane >> 3) & 1) * 8 + (lane & 7)) * KSTR +
                           (lane >> 4) * 8) * 2;
            #pragma unroll
            for (int t = 0; t < 4; t++) {
                uint32_t ah[4], al[4];
                split_pack2(Sa[2 * t][0],     Sa[2 * t][1],     ah[0], al[0]);
                split_pack2(Sa[2 * t][2],     Sa[2 * t][3],     ah[1], al[1]);
                split_pack2(Sa[2 * t + 1][0], Sa[2 * t + 1][1], ah[2], al[2]);
                split_pack2(Sa[2 * t + 1][2], Sa[2 * t + 1][3], ah[3], al[3]);
                const uint32_t ro = (uint32_t)(t * 16 * KSTR) * 2;
                #pragma unroll
                for (int jp = 0; jp < 4; jp++) {
                    const uint32_t co = (uint32_t)(jp * 16) * 2;
                    uint32_t vh4[4], vl4[4];
                    ldsm4t(vh4, vbh + ro + v_lro + co);
                    ldsm4t(vl4, vbl + ro + v_lro + co);
                    mma16816(Oa[2 * jp],     ah, &vh4[0]);
                    mma16816(Oa[2 * jp],     ah, &vl4[0]);
                    mma16816(Oa[2 * jp],     al, &vh4[0]);
                    mma16816(Oa[2 * jp + 1], ah, &vh4[2]);
                    mma16816(Oa[2 * jp + 1], ah, &vl4[2]);
                    mma16816(Oa[2 * jp + 1], al, &vh4[2]);
                }
            }
        }
        __syncthreads();
    }

    const float inv0 = 1.0f / l0, inv1 = 1.0f / l1;
    const size_t row_off = (size_t)(b * L_ + r0) * D_ + h * 64;
    #pragma unroll
    for (int j = 0; j < 8; j++) {
        const int n = j * 8 + 2 * (lane & 3);
        *(float2*)(ctx + row_off + n) =
            make_float2(Oa[j][0] * inv0, Oa[j][1] * inv0);
        *(float2*)(ctx + row_off + (size_t)8 * D_ + n) =
            make_float2(Oa[j][2] * inv1, Oa[j][3] * inv1);
    }
}

// ---------------------------------------------------------------------------
// kernel_launch — graph-capturable, allocation-free
// ---------------------------------------------------------------------------
extern "C" void kernel_launch(void* const* d_in, const int* in_sizes, int n_in,
                              void* d_out, int out_size)
{
    (void)in_sizes; (void)n_in; (void)out_size;
    const float* x     = (const float*)d_in[0];
    const float* w_qkv = (const float*)d_in[1];
    const float* w_out = (const float*)d_in[2];
    float* out = (float*)d_out;

    int8_t *x1, *x2, *wq1, *wq2, *wo1, *wo2, *c1, *c2, *qk1, *qk2;
    __nv_bfloat16 *qh, *ql;
    float *ctx, *rsx, *rswq, *rswo, *rsc, *rsqk;
    cudaGetSymbolAddress((void**)&x1, g_x1);
    cudaGetSymbolAddress((void**)&x2, g_x2);
    cudaGetSymbolAddress((void**)&wq1, g_wq1);
    cudaGetSymbolAddress((void**)&wq2, g_wq2);
    cudaGetSymbolAddress((void**)&wo1, g_wo1);
    cudaGetSymbolAddress((void**)&wo2, g_wo2);
    cudaGetSymbolAddress((void**)&c1, g_c1);
    cudaGetSymbolAddress((void**)&c2, g_c2);
    cudaGetSymbolAddress((void**)&qk1, g_qk1);
    cudaGetSymbolAddress((void**)&qk2, g_qk2);
    cudaGetSymbolAddress((void**)&qh, g_qkvh);
    cudaGetSymbolAddress((void**)&ql, g_qkvl);
    cudaGetSymbolAddress((void**)&ctx, g_ctx);
    cudaGetSymbolAddress((void**)&rsx, g_rsx);
    cudaGetSymbolAddress((void**)&rswq, g_rswq);
    cudaGetSymbolAddress((void**)&rswo, g_rswo);
    cudaGetSymbolAddress((void**)&rsc, g_rsc);
    cudaGetSymbolAddress((void**)&rsqk, g_rsqk);

    cudaFuncSetAttribute(attn_mma,
                         cudaFuncAttributeMaxDynamicSharedMemorySize, AT_SMEM);
    cudaFuncSetAttribute(gemm_i8_qkv,
                         cudaFuncAttributeMaxDynamicSharedMemorySize, I_SMEM);
    cudaFuncSetAttribute(gemm_i8_out,
                         cudaFuncAttributeMaxDynamicSharedMemorySize, I_SMEM);

    // warp-per-row quantization (no block barriers)
    rowquant_k<<<TOK / 8, 256>>>((const float4*)x, (char4*)x1, (char4*)x2, rsx);
    rowquant_k<<<3 * D_ / 8, 256>>>((const float4*)w_qkv, (char4*)wq1, (char4*)wq2, rswq);
    rowquant_k<<<D_ / 8, 256>>>((const float4*)w_out, (char4*)wo1, (char4*)wo2, rswo);

    // 1) QKV projection (int8, 3-term, BK=64) -> split bf16 head-major qkv
    {
        dim3 grid(3 * D_ / 128, TOK / 64);
        gemm_i8_qkv<<<grid, 256, I_SMEM>>>(x1, x2, wq1, wq2, rsx, rswq, qh, ql, D_);
    }
    // 1b) quantize Q,K head-rows to 2-level int8
    qk_quant_k<<<QKROWS / 8, 256>>>(qh, ql, qk1, qk2, rsqk);

    // 2) flash attention (int8 QK^T + bf16 PV) -> fp32 ctx
    {
        dim3 grid(L_ / 128, B_ * H_);
        attn_mma<<<grid, 256, AT_SMEM>>>(qk1, qk2, rsqk, qh, ql, ctx);
    }
    // 3) per-row quantize ctx, output projection (int8, 3-term)
    rowquant_k<<<TOK / 8, 256>>>((const float4*)ctx, (char4*)c1, (char4*)c2, rsc);
    {
        dim3 grid(D_ / 128, TOK / 64);
        gemm_i8_out<<<grid, 256, I_SMEM>>>(c1, c2, wo1, wo2, rsc, rswo, out, D_, D_);
    }
}

// round 16
// speedup vs baseline: 1.6553x; 1.0952x over previous
#include <cuda_runtime.h>
#include <cuda_bf16.h>
#include <cuda_fp16.h>
#include <cstdint>
#include <cstddef>

// Problem constants
#define B_   2
#define L_   2048
#define D_   1024
#define H_   16
#define HD_  64
#define TOK  (B_ * L_)          // 4096 tokens

// ---------------------------------------------------------------------------
// Scratch (__device__ globals; no cudaMalloc allowed)
// ---------------------------------------------------------------------------
__device__ __align__(16) int8_t g_x1[(size_t)TOK * D_];
__device__ __align__(16) int8_t g_x2[(size_t)TOK * D_];
__device__ __align__(16) int8_t g_wq1[(size_t)3 * D_ * D_];
__device__ __align__(16) int8_t g_wq2[(size_t)3 * D_ * D_];
__device__ __align__(16) int8_t g_wo1[(size_t)D_ * D_];
__device__ __align__(16) int8_t g_wo2[(size_t)D_ * D_];
__device__ __align__(16) int8_t g_c1[(size_t)TOK * D_];
__device__ __align__(16) int8_t g_c2[(size_t)TOK * D_];
// per-row quantization scales
__device__ float g_rsx[TOK];
__device__ float g_rswq[3 * D_];
__device__ float g_rswo[D_];
__device__ float g_rsc[TOK];
// head-major split qkv: [part(q/k/v)][b][h][l][64]
// parts 0,1 (Q,K): bf16 hi/lo (consumed by qk_quant)
// part 2 (V): fp16 hi/lo (consumed by attention PV)
__device__ __align__(16) __nv_bfloat16 g_qkvh[(size_t)3 * TOK * D_];
__device__ __align__(16) __nv_bfloat16 g_qkvl[(size_t)3 * TOK * D_];
// int8 2-level Q/K for attention: [part(q/k)][b][h][l][64]
#define QKROWS (2 * B_ * H_ * L_)        // 131072 rows of 64
__device__ __align__(16) int8_t g_qk1[(size_t)QKROWS * 64];
__device__ __align__(16) int8_t g_qk2[(size_t)QKROWS * 64];
__device__ float g_rsqk[QKROWS];
// attention context fp32 [tok][1024]
__device__ __align__(16) float g_ctx[(size_t)TOK * D_];

// ---------------------------------------------------------------------------
// Helpers
// ---------------------------------------------------------------------------
__device__ __forceinline__ uint32_t smem_u32(const void* p) {
    uint32_t a;
    asm("{ .reg .u64 t; cvta.to.shared.u64 t, %1; cvt.u32.u64 %0, t; }" : "=r"(a) : "l"(p));
    return a;
}

__device__ __forceinline__ void mma_f16(float* c, const uint32_t* a, const uint32_t* b) {
    asm volatile("mma.sync.aligned.m16n8k16.row.col.f32.f16.f16.f32 "
                 "{%0,%1,%2,%3}, {%4,%5,%6,%7}, {%8,%9}, {%0,%1,%2,%3};"
                 : "+f"(c[0]), "+f"(c[1]), "+f"(c[2]), "+f"(c[3])
                 : "r"(a[0]), "r"(a[1]), "r"(a[2]), "r"(a[3]),
                   "r"(b[0]), "r"(b[1]));
}

__device__ __forceinline__ void mma_i8(int* c, const uint32_t* a, const uint32_t* b) {
    asm volatile("mma.sync.aligned.m16n8k32.row.col.s32.s8.s8.s32 "
                 "{%0,%1,%2,%3}, {%4,%5,%6,%7}, {%8,%9}, {%0,%1,%2,%3};"
                 : "+r"(c[0]), "+r"(c[1]), "+r"(c[2]), "+r"(c[3])
                 : "r"(a[0]), "r"(a[1]), "r"(a[2]), "r"(a[3]),
                   "r"(b[0]), "r"(b[1]));
}

__device__ __forceinline__ void ldsm4(uint32_t* r, uint32_t addr) {
    asm volatile("ldmatrix.sync.aligned.m8n8.x4.shared.b16 {%0,%1,%2,%3}, [%4];"
                 : "=r"(r[0]), "=r"(r[1]), "=r"(r[2]), "=r"(r[3]) : "r"(addr));
}
__device__ __forceinline__ void ldsm4t(uint32_t* r, uint32_t addr) {
    asm volatile("ldmatrix.sync.aligned.m8n8.x4.trans.shared.b16 {%0,%1,%2,%3}, [%4];"
                 : "=r"(r[0]), "=r"(r[1]), "=r"(r[2]), "=r"(r[3]) : "r"(addr));
}

// bf16 split: pack (x,y) to bf16x2 hi pair + bf16x2 lo (residual) pair
__device__ __forceinline__ void split_pack2(float x, float y, uint32_t& hp, uint32_t& lp) {
    asm("cvt.rn.satfinite.bf16x2.f32 %0, %1, %2;" : "=r"(hp) : "f"(y), "f"(x));
    const float hx = __bfloat162float(__ushort_as_bfloat16((uint16_t)hp));
    const float hy = __bfloat162float(__ushort_as_bfloat16((uint16_t)(hp >> 16)));
    asm("cvt.rn.satfinite.bf16x2.f32 %0, %1, %2;" : "=r"(lp) : "f"(y - hy), "f"(x - hx));
}
// fp16 split: pack (x,y) to f16x2 hi pair + f16x2 lo (residual) pair
__device__ __forceinline__ void split_pack2_f16(float x, float y, uint32_t& hp, uint32_t& lp) {
    asm("cvt.rn.f16x2.f32 %0, %1, %2;" : "=r"(hp) : "f"(y), "f"(x));
    const float hx = __half2float(__ushort_as_half((uint16_t)hp));
    const float hy = __half2float(__ushort_as_half((uint16_t)(hp >> 16)));
    asm("cvt.rn.f16x2.f32 %0, %1, %2;" : "=r"(lp) : "f"(y - hy), "f"(x - hx));
}
// single fp16 pack (no residual)
__device__ __forceinline__ uint32_t pack_f16(float x, float y) {
    uint32_t p;
    asm("cvt.rn.f16x2.f32 %0, %1, %2;" : "=r"(p) : "f"(y), "f"(x));
    return p;
}

#define CP_ASYNC16(dst, src) \
    asm volatile("cp.async.cg.shared.global [%0], [%1], 16;" :: "r"(dst), "l"(src) : "memory")
#define CP_COMMIT() asm volatile("cp.async.commit_group;" ::: "memory")
#define CP_WAIT1()  asm volatile("cp.async.wait_group 1;" ::: "memory")
#define CP_WAIT0()  asm volatile("cp.async.wait_group 0;" ::: "memory")

// ---------------------------------------------------------------------------
// Warp-per-row absmax + 2-level int8 quant, fused over x / w_qkv / w_out.
// rows: [0,4096) -> x, [4096,7168) -> w_qkv, [7168,8192) -> w_out.
// ---------------------------------------------------------------------------
__global__ void __launch_bounds__(256) rowquant3_k(
    const float4* __restrict__ x, const float4* __restrict__ wq,
    const float4* __restrict__ wo,
    char4* __restrict__ x1, char4* __restrict__ x2,
    char4* __restrict__ wq1, char4* __restrict__ wq2,
    char4* __restrict__ wo1, char4* __restrict__ wo2,
    float* __restrict__ rsx, float* __restrict__ rswq, float* __restrict__ rswo)
{
    const int warp = threadIdx.x >> 5, lane = threadIdx.x & 31;
    const int g = blockIdx.x * 8 + warp;
    const float4* in; char4 *q1, *q2; float* rs; int r;
    if (g < 4096)      { in = x;  q1 = x1;  q2 = x2;  rs = rsx;  r = g; }
    else if (g < 7168) { in = wq; q1 = wq1; q2 = wq2; rs = rswq; r = g - 4096; }
    else               { in = wo; q1 = wo1; q2 = wo2; rs = rswo; r = g - 7168; }

    const float4* rowp = in + (size_t)r * 256;
    float4 v[8];
    float m = 0.0f;
    #pragma unroll
    for (int i = 0; i < 8; i++) {
        v[i] = rowp[lane + i * 32];
        m = fmaxf(m, fmaxf(fmaxf(fabsf(v[i].x), fabsf(v[i].y)),
                           fmaxf(fabsf(v[i].z), fabsf(v[i].w))));
    }
    #pragma unroll
    for (int o = 16; o; o >>= 1) m = fmaxf(m, __shfl_xor_sync(0xffffffffu, m, o));
    const float s = fmaxf(m, 1e-20f);
    const float k = 127.0f / s;
    #pragma unroll
    for (int i = 0; i < 8; i++) {
        float u0 = v[i].x * k, u1 = v[i].y * k, u2 = v[i].z * k, u3 = v[i].w * k;
        float a0 = rintf(u0), a1 = rintf(u1), a2 = rintf(u2), a3 = rintf(u3);
        float b0 = rintf((u0 - a0) * 254.0f), b1 = rintf((u1 - a1) * 254.0f);
        float b2 = rintf((u2 - a2) * 254.0f), b3 = rintf((u3 - a3) * 254.0f);
        const size_t idx = (size_t)r * 256 + lane + i * 32;
        q1[idx] = make_char4((int)a0, (int)a1, (int)a2, (int)a3);
        q2[idx] = make_char4((int)b0, (int)b1, (int)b2, (int)b3);
    }
    if (lane == 0) rs[r] = s;
}

// single-tensor variant (for ctx)
__global__ void __launch_bounds__(256) rowquant_k(
    const float4* __restrict__ in, char4* __restrict__ q1,
    char4* __restrict__ q2, float* __restrict__ rs)
{
    const int warp = threadIdx.x >> 5, lane = threadIdx.x & 31;
    const int r = blockIdx.x * 8 + warp;
    const float4* rowp = in + (size_t)r * 256;
    float4 v[8];
    float m = 0.0f;
    #pragma unroll
    for (int i = 0; i < 8; i++) {
        v[i] = rowp[lane + i * 32];
        m = fmaxf(m, fmaxf(fmaxf(fabsf(v[i].x), fabsf(v[i].y)),
                           fmaxf(fabsf(v[i].z), fabsf(v[i].w))));
    }
    #pragma unroll
    for (int o = 16; o; o >>= 1) m = fmaxf(m, __shfl_xor_sync(0xffffffffu, m, o));
    const float s = fmaxf(m, 1e-20f);
    const float k = 127.0f / s;
    #pragma unroll
    for (int i = 0; i < 8; i++) {
        float u0 = v[i].x * k, u1 = v[i].y * k, u2 = v[i].z * k, u3 = v[i].w * k;
        float a0 = rintf(u0), a1 = rintf(u1), a2 = rintf(u2), a3 = rintf(u3);
        float b0 = rintf((u0 - a0) * 254.0f), b1 = rintf((u1 - a1) * 254.0f);
        float b2 = rintf((u2 - a2) * 254.0f), b3 = rintf((u3 - a3) * 254.0f);
        const size_t idx = (size_t)r * 256 + lane + i * 32;
        q1[idx] = make_char4((int)a0, (int)a1, (int)a2, (int)a3);
        q2[idx] = make_char4((int)b0, (int)b1, (int)b2, (int)b3);
    }
    if (lane == 0) rs[r] = s;
}

// ---------------------------------------------------------------------------
// Q/K head-row quantization (reads bf16 hi/lo parts 0,1): warp per 64-row.
// ---------------------------------------------------------------------------
__global__ void __launch_bounds__(256) qk_quant_k(
    const __nv_bfloat16* __restrict__ qkvh,
    const __nv_bfloat16* __restrict__ qkvl,
    int8_t* __restrict__ q1, int8_t* __restrict__ q2,
    float* __restrict__ rs)
{
    const int warp = threadIdx.x >> 5, lane = threadIdx.x & 31;
    const int row = blockIdx.x * 8 + warp;
    const size_t soff = (size_t)row * 64 + (size_t)lane * 2;
    const uint32_t ph = *(const uint32_t*)(qkvh + soff);
    const uint32_t pl = *(const uint32_t*)(qkvl + soff);
    float f0 = __bfloat162float(__ushort_as_bfloat16((uint16_t)ph)) +
               __bfloat162float(__ushort_as_bfloat16((uint16_t)pl));
    float f1 = __bfloat162float(__ushort_as_bfloat16((uint16_t)(ph >> 16))) +
               __bfloat162float(__ushort_as_bfloat16((uint16_t)(pl >> 16)));
    float m = fmaxf(fabsf(f0), fabsf(f1));
    #pragma unroll
    for (int o = 16; o; o >>= 1) m = fmaxf(m, __shfl_xor_sync(0xffffffffu, m, o));
    const float s = fmaxf(m, 1e-20f);
    const float k = 127.0f / s;
    float u0 = f0 * k, u1 = f1 * k;
    float a0 = rintf(u0), a1 = rintf(u1);
    float b0 = rintf((u0 - a0) * 254.0f), b1 = rintf((u1 - a1) * 254.0f);
    char2 c1; c1.x = (char)(int)a0; c1.y = (char)(int)a1;
    char2 c2; c2.x = (char)(int)b0; c2.y = (char)(int)b1;
    *(char2*)(q1 + soff) = c1;
    *(char2*)(q2 + soff) = c2;
    if (lane == 0) rs[row] = s;
}

// ---------------------------------------------------------------------------
// int8 GEMM (3-term, per-row scales) — proven R15 body (BK=64, 3-stage).
// ---------------------------------------------------------------------------
#define ISROW   80
#define IT_A    (64 * ISROW)
#define IT_B    (128 * ISROW)
#define I_STAGE (2 * IT_A + 2 * IT_B)
#define I_SMEM  (3 * I_STAGE)

#define GEMM_I8_BODY(A1p, A2p, B1p, B2p, K)                                    \
    extern __shared__ __align__(16) char smemraw[];                            \
    const uint32_t sb = smem_u32(smemraw);                                     \
    const int tid = threadIdx.x, lane = tid & 31, warp = tid >> 5;             \
    const int wm = warp >> 2, wn = warp & 3;                                   \
    const int bm = blockIdx.y * 64, bn = blockIdx.x * 128;                     \
    int acc1[2][4][4], accX[2][4][4];                                          \
    _Pragma("unroll")                                                          \
    for (int i = 0; i < 2; i++)                                                \
        _Pragma("unroll")                                                      \
        for (int j = 0; j < 4; j++)                                            \
            _Pragma("unroll")                                                  \
            for (int e = 0; e < 4; e++) { acc1[i][j][e] = 0; accX[i][j][e] = 0; } \
    const int nk = K / 64;                                                     \
    auto load_st = [&](int kt, int st) {                                       \
        const uint32_t base = sb + st * I_STAGE;                               \
        const int ko = kt * 64;                                                \
        _Pragma("unroll")                                                      \
        for (int i = 0; i < 6; i++) {                                          \
            const int idx = tid + i * 256;                                     \
            uint32_t dst; const int8_t* src;                                   \
            if (idx < 512) {                                                   \
                const int var = idx >> 8, rem = idx & 255;                     \
                const int row = rem >> 2, seg = rem & 3;                       \
                dst = base + var * IT_A + row * ISROW + seg * 16;              \
                src = (var == 0 ? A1p : A2p) +                                 \
                      (size_t)(bm + row) * K + ko + seg * 16;                  \
            } else {                                                           \
                const int j2 = idx - 512;                                      \
                const int var = j2 >> 9, rem = j2 & 511;                       \
                const int row = rem >> 2, seg = rem & 3;                       \
                dst = base + 2 * IT_A + var * IT_B + row * ISROW + seg * 16;   \
                src = (var == 0 ? B1p : B2p) +                                 \
                      (size_t)(bn + row) * K + ko + seg * 16;                  \
            }                                                                  \
            CP_ASYNC16(dst, src);                                              \
        }                                                                      \
        CP_COMMIT();                                                           \
    };                                                                         \
    load_st(0, 0); load_st(1, 1);                                              \
    for (int kt = 0; kt < nk; kt++) {                                          \
        const int st = kt % 3;                                                 \
        if (kt + 1 < nk) { CP_WAIT1(); } else { CP_WAIT0(); }                  \
        __syncthreads();                                                       \
        if (kt + 2 < nk) load_st(kt + 2, (kt + 2) % 3);                        \
        const uint32_t aT = sb + st * I_STAGE;                                 \
        _Pragma("unroll")                                                      \
        for (int c = 0; c < 2; c++) {                                          \
            const uint32_t a_lro = (uint32_t)((lane & 15) * ISROW +            \
                                              (lane >> 4) * 16 + c * 32);      \
            const uint32_t b_lro = (uint32_t)((((lane >> 4) << 3) +            \
                                               (lane & 7)) * ISROW +           \
                                              ((lane >> 3) & 1) * 16 + c * 32);\
            uint32_t f1[2][4], f2[2][4], gB1[2][4], gB2[2][4];                 \
            _Pragma("unroll")                                                  \
            for (int mi = 0; mi < 2; mi++) {                                   \
                const uint32_t mo = (uint32_t)((wm * 32 + mi * 16) * ISROW);   \
                ldsm4(f1[mi], aT + 0 * IT_A + mo + a_lro);                     \
                ldsm4(f2[mi], aT + 1 * IT_A + mo + a_lro);                     \
            }                                                                  \
            _Pragma("unroll")                                                  \
            for (int np = 0; np < 2; np++) {                                   \
                const uint32_t no = (uint32_t)((wn * 32 + np * 16) * ISROW);   \
                ldsm4(gB1[np], aT + 2 * IT_A + no + b_lro);                    \
                ldsm4(gB2[np], aT + 2 * IT_A + IT_B + no + b_lro);             \
            }                                                                  \
            _Pragma("unroll")                                                  \
            for (int mi = 0; mi < 2; mi++)                                     \
                _Pragma("unroll")                                              \
                for (int nj = 0; nj < 4; nj++)                                 \
                    mma_i8(acc1[mi][nj], f1[mi], &gB1[nj >> 1][(nj & 1) * 2]); \
            _Pragma("unroll")                                                  \
            for (int mi = 0; mi < 2; mi++)                                     \
                _Pragma("unroll")                                              \
                for (int nj = 0; nj < 4; nj++)                                 \
                    mma_i8(accX[mi][nj], f1[mi], &gB2[nj >> 1][(nj & 1) * 2]); \
            _Pragma("unroll")                                                  \
            for (int mi = 0; mi < 2; mi++)                                     \
                _Pragma("unroll")                                              \
                for (int nj = 0; nj < 4; nj++)                                 \
                    mma_i8(accX[mi][nj], f2[mi], &gB1[nj >> 1][(nj & 1) * 2]); \
        }                                                                      \
    }

#define RAW(mi, nj, e) \
    ((float)acc1[mi][nj][e] + (float)accX[mi][nj][e] * (1.0f / 254.0f))

// QKV projection: per-row dequant; parts 0,1 (Q,K) -> bf16 hi/lo,
// part 2 (V) -> fp16 hi/lo. Head-major writeout.
__global__ void __launch_bounds__(256) gemm_i8_qkv(
    const int8_t* __restrict__ A1p, const int8_t* __restrict__ A2p,
    const int8_t* __restrict__ B1p, const int8_t* __restrict__ B2p,
    const float* __restrict__ rsA, const float* __restrict__ rsB,
    __nv_bfloat16* __restrict__ Qh, __nv_bfloat16* __restrict__ Ql, int K)
{
    GEMM_I8_BODY(A1p, A2p, B1p, B2p, K)
    const int part = bn >> 10;           // whole CTA tile in one part
    #pragma unroll
    for (int mi = 0; mi < 2; mi++) {
        const int m = bm + wm * 32 + mi * 16 + (lane >> 2);   // token
        const int bb = m >> 11, ll = m & 2047;
        const float sa0 = __ldg(rsA + m)     * (1.0f / 16129.0f);
        const float sa1 = __ldg(rsA + m + 8) * (1.0f / 16129.0f);
        #pragma unroll
        for (int nj = 0; nj < 4; nj++) {
            const int n = bn + wn * 32 + nj * 8 + (lane & 3) * 2;
            const float sb0 = __ldg(rsB + n), sb1 = __ldg(rsB + n + 1);
            const int rem = n & 1023, hh = rem >> 6, dd = rem & 63;
            const size_t off = (((size_t)(part * B_ + bb) * H_ + hh) * L_ + ll) * HD_ + dd;
            uint32_t hp, lp;
            if (part == 2) {
                split_pack2_f16(sa0 * sb0 * RAW(mi, nj, 0), sa0 * sb1 * RAW(mi, nj, 1), hp, lp);
            } else {
                split_pack2(sa0 * sb0 * RAW(mi, nj, 0), sa0 * sb1 * RAW(mi, nj, 1), hp, lp);
            }
            *(uint32_t*)(Qh + off) = hp;
            *(uint32_t*)(Ql + off) = lp;
            if (part == 2) {
                split_pack2_f16(sa1 * sb0 * RAW(mi, nj, 2), sa1 * sb1 * RAW(mi, nj, 3), hp, lp);
            } else {
                split_pack2(sa1 * sb0 * RAW(mi, nj, 2), sa1 * sb1 * RAW(mi, nj, 3), hp, lp);
            }
            *(uint32_t*)(Qh + off + (size_t)8 * HD_) = hp;
            *(uint32_t*)(Ql + off + (size_t)8 * HD_) = lp;
        }
    }
}

// Output projection: per-row dequant + fp32 row-major C[M,N]
__global__ void __launch_bounds__(256) gemm_i8_out(
    const int8_t* __restrict__ A1p, const int8_t* __restrict__ A2p,
    const int8_t* __restrict__ B1p, const int8_t* __restrict__ B2p,
    const float* __restrict__ rsA, const float* __restrict__ rsB,
    float* __restrict__ C, int N, int K)
{
    GEMM_I8_BODY(A1p, A2p, B1p, B2p, K)
    #pragma unroll
    for (int mi = 0; mi < 2; mi++) {
        const int m = bm + wm * 32 + mi * 16 + (lane >> 2);
        const float sa0 = __ldg(rsA + m)     * (1.0f / 16129.0f);
        const float sa1 = __ldg(rsA + m + 8) * (1.0f / 16129.0f);
        #pragma unroll
        for (int nj = 0; nj < 4; nj++) {
            const int n = bn + wn * 32 + nj * 8 + (lane & 3) * 2;
            const float sb0 = __ldg(rsB + n), sb1 = __ldg(rsB + n + 1);
            *(float2*)(C + (size_t)m * N + n) =
                make_float2(sa0 * sb0 * RAW(mi, nj, 0), sa0 * sb1 * RAW(mi, nj, 1));
            *(float2*)(C + (size_t)(m + 8) * N + n) =
                make_float2(sa1 * sb0 * RAW(mi, nj, 2), sa1 * sb1 * RAW(mi, nj, 3));
        }
    }
}

// ---------------------------------------------------------------------------
// Causal flash attention: int8 3-term QK^T; fp16 P (single) x fp16 V (hi+lo).
// Softmax in exp2 domain (log2e folded into dequant scales).
// ---------------------------------------------------------------------------
#define KROW8 80
#define AK_TILE (64 * KROW8)
#define KSTR  72
#define AV_TILE (64 * KSTR * 2)
#define AT_STAGE (2 * AK_TILE + 2 * AV_TILE + 256)   // 28928
#define AT_SMEM  (2 * AT_STAGE)                      // 57856

__global__ void __launch_bounds__(256, 2) attn_mma(
    const int8_t* __restrict__ qk1, const int8_t* __restrict__ qk2,
    const float* __restrict__ rsqk,
    const __nv_bfloat16* __restrict__ qkvh,
    const __nv_bfloat16* __restrict__ qkvl,
    float* __restrict__ ctx)
{
    extern __shared__ __align__(16) char smem[];
    const uint32_t sb = smem_u32(smem);
    const int tid = threadIdx.x, lane = tid & 31, warp = tid >> 5;
    const int qt = (int)gridDim.x - 1 - (int)blockIdx.x;
    const int bh = blockIdx.y, b = bh >> 4, h = bh & 15;
    const int q0 = qt * 128;
    const size_t PART = (size_t)TOK * D_;
    const size_t headoff = (size_t)bh * L_ * HD_;
    const int8_t* Q8a = qk1 + headoff;
    const int8_t* Q8b = qk2 + headoff;
    const int8_t* K8a = qk1 + (size_t)B_ * H_ * L_ * 64 + headoff;
    const int8_t* K8b = qk2 + (size_t)B_ * H_ * L_ * 64 + headoff;
    const float* rsQ = rsqk + (size_t)bh * L_;
    const float* rsK = rsqk + (size_t)B_ * H_ * L_ + (size_t)bh * L_;
    // V stored as fp16 hi/lo in part 2
    const __half* Vh = (const __half*)(qkvh + 2 * PART + headoff);
    const __half* Vl = (const __half*)(qkvl + 2 * PART + headoff);

    const int r0 = q0 + warp * 16 + (lane >> 2);

    uint32_t qf1[2][4], qf2[2][4];
    {
        const int8_t* p1 = Q8a + (size_t)r0 * 64 + 4 * (lane & 3);
        const int8_t* p2 = Q8b + (size_t)r0 * 64 + 4 * (lane & 3);
        #pragma unroll
        for (int c = 0; c < 2; c++) {
            qf1[c][0] = *(const uint32_t*)(p1 + c * 32);
            qf1[c][1] = *(const uint32_t*)(p1 + 8 * 64 + c * 32);
            qf1[c][2] = *(const uint32_t*)(p1 + c * 32 + 16);
            qf1[c][3] = *(const uint32_t*)(p1 + 8 * 64 + c * 32 + 16);
            qf2[c][0] = *(const uint32_t*)(p2 + c * 32);
            qf2[c][1] = *(const uint32_t*)(p2 + 8 * 64 + c * 32);
            qf2[c][2] = *(const uint32_t*)(p2 + c * 32 + 16);
            qf2[c][3] = *(const uint32_t*)(p2 + 8 * 64 + c * 32 + 16);
        }
    }
    // dequant scales with 0.125 logit scale AND log2e folded (exp2 domain)
    const float QSC = 0.125f * 1.4426950408889634f / 16129.0f;
    const float sQ0 = __ldg(rsQ + r0)     * QSC;
    const float sQ1 = __ldg(rsQ + r0 + 8) * QSC;

    float Oa[8][4];
    #pragma unroll
    for (int j = 0; j < 8; j++)
        #pragma unroll
        for (int e = 0; e < 4; e++) Oa[j][e] = 0.0f;
    float m0 = -1e30f, m1 = -1e30f, l0 = 0.0f, l1 = 0.0f;

    const int ntiles = 2 * qt + 2;

    auto load_tile = [&](int kt, int stage) {
        const uint32_t dstbase = sb + stage * AT_STAGE;
        const int k0 = kt * 64;
        {
            const int row = tid >> 2, seg = tid & 3;
            const size_t g = (size_t)(k0 + row) * 64 + seg * 16;
            const uint32_t dof = dstbase + row * KROW8 + seg * 16;
            CP_ASYNC16(dof, K8a + g);
            CP_ASYNC16(dof + AK_TILE, K8b + g);
        }
        #pragma unroll
        for (int i = 0; i < 2; i++) {
            const int rem = tid + i * 256;
            const int row = rem >> 3, dch = rem & 7;
            const size_t g = (size_t)(k0 + row) * HD_ + dch * 8;
            const uint32_t dof = dstbase + 2 * AK_TILE + row * (KSTR * 2) + dch * 16;
            CP_ASYNC16(dof, Vh + g);
            CP_ASYNC16(dof + AV_TILE, Vl + g);
        }
        if (tid < 16) {
            CP_ASYNC16(dstbase + 2 * AK_TILE + 2 * AV_TILE + tid * 16,
                       (const int8_t*)(rsK + k0) + tid * 16);
        }
        CP_COMMIT();
    };

    load_tile(0, 0);

    for (int kt = 0; kt < ntiles; kt++) {
        const int stage = kt & 1;
        if (kt + 1 < ntiles) { load_tile(kt + 1, (kt + 1) & 1); CP_WAIT1(); }
        else                 { CP_WAIT0(); }
        __syncthreads();

        const int k0 = kt * 64;
        if (k0 <= q0 + warp * 16 + 15) {
            const uint32_t kb1 = sb + stage * AT_STAGE;
            const uint32_t kb2 = kb1 + AK_TILE;
            const uint32_t vbh = kb1 + 2 * AK_TILE;
            const uint32_t vbl = vbh + AV_TILE;
            const float* skp = (const float*)(smem + stage * AT_STAGE +
                                              2 * AK_TILE + 2 * AV_TILE);

            float Sa[8][4];
            const uint32_t k_lro =
                (uint32_t)((((lane >> 4) << 3) + (lane & 7)) * KROW8 +
                           ((lane >> 3) & 1) * 16);
            #pragma unroll
            for (int jp = 0; jp < 4; jp++) {
                int c1a[4] = {0, 0, 0, 0}, cXa[4] = {0, 0, 0, 0};
                int c1b[4] = {0, 0, 0, 0}, cXb[4] = {0, 0, 0, 0};
                const uint32_t no = (uint32_t)(jp * 16 * KROW8);
                #pragma unroll
                for (int c = 0; c < 2; c++) {
                    uint32_t k4a[4], k4b[4];
                    ldsm4(k4a, kb1 + no + k_lro + c * 32);
                    ldsm4(k4b, kb2 + no + k_lro + c * 32);
                    mma_i8(c1a, qf1[c], &k4a[0]);
                    mma_i8(cXa, qf1[c], &k4b[0]);
                    mma_i8(cXa, qf2[c], &k4a[0]);
                    mma_i8(c1b, qf1[c], &k4a[2]);
                    mma_i8(cXb, qf1[c], &k4b[2]);
                    mma_i8(cXb, qf2[c], &k4a[2]);
                }
                const int kloc = jp * 16 + 2 * (lane & 3);
                const float skA0 = skp[kloc],     skA1 = skp[kloc + 1];
                const float skB0 = skp[kloc + 8], skB1 = skp[kloc + 9];
                Sa[2 * jp][0] = sQ0 * skA0 * ((float)c1a[0] + (float)cXa[0] * (1.0f / 254.0f));
                Sa[2 * jp][1] = sQ0 * skA1 * ((float)c1a[1] + (float)cXa[1] * (1.0f / 254.0f));
                Sa[2 * jp][2] = sQ1 * skA0 * ((float)c1a[2] + (float)cXa[2] * (1.0f / 254.0f));
                Sa[2 * jp][3] = sQ1 * skA1 * ((float)c1a[3] + (float)cXa[3] * (1.0f / 254.0f));
                Sa[2 * jp + 1][0] = sQ0 * skB0 * ((float)c1b[0] + (float)cXb[0] * (1.0f / 254.0f));
                Sa[2 * jp + 1][1] = sQ0 * skB1 * ((float)c1b[1] + (float)cXb[1] * (1.0f / 254.0f));
                Sa[2 * jp + 1][2] = sQ1 * skB0 * ((float)c1b[2] + (float)cXb[2] * (1.0f / 254.0f));
                Sa[2 * jp + 1][3] = sQ1 * skB1 * ((float)c1b[3] + (float)cXb[3] * (1.0f / 254.0f));
            }

            const bool needmask = (k0 + 63 > q0 + warp * 16);
            if (needmask) {
                #pragma unroll
                for (int j = 0; j < 8; j++) {
                    const int key0 = k0 + j * 8 + 2 * (lane & 3);
                    if (key0     > r0)     Sa[j][0] = -1e30f;
                    if (key0 + 1 > r0)     Sa[j][1] = -1e30f;
                    if (key0     > r0 + 8) Sa[j][2] = -1e30f;
                    if (key0 + 1 > r0 + 8) Sa[j][3] = -1e30f;
                }
            }

            // online softmax in exp2 domain
            float mx0 = -1e30f, mx1 = -1e30f;
            #pragma unroll
            for (int j = 0; j < 8; j++) {
                mx0 = fmaxf(mx0, fmaxf(Sa[j][0], Sa[j][1]));
                mx1 = fmaxf(mx1, fmaxf(Sa[j][2], Sa[j][3]));
            }
            mx0 = fmaxf(mx0, __shfl_xor_sync(0xffffffffu, mx0, 1));
            mx0 = fmaxf(mx0, __shfl_xor_sync(0xffffffffu, mx0, 2));
            mx1 = fmaxf(mx1, __shfl_xor_sync(0xffffffffu, mx1, 1));
            mx1 = fmaxf(mx1, __shfl_xor_sync(0xffffffffu, mx1, 2));
            const float mn0 = fmaxf(m0, mx0), mn1 = fmaxf(m1, mx1);
            const float a0 = exp2f(m0 - mn0), a1 = exp2f(m1 - mn1);
            m0 = mn0; m1 = mn1;
            float rs0 = 0.0f, rs1 = 0.0f;
            #pragma unroll
            for (int j = 0; j < 8; j++) {
                Sa[j][0] = exp2f(Sa[j][0] - mn0); rs0 += Sa[j][0];
                Sa[j][1] = exp2f(Sa[j][1] - mn0); rs0 += Sa[j][1];
                Sa[j][2] = exp2f(Sa[j][2] - mn1); rs1 += Sa[j][2];
                Sa[j][3] = exp2f(Sa[j][3] - mn1); rs1 += Sa[j][3];
            }
            rs0 += __shfl_xor_sync(0xffffffffu, rs0, 1);
            rs0 += __shfl_xor_sync(0xffffffffu, rs0, 2);
            rs1 += __shfl_xor_sync(0xffffffffu, rs1, 1);
            rs1 += __shfl_xor_sync(0xffffffffu, rs1, 2);
            l0 = l0 * a0 + rs0;
            l1 = l1 * a1 + rs1;
            #pragma unroll
            for (int j = 0; j < 8; j++) {
                Oa[j][0] *= a0; Oa[j][1] *= a0;
                Oa[j][2] *= a1; Oa[j][3] *= a1;
            }

            // ---- O += P V  (P single fp16, V fp16 hi+lo) ----
            const uint32_t v_lro =
                (uint32_t)((((lane >> 3) & 1) * 8 + (lane & 7)) * KSTR +
                           (lane >> 4) * 8) * 2;
            #pragma unroll
            for (int t = 0; t < 4; t++) {
                uint32_t ah[4];
                ah[0] = pack_f16(Sa[2 * t][0],     Sa[2 * t][1]);
                ah[1] = pack_f16(Sa[2 * t][2],     Sa[2 * t][3]);
                ah[2] = pack_f16(Sa[2 * t + 1][0], Sa[2 * t + 1][1]);
                ah[3] = pack_f16(Sa[2 * t + 1][2], Sa[2 * t + 1][3]);
                const uint32_t ro = (uint32_t)(t * 16 * KSTR) * 2;
                #pragma unroll
                for (int jp = 0; jp < 4; jp++) {
                    const uint32_t co = (uint32_t)(jp * 16) * 2;
                    uint32_t vh4[4], vl4[4];
                    ldsm4t(vh4, vbh + ro + v_lro + co);
                    ldsm4t(vl4, vbl + ro + v_lro + co);
                    mma_f16(Oa[2 * jp],     ah, &vh4[0]);
                    mma_f16(Oa[2 * jp],     ah, &vl4[0]);
                    mma_f16(Oa[2 * jp + 1], ah, &vh4[2]);
                    mma_f16(Oa[2 * jp + 1], ah, &vl4[2]);
                }
            }
        }
        __syncthreads();
    }

    const float inv0 = 1.0f / l0, inv1 = 1.0f / l1;
    const size_t row_off = (size_t)(b * L_ + r0) * D_ + h * 64;
    #pragma unroll
    for (int j = 0; j < 8; j++) {
        const int n = j * 8 + 2 * (lane & 3);
        *(float2*)(ctx + row_off + n) =
            make_float2(Oa[j][0] * inv0, Oa[j][1] * inv0);
        *(float2*)(ctx + row_off + (size_t)8 * D_ + n) =
            make_float2(Oa[j][2] * inv1, Oa[j][3] * inv1);
    }
}

// ---------------------------------------------------------------------------
// kernel_launch — graph-capturable, allocation-free
// ---------------------------------------------------------------------------
extern "C" void kernel_launch(void* const* d_in, const int* in_sizes, int n_in,
                              void* d_out, int out_size)
{
    (void)in_sizes; (void)n_in; (void)out_size;
    const float* x     = (const float*)d_in[0];
    const float* w_qkv = (const float*)d_in[1];
    const float* w_out = (const float*)d_in[2];
    float* out = (float*)d_out;

    int8_t *x1, *x2, *wq1, *wq2, *wo1, *wo2, *c1, *c2, *qk1, *qk2;
    __nv_bfloat16 *qh, *ql;
    float *ctx, *rsx, *rswq, *rswo, *rsc, *rsqk;
    cudaGetSymbolAddress((void**)&x1, g_x1);
    cudaGetSymbolAddress((void**)&x2, g_x2);
    cudaGetSymbolAddress((void**)&wq1, g_wq1);
    cudaGetSymbolAddress((void**)&wq2, g_wq2);
    cudaGetSymbolAddress((void**)&wo1, g_wo1);
    cudaGetSymbolAddress((void**)&wo2, g_wo2);
    cudaGetSymbolAddress((void**)&c1, g_c1);
    cudaGetSymbolAddress((void**)&c2, g_c2);
    cudaGetSymbolAddress((void**)&qk1, g_qk1);
    cudaGetSymbolAddress((void**)&qk2, g_qk2);
    cudaGetSymbolAddress((void**)&qh, g_qkvh);
    cudaGetSymbolAddress((void**)&ql, g_qkvl);
    cudaGetSymbolAddress((void**)&ctx, g_ctx);
    cudaGetSymbolAddress((void**)&rsx, g_rsx);
    cudaGetSymbolAddress((void**)&rswq, g_rswq);
    cudaGetSymbolAddress((void**)&rswo, g_rswo);
    cudaGetSymbolAddress((void**)&rsc, g_rsc);
    cudaGetSymbolAddress((void**)&rsqk, g_rsqk);

    cudaFuncSetAttribute(attn_mma,
                         cudaFuncAttributeMaxDynamicSharedMemorySize, AT_SMEM);
    cudaFuncSetAttribute(gemm_i8_qkv,
                         cudaFuncAttributeMaxDynamicSharedMemorySize, I_SMEM);
    cudaFuncSetAttribute(gemm_i8_out,
                         cudaFuncAttributeMaxDynamicSharedMemorySize, I_SMEM);

    // fused warp-per-row quantization of x, w_qkv, w_out (one launch)
    rowquant3_k<<<(TOK + 3 * D_ + D_) / 8, 256>>>(
        (const float4*)x, (const float4*)w_qkv, (const float4*)w_out,
        (char4*)x1, (char4*)x2, (char4*)wq1, (char4*)wq2,
        (char4*)wo1, (char4*)wo2, rsx, rswq, rswo);

    // 1) QKV projection (int8, 3-term) -> Q/K bf16 hi/lo, V fp16 hi/lo
    {
        dim3 grid(3 * D_ / 128, TOK / 64);
        gemm_i8_qkv<<<grid, 256, I_SMEM>>>(x1, x2, wq1, wq2, rsx, rswq, qh, ql, D_);
    }
    // 1b) quantize Q,K head-rows to 2-level int8
    qk_quant_k<<<QKROWS / 8, 256>>>(qh, ql, qk1, qk2, rsqk);

    // 2) flash attention (int8 QK^T + fp16 PV) -> fp32 ctx
    {
        dim3 grid(L_ / 128, B_ * H_);
        attn_mma<<<grid, 256, AT_SMEM>>>(qk1, qk2, rsqk, qh, ql, ctx);
    }
    // 3) per-row quantize ctx, output projection (int8, 3-term)
    rowquant_k<<<TOK / 8, 256>>>((const float4*)ctx, (char4*)c1, (char4*)c2, rsc);
    {
        dim3 grid(D_ / 128, TOK / 64);
        gemm_i8_out<<<grid, 256, I_SMEM>>>(c1, c2, wo1, wo2, rsc, rswo, out, D_, D_);
    }
}

// round 17
// speedup vs baseline: 1.7952x; 1.0846x over previous
#include <cuda_runtime.h>
#include <cuda_bf16.h>
#include <cuda_fp16.h>
#include <cstdint>
#include <cstddef>

// Problem constants
#define B_   2
#define L_   2048
#define D_   1024
#define H_   16
#define HD_  64
#define TOK  (B_ * L_)          // 4096 tokens

// ---------------------------------------------------------------------------
// Scratch (__device__ globals; no cudaMalloc allowed)
// ---------------------------------------------------------------------------
__device__ __align__(16) int8_t g_x1[(size_t)TOK * D_];
__device__ __align__(16) int8_t g_x2[(size_t)TOK * D_];
__device__ __align__(16) int8_t g_wq1[(size_t)3 * D_ * D_];
__device__ __align__(16) int8_t g_wq2[(size_t)3 * D_ * D_];
__device__ __align__(16) int8_t g_wo1[(size_t)D_ * D_];
__device__ __align__(16) int8_t g_wo2[(size_t)D_ * D_];
__device__ __align__(16) int8_t g_c1[(size_t)TOK * D_];
__device__ __align__(16) int8_t g_c2[(size_t)TOK * D_];
// per-row quantization scales
__device__ float g_rsx[TOK];
__device__ float g_rswq[3 * D_];
__device__ float g_rswo[D_];
__device__ float g_rsc[TOK];
// head-major split qkv: [part(q/k/v)][b][h][l][64]
// parts 0,1 (Q,K): bf16 hi/lo (consumed by qk_quant)
// part 2 (V): single fp16 in g_qkvh (g_qkvl part 2 unused)
__device__ __align__(16) __nv_bfloat16 g_qkvh[(size_t)3 * TOK * D_];
__device__ __align__(16) __nv_bfloat16 g_qkvl[(size_t)3 * TOK * D_];
// int8 2-level Q/K for attention: [part(q/k)][b][h][l][64]
#define QKROWS (2 * B_ * H_ * L_)        // 131072 rows of 64
__device__ __align__(16) int8_t g_qk1[(size_t)QKROWS * 64];
__device__ __align__(16) int8_t g_qk2[(size_t)QKROWS * 64];
__device__ float g_rsqk[QKROWS];
// attention context fp32 [tok][1024]
__device__ __align__(16) float g_ctx[(size_t)TOK * D_];

// ---------------------------------------------------------------------------
// Helpers
// ---------------------------------------------------------------------------
__device__ __forceinline__ uint32_t smem_u32(const void* p) {
    uint32_t a;
    asm("{ .reg .u64 t; cvta.to.shared.u64 t, %1; cvt.u32.u64 %0, t; }" : "=r"(a) : "l"(p));
    return a;
}

__device__ __forceinline__ void mma_f16(float* c, const uint32_t* a, const uint32_t* b) {
    asm volatile("mma.sync.aligned.m16n8k16.row.col.f32.f16.f16.f32 "
                 "{%0,%1,%2,%3}, {%4,%5,%6,%7}, {%8,%9}, {%0,%1,%2,%3};"
                 : "+f"(c[0]), "+f"(c[1]), "+f"(c[2]), "+f"(c[3])
                 : "r"(a[0]), "r"(a[1]), "r"(a[2]), "r"(a[3]),
                   "r"(b[0]), "r"(b[1]));
}

__device__ __forceinline__ void mma_i8(int* c, const uint32_t* a, const uint32_t* b) {
    asm volatile("mma.sync.aligned.m16n8k32.row.col.s32.s8.s8.s32 "
                 "{%0,%1,%2,%3}, {%4,%5,%6,%7}, {%8,%9}, {%0,%1,%2,%3};"
                 : "+r"(c[0]), "+r"(c[1]), "+r"(c[2]), "+r"(c[3])
                 : "r"(a[0]), "r"(a[1]), "r"(a[2]), "r"(a[3]),
                   "r"(b[0]), "r"(b[1]));
}

__device__ __forceinline__ void ldsm4(uint32_t* r, uint32_t addr) {
    asm volatile("ldmatrix.sync.aligned.m8n8.x4.shared.b16 {%0,%1,%2,%3}, [%4];"
                 : "=r"(r[0]), "=r"(r[1]), "=r"(r[2]), "=r"(r[3]) : "r"(addr));
}
__device__ __forceinline__ void ldsm4t(uint32_t* r, uint32_t addr) {
    asm volatile("ldmatrix.sync.aligned.m8n8.x4.trans.shared.b16 {%0,%1,%2,%3}, [%4];"
                 : "=r"(r[0]), "=r"(r[1]), "=r"(r[2]), "=r"(r[3]) : "r"(addr));
}

// bf16 split: pack (x,y) to bf16x2 hi pair + bf16x2 lo (residual) pair
__device__ __forceinline__ void split_pack2(float x, float y, uint32_t& hp, uint32_t& lp) {
    asm("cvt.rn.satfinite.bf16x2.f32 %0, %1, %2;" : "=r"(hp) : "f"(y), "f"(x));
    const float hx = __bfloat162float(__ushort_as_bfloat16((uint16_t)hp));
    const float hy = __bfloat162float(__ushort_as_bfloat16((uint16_t)(hp >> 16)));
    asm("cvt.rn.satfinite.bf16x2.f32 %0, %1, %2;" : "=r"(lp) : "f"(y - hy), "f"(x - hx));
}
// single fp16 pack (no residual)
__device__ __forceinline__ uint32_t pack_f16(float x, float y) {
    uint32_t p;
    asm("cvt.rn.f16x2.f32 %0, %1, %2;" : "=r"(p) : "f"(y), "f"(x));
    return p;
}

#define CP_ASYNC16(dst, src) \
    asm volatile("cp.async.cg.shared.global [%0], [%1], 16;" :: "r"(dst), "l"(src) : "memory")
#define CP_COMMIT() asm volatile("cp.async.commit_group;" ::: "memory")
#define CP_WAIT1()  asm volatile("cp.async.wait_group 1;" ::: "memory")
#define CP_WAIT0()  asm volatile("cp.async.wait_group 0;" ::: "memory")

// ---------------------------------------------------------------------------
// Warp-per-row absmax + 2-level int8 quant, fused over x / w_qkv / w_out.
// ---------------------------------------------------------------------------
__global__ void __launch_bounds__(256) rowquant3_k(
    const float4* __restrict__ x, const float4* __restrict__ wq,
    const float4* __restrict__ wo,
    char4* __restrict__ x1, char4* __restrict__ x2,
    char4* __restrict__ wq1, char4* __restrict__ wq2,
    char4* __restrict__ wo1, char4* __restrict__ wo2,
    float* __restrict__ rsx, float* __restrict__ rswq, float* __restrict__ rswo)
{
    const int warp = threadIdx.x >> 5, lane = threadIdx.x & 31;
    const int g = blockIdx.x * 8 + warp;
    const float4* in; char4 *q1, *q2; float* rs; int r;
    if (g < 4096)      { in = x;  q1 = x1;  q2 = x2;  rs = rsx;  r = g; }
    else if (g < 7168) { in = wq; q1 = wq1; q2 = wq2; rs = rswq; r = g - 4096; }
    else               { in = wo; q1 = wo1; q2 = wo2; rs = rswo; r = g - 7168; }

    const float4* rowp = in + (size_t)r * 256;
    float4 v[8];
    float m = 0.0f;
    #pragma unroll
    for (int i = 0; i < 8; i++) {
        v[i] = rowp[lane + i * 32];
        m = fmaxf(m, fmaxf(fmaxf(fabsf(v[i].x), fabsf(v[i].y)),
                           fmaxf(fabsf(v[i].z), fabsf(v[i].w))));
    }
    #pragma unroll
    for (int o = 16; o; o >>= 1) m = fmaxf(m, __shfl_xor_sync(0xffffffffu, m, o));
    const float s = fmaxf(m, 1e-20f);
    const float k = 127.0f / s;
    #pragma unroll
    for (int i = 0; i < 8; i++) {
        float u0 = v[i].x * k, u1 = v[i].y * k, u2 = v[i].z * k, u3 = v[i].w * k;
        float a0 = rintf(u0), a1 = rintf(u1), a2 = rintf(u2), a3 = rintf(u3);
        float b0 = rintf((u0 - a0) * 254.0f), b1 = rintf((u1 - a1) * 254.0f);
        float b2 = rintf((u2 - a2) * 254.0f), b3 = rintf((u3 - a3) * 254.0f);
        const size_t idx = (size_t)r * 256 + lane + i * 32;
        q1[idx] = make_char4((int)a0, (int)a1, (int)a2, (int)a3);
        q2[idx] = make_char4((int)b0, (int)b1, (int)b2, (int)b3);
    }
    if (lane == 0) rs[r] = s;
}

// single-tensor variant (for ctx)
__global__ void __launch_bounds__(256) rowquant_k(
    const float4* __restrict__ in, char4* __restrict__ q1,
    char4* __restrict__ q2, float* __restrict__ rs)
{
    const int warp = threadIdx.x >> 5, lane = threadIdx.x & 31;
    const int r = blockIdx.x * 8 + warp;
    const float4* rowp = in + (size_t)r * 256;
    float4 v[8];
    float m = 0.0f;
    #pragma unroll
    for (int i = 0; i < 8; i++) {
        v[i] = rowp[lane + i * 32];
        m = fmaxf(m, fmaxf(fmaxf(fabsf(v[i].x), fabsf(v[i].y)),
                           fmaxf(fabsf(v[i].z), fabsf(v[i].w))));
    }
    #pragma unroll
    for (int o = 16; o; o >>= 1) m = fmaxf(m, __shfl_xor_sync(0xffffffffu, m, o));
    const float s = fmaxf(m, 1e-20f);
    const float k = 127.0f / s;
    #pragma unroll
    for (int i = 0; i < 8; i++) {
        float u0 = v[i].x * k, u1 = v[i].y * k, u2 = v[i].z * k, u3 = v[i].w * k;
        float a0 = rintf(u0), a1 = rintf(u1), a2 = rintf(u2), a3 = rintf(u3);
        float b0 = rintf((u0 - a0) * 254.0f), b1 = rintf((u1 - a1) * 254.0f);
        float b2 = rintf((u2 - a2) * 254.0f), b3 = rintf((u3 - a3) * 254.0f);
        const size_t idx = (size_t)r * 256 + lane + i * 32;
        q1[idx] = make_char4((int)a0, (int)a1, (int)a2, (int)a3);
        q2[idx] = make_char4((int)b0, (int)b1, (int)b2, (int)b3);
    }
    if (lane == 0) rs[r] = s;
}

// ---------------------------------------------------------------------------
// Q/K head-row quantization (reads bf16 hi/lo parts 0,1): warp per 64-row.
// ---------------------------------------------------------------------------
__global__ void __launch_bounds__(256) qk_quant_k(
    const __nv_bfloat16* __restrict__ qkvh,
    const __nv_bfloat16* __restrict__ qkvl,
    int8_t* __restrict__ q1, int8_t* __restrict__ q2,
    float* __restrict__ rs)
{
    const int warp = threadIdx.x >> 5, lane = threadIdx.x & 31;
    const int row = blockIdx.x * 8 + warp;
    const size_t soff = (size_t)row * 64 + (size_t)lane * 2;
    const uint32_t ph = *(const uint32_t*)(qkvh + soff);
    const uint32_t pl = *(const uint32_t*)(qkvl + soff);
    float f0 = __bfloat162float(__ushort_as_bfloat16((uint16_t)ph)) +
               __bfloat162float(__ushort_as_bfloat16((uint16_t)pl));
    float f1 = __bfloat162float(__ushort_as_bfloat16((uint16_t)(ph >> 16))) +
               __bfloat162float(__ushort_as_bfloat16((uint16_t)(pl >> 16)));
    float m = fmaxf(fabsf(f0), fabsf(f1));
    #pragma unroll
    for (int o = 16; o; o >>= 1) m = fmaxf(m, __shfl_xor_sync(0xffffffffu, m, o));
    const float s = fmaxf(m, 1e-20f);
    const float k = 127.0f / s;
    float u0 = f0 * k, u1 = f1 * k;
    float a0 = rintf(u0), a1 = rintf(u1);
    float b0 = rintf((u0 - a0) * 254.0f), b1 = rintf((u1 - a1) * 254.0f);
    char2 c1; c1.x = (char)(int)a0; c1.y = (char)(int)a1;
    char2 c2; c2.x = (char)(int)b0; c2.y = (char)(int)b1;
    *(char2*)(q1 + soff) = c1;
    *(char2*)(q2 + soff) = c2;
    if (lane == 0) rs[row] = s;
}

// ---------------------------------------------------------------------------
// int8 GEMM (3-term, per-row scales) — proven R15 body (BK=64, 3-stage).
// ---------------------------------------------------------------------------
#define ISROW   80
#define IT_A    (64 * ISROW)
#define IT_B    (128 * ISROW)
#define I_STAGE (2 * IT_A + 2 * IT_B)
#define I_SMEM  (3 * I_STAGE)

#define GEMM_I8_BODY(A1p, A2p, B1p, B2p, K)                                    \
    extern __shared__ __align__(16) char smemraw[];                            \
    const uint32_t sb = smem_u32(smemraw);                                     \
    const int tid = threadIdx.x, lane = tid & 31, warp = tid >> 5;             \
    const int wm = warp >> 2, wn = warp & 3;                                   \
    const int bm = blockIdx.y * 64, bn = blockIdx.x * 128;                     \
    int acc1[2][4][4], accX[2][4][4];                                          \
    _Pragma("unroll")                                                          \
    for (int i = 0; i < 2; i++)                                                \
        _Pragma("unroll")                                                      \
        for (int j = 0; j < 4; j++)                                            \
            _Pragma("unroll")                                                  \
            for (int e = 0; e < 4; e++) { acc1[i][j][e] = 0; accX[i][j][e] = 0; } \
    const int nk = K / 64;                                                     \
    auto load_st = [&](int kt, int st) {                                       \
        const uint32_t base = sb + st * I_STAGE;                               \
        const int ko = kt * 64;                                                \
        _Pragma("unroll")                                                      \
        for (int i = 0; i < 6; i++) {                                          \
            const int idx = tid + i * 256;                                     \
            uint32_t dst; const int8_t* src;                                   \
            if (idx < 512) {                                                   \
                const int var = idx >> 8, rem = idx & 255;                     \
                const int row = rem >> 2, seg = rem & 3;                       \
                dst = base + var * IT_A + row * ISROW + seg * 16;              \
                src = (var == 0 ? A1p : A2p) +                                 \
                      (size_t)(bm + row) * K + ko + seg * 16;                  \
            } else {                                                           \
                const int j2 = idx - 512;                                      \
                const int var = j2 >> 9, rem = j2 & 511;                       \
                const int row = rem >> 2, seg = rem & 3;                       \
                dst = base + 2 * IT_A + var * IT_B + row * ISROW + seg * 16;   \
                src = (var == 0 ? B1p : B2p) +                                 \
                      (size_t)(bn + row) * K + ko + seg * 16;                  \
            }                                                                  \
            CP_ASYNC16(dst, src);                                              \
        }                                                                      \
        CP_COMMIT();                                                           \
    };                                                                         \
    load_st(0, 0); load_st(1, 1);                                              \
    for (int kt = 0; kt < nk; kt++) {                                          \
        const int st = kt % 3;                                                 \
        if (kt + 1 < nk) { CP_WAIT1(); } else { CP_WAIT0(); }                  \
        __syncthreads();                                                       \
        if (kt + 2 < nk) load_st(kt + 2, (kt + 2) % 3);                        \
        const uint32_t aT = sb + st * I_STAGE;                                 \
        _Pragma("unroll")                                                      \
        for (int c = 0; c < 2; c++) {                                          \
            const uint32_t a_lro = (uint32_t)((lane & 15) * ISROW +            \
                                              (lane >> 4) * 16 + c * 32);      \
            const uint32_t b_lro = (uint32_t)((((lane >> 4) << 3) +            \
                                               (lane & 7)) * ISROW +           \
                                              ((lane >> 3) & 1) * 16 + c * 32);\
            uint32_t f1[2][4], f2[2][4], gB1[2][4], gB2[2][4];                 \
            _Pragma("unroll")                                                  \
            for (int mi = 0; mi < 2; mi++) {                                   \
                const uint32_t mo = (uint32_t)((wm * 32 + mi * 16) * ISROW);   \
                ldsm4(f1[mi], aT + 0 * IT_A + mo + a_lro);                     \
                ldsm4(f2[mi], aT + 1 * IT_A + mo + a_lro);                     \
            }                                                                  \
            _Pragma("unroll")                                                  \
            for (int np = 0; np < 2; np++) {                                   \
                const uint32_t no = (uint32_t)((wn * 32 + np * 16) * ISROW);   \
                ldsm4(gB1[np], aT + 2 * IT_A + no + b_lro);                    \
                ldsm4(gB2[np], aT + 2 * IT_A + IT_B + no + b_lro);             \
            }                                                                  \
            _Pragma("unroll")                                                  \
            for (int mi = 0; mi < 2; mi++)                                     \
                _Pragma("unroll")                                              \
                for (int nj = 0; nj < 4; nj++)                                 \
                    mma_i8(acc1[mi][nj], f1[mi], &gB1[nj >> 1][(nj & 1) * 2]); \
            _Pragma("unroll")                                                  \
            for (int mi = 0; mi < 2; mi++)                                     \
                _Pragma("unroll")                                              \
                for (int nj = 0; nj < 4; nj++)                                 \
                    mma_i8(accX[mi][nj], f1[mi], &gB2[nj >> 1][(nj & 1) * 2]); \
            _Pragma("unroll")                                                  \
            for (int mi = 0; mi < 2; mi++)                                     \
                _Pragma("unroll")                                              \
                for (int nj = 0; nj < 4; nj++)                                 \
                    mma_i8(accX[mi][nj], f2[mi], &gB1[nj >> 1][(nj & 1) * 2]); \
        }                                                                      \
    }

#define RAW(mi, nj, e) \
    ((float)acc1[mi][nj][e] + (float)accX[mi][nj][e] * (1.0f / 254.0f))

// QKV projection: per-row dequant; parts 0,1 (Q,K) -> bf16 hi/lo,
// part 2 (V) -> single fp16 (hi only). Head-major writeout.
__global__ void __launch_bounds__(256) gemm_i8_qkv(
    const int8_t* __restrict__ A1p, const int8_t* __restrict__ A2p,
    const int8_t* __restrict__ B1p, const int8_t* __restrict__ B2p,
    const float* __restrict__ rsA, const float* __restrict__ rsB,
    __nv_bfloat16* __restrict__ Qh, __nv_bfloat16* __restrict__ Ql, int K)
{
    GEMM_I8_BODY(A1p, A2p, B1p, B2p, K)
    const int part = bn >> 10;           // whole CTA tile in one part
    #pragma unroll
    for (int mi = 0; mi < 2; mi++) {
        const int m = bm + wm * 32 + mi * 16 + (lane >> 2);   // token
        const int bb = m >> 11, ll = m & 2047;
        const float sa0 = __ldg(rsA + m)     * (1.0f / 16129.0f);
        const float sa1 = __ldg(rsA + m + 8) * (1.0f / 16129.0f);
        #pragma unroll
        for (int nj = 0; nj < 4; nj++) {
            const int n = bn + wn * 32 + nj * 8 + (lane & 3) * 2;
            const float sb0 = __ldg(rsB + n), sb1 = __ldg(rsB + n + 1);
            const int rem = n & 1023, hh = rem >> 6, dd = rem & 63;
            const size_t off = (((size_t)(part * B_ + bb) * H_ + hh) * L_ + ll) * HD_ + dd;
            if (part == 2) {
                *(uint32_t*)(Qh + off) =
                    pack_f16(sa0 * sb0 * RAW(mi, nj, 0), sa0 * sb1 * RAW(mi, nj, 1));
                *(uint32_t*)(Qh + off + (size_t)8 * HD_) =
                    pack_f16(sa1 * sb0 * RAW(mi, nj, 2), sa1 * sb1 * RAW(mi, nj, 3));
            } else {
                uint32_t hp, lp;
                split_pack2(sa0 * sb0 * RAW(mi, nj, 0), sa0 * sb1 * RAW(mi, nj, 1), hp, lp);
                *(uint32_t*)(Qh + off) = hp;
                *(uint32_t*)(Ql + off) = lp;
                split_pack2(sa1 * sb0 * RAW(mi, nj, 2), sa1 * sb1 * RAW(mi, nj, 3), hp, lp);
                *(uint32_t*)(Qh + off + (size_t)8 * HD_) = hp;
                *(uint32_t*)(Ql + off + (size_t)8 * HD_) = lp;
            }
        }
    }
}

// Output projection: per-row dequant + fp32 row-major C[M,N]
__global__ void __launch_bounds__(256) gemm_i8_out(
    const int8_t* __restrict__ A1p, const int8_t* __restrict__ A2p,
    const int8_t* __restrict__ B1p, const int8_t* __restrict__ B2p,
    const float* __restrict__ rsA, const float* __restrict__ rsB,
    float* __restrict__ C, int N, int K)
{
    GEMM_I8_BODY(A1p, A2p, B1p, B2p, K)
    #pragma unroll
    for (int mi = 0; mi < 2; mi++) {
        const int m = bm + wm * 32 + mi * 16 + (lane >> 2);
        const float sa0 = __ldg(rsA + m)     * (1.0f / 16129.0f);
        const float sa1 = __ldg(rsA + m + 8) * (1.0f / 16129.0f);
        #pragma unroll
        for (int nj = 0; nj < 4; nj++) {
            const int n = bn + wn * 32 + nj * 8 + (lane & 3) * 2;
            const float sb0 = __ldg(rsB + n), sb1 = __ldg(rsB + n + 1);
            *(float2*)(C + (size_t)m * N + n) =
                make_float2(sa0 * sb0 * RAW(mi, nj, 0), sa0 * sb1 * RAW(mi, nj, 1));
            *(float2*)(C + (size_t)(m + 8) * N + n) =
                make_float2(sa1 * sb0 * RAW(mi, nj, 2), sa1 * sb1 * RAW(mi, nj, 3));
        }
    }
}

// ---------------------------------------------------------------------------
// Causal flash attention: int8 3-term QK^T (IMAD-combined dequant);
// fp16 P (single) x fp16 V (single). Softmax in exp2 domain.
// ---------------------------------------------------------------------------
#define KROW8 80
#define AK_TILE (64 * KROW8)              // 5120
#define KSTR  72
#define AV_TILE (64 * KSTR * 2)           // 9216
#define AT_STAGE (2 * AK_TILE + AV_TILE + 256)   // 19712
#define AT_SMEM  (2 * AT_STAGE)                  // 39424

__global__ void __launch_bounds__(256, 2) attn_mma(
    const int8_t* __restrict__ qk1, const int8_t* __restrict__ qk2,
    const float* __restrict__ rsqk,
    const __nv_bfloat16* __restrict__ qkvh,
    float* __restrict__ ctx)
{
    extern __shared__ __align__(16) char smem[];
    const uint32_t sb = smem_u32(smem);
    const int tid = threadIdx.x, lane = tid & 31, warp = tid >> 5;
    const int qt = (int)gridDim.x - 1 - (int)blockIdx.x;
    const int bh = blockIdx.y, b = bh >> 4, h = bh & 15;
    const int q0 = qt * 128;
    const size_t PART = (size_t)TOK * D_;
    const size_t headoff = (size_t)bh * L_ * HD_;
    const int8_t* Q8a = qk1 + headoff;
    const int8_t* Q8b = qk2 + headoff;
    const int8_t* K8a = qk1 + (size_t)B_ * H_ * L_ * 64 + headoff;
    const int8_t* K8b = qk2 + (size_t)B_ * H_ * L_ * 64 + headoff;
    const float* rsQ = rsqk + (size_t)bh * L_;
    const float* rsK = rsqk + (size_t)B_ * H_ * L_ + (size_t)bh * L_;
    const __half* Vh = (const __half*)(qkvh + 2 * PART + headoff);

    const int r0 = q0 + warp * 16 + (lane >> 2);

    uint32_t qf1[2][4], qf2[2][4];
    {
        const int8_t* p1 = Q8a + (size_t)r0 * 64 + 4 * (lane & 3);
        const int8_t* p2 = Q8b + (size_t)r0 * 64 + 4 * (lane & 3);
        #pragma unroll
        for (int c = 0; c < 2; c++) {
            qf1[c][0] = *(const uint32_t*)(p1 + c * 32);
            qf1[c][1] = *(const uint32_t*)(p1 + 8 * 64 + c * 32);
            qf1[c][2] = *(const uint32_t*)(p1 + c * 32 + 16);
            qf1[c][3] = *(const uint32_t*)(p1 + 8 * 64 + c * 32 + 16);
            qf2[c][0] = *(const uint32_t*)(p2 + c * 32);
            qf2[c][1] = *(const uint32_t*)(p2 + 8 * 64 + c * 32);
            qf2[c][2] = *(const uint32_t*)(p2 + c * 32 + 16);
            qf2[c][3] = *(const uint32_t*)(p2 + 8 * 64 + c * 32 + 16);
        }
    }
    // dequant scales: 0.125 logit scale, log2e (exp2 domain), /127^2, /254 (IMAD form)
    const float QSC = 0.125f * 1.4426950408889634f / (16129.0f * 254.0f);
    const float sQ0 = __ldg(rsQ + r0)     * QSC;
    const float sQ1 = __ldg(rsQ + r0 + 8) * QSC;

    float Oa[8][4];
    #pragma unroll
    for (int j = 0; j < 8; j++)
        #pragma unroll
        for (int e = 0; e < 4; e++) Oa[j][e] = 0.0f;
    float m0 = -1e30f, m1 = -1e30f, l0 = 0.0f, l1 = 0.0f;

    const int ntiles = 2 * qt + 2;

    auto load_tile = [&](int kt, int stage) {
        const uint32_t dstbase = sb + stage * AT_STAGE;
        const int k0 = kt * 64;
        {
            const int row = tid >> 2, seg = tid & 3;
            const size_t g = (size_t)(k0 + row) * 64 + seg * 16;
            const uint32_t dof = dstbase + row * KROW8 + seg * 16;
            CP_ASYNC16(dof, K8a + g);
            CP_ASYNC16(dof + AK_TILE, K8b + g);
        }
        #pragma unroll
        for (int i = 0; i < 2; i++) {
            const int rem = tid + i * 256;
            const int row = rem >> 3, dch = rem & 7;
            const size_t g = (size_t)(k0 + row) * HD_ + dch * 8;
            CP_ASYNC16(dstbase + 2 * AK_TILE + row * (KSTR * 2) + dch * 16, Vh + g);
        }
        if (tid < 16) {
            CP_ASYNC16(dstbase + 2 * AK_TILE + AV_TILE + tid * 16,
                       (const int8_t*)(rsK + k0) + tid * 16);
        }
        CP_COMMIT();
    };

    load_tile(0, 0);

    for (int kt = 0; kt < ntiles; kt++) {
        const int stage = kt & 1;
        if (kt + 1 < ntiles) { load_tile(kt + 1, (kt + 1) & 1); CP_WAIT1(); }
        else                 { CP_WAIT0(); }
        __syncthreads();

        const int k0 = kt * 64;
        if (k0 <= q0 + warp * 16 + 15) {
            const uint32_t kb1 = sb + stage * AT_STAGE;
            const uint32_t kb2 = kb1 + AK_TILE;
            const uint32_t vbh = kb1 + 2 * AK_TILE;
            const float* skp = (const float*)(smem + stage * AT_STAGE +
                                              2 * AK_TILE + AV_TILE);

            float Sa[8][4];
            const uint32_t k_lro =
                (uint32_t)((((lane >> 4) << 3) + (lane & 7)) * KROW8 +
                           ((lane >> 3) & 1) * 16);
            #pragma unroll
            for (int jp = 0; jp < 4; jp++) {
                int c1a[4] = {0, 0, 0, 0}, cXa[4] = {0, 0, 0, 0};
                int c1b[4] = {0, 0, 0, 0}, cXb[4] = {0, 0, 0, 0};
                const uint32_t no = (uint32_t)(jp * 16 * KROW8);
                #pragma unroll
                for (int c = 0; c < 2; c++) {
                    uint32_t k4a[4], k4b[4];
                    ldsm4(k4a, kb1 + no + k_lro + c * 32);
                    ldsm4(k4b, kb2 + no + k_lro + c * 32);
                    mma_i8(c1a, qf1[c], &k4a[0]);
                    mma_i8(cXa, qf1[c], &k4b[0]);
                    mma_i8(cXa, qf2[c], &k4a[0]);
                    mma_i8(c1b, qf1[c], &k4a[2]);
                    mma_i8(cXb, qf1[c], &k4b[2]);
                    mma_i8(cXb, qf2[c], &k4a[2]);
                }
                const int kloc = jp * 16 + 2 * (lane & 3);
                const float skA0 = skp[kloc],     skA1 = skp[kloc + 1];
                const float skB0 = skp[kloc + 8], skB1 = skp[kloc + 9];
                // IMAD-combined dequant: value = 254*c1 + cX (K=64: no overflow)
                Sa[2 * jp][0] = sQ0 * skA0 * (float)(254 * c1a[0] + cXa[0]);
                Sa[2 * jp][1] = sQ0 * skA1 * (float)(254 * c1a[1] + cXa[1]);
                Sa[2 * jp][2] = sQ1 * skA0 * (float)(254 * c1a[2] + cXa[2]);
                Sa[2 * jp][3] = sQ1 * skA1 * (float)(254 * c1a[3] + cXa[3]);
                Sa[2 * jp + 1][0] = sQ0 * skB0 * (float)(254 * c1b[0] + cXb[0]);
                Sa[2 * jp + 1][1] = sQ0 * skB1 * (float)(254 * c1b[1] + cXb[1]);
                Sa[2 * jp + 1][2] = sQ1 * skB0 * (float)(254 * c1b[2] + cXb[2]);
                Sa[2 * jp + 1][3] = sQ1 * skB1 * (float)(254 * c1b[3] + cXb[3]);
            }

            const bool needmask = (k0 + 63 > q0 + warp * 16);
            if (needmask) {
                #pragma unroll
                for (int j = 0; j < 8; j++) {
                    const int key0 = k0 + j * 8 + 2 * (lane & 3);
                    if (key0     > r0)     Sa[j][0] = -1e30f;
                    if (key0 + 1 > r0)     Sa[j][1] = -1e30f;
                    if (key0     > r0 + 8) Sa[j][2] = -1e30f;
                    if (key0 + 1 > r0 + 8) Sa[j][3] = -1e30f;
                }
            }

            // online softmax in exp2 domain
            float mx0 = -1e30f, mx1 = -1e30f;
            #pragma unroll
            for (int j = 0; j < 8; j++) {
                mx0 = fmaxf(mx0, fmaxf(Sa[j][0], Sa[j][1]));
                mx1 = fmaxf(mx1, fmaxf(Sa[j][2], Sa[j][3]));
            }
            mx0 = fmaxf(mx0, __shfl_xor_sync(0xffffffffu, mx0, 1));
            mx0 = fmaxf(mx0, __shfl_xor_sync(0xffffffffu, mx0, 2));
            mx1 = fmaxf(mx1, __shfl_xor_sync(0xffffffffu, mx1, 1));
            mx1 = fmaxf(mx1, __shfl_xor_sync(0xffffffffu, mx1, 2));
            const float mn0 = fmaxf(m0, mx0), mn1 = fmaxf(m1, mx1);
            const float a0 = exp2f(m0 - mn0), a1 = exp2f(m1 - mn1);
            m0 = mn0; m1 = mn1;
            float rs0 = 0.0f, rs1 = 0.0f;
            #pragma unroll
            for (int j = 0; j < 8; j++) {
                Sa[j][0] = exp2f(Sa[j][0] - mn0); rs0 += Sa[j][0];
                Sa[j][1] = exp2f(Sa[j][1] - mn0); rs0 += Sa[j][1];
                Sa[j][2] = exp2f(Sa[j][2] - mn1); rs1 += Sa[j][2];
                Sa[j][3] = exp2f(Sa[j][3] - mn1); rs1 += Sa[j][3];
            }
            rs0 += __shfl_xor_sync(0xffffffffu, rs0, 1);
            rs0 += __shfl_xor_sync(0xffffffffu, rs0, 2);
            rs1 += __shfl_xor_sync(0xffffffffu, rs1, 1);
            rs1 += __shfl_xor_sync(0xffffffffu, rs1, 2);
            l0 = l0 * a0 + rs0;
            l1 = l1 * a1 + rs1;
            #pragma unroll
            for (int j = 0; j < 8; j++) {
                Oa[j][0] *= a0; Oa[j][1] *= a0;
                Oa[j][2] *= a1; Oa[j][3] *= a1;
            }

            // ---- O += P V  (P single fp16, V single fp16) ----
            const uint32_t v_lro =
                (uint32_t)((((lane >> 3) & 1) * 8 + (lane & 7)) * KSTR +
                           (lane >> 4) * 8) * 2;
            #pragma unroll
            for (int t = 0; t < 4; t++) {
                uint32_t ah[4];
                ah[0] = pack_f16(Sa[2 * t][0],     Sa[2 * t][1]);
                ah[1] = pack_f16(Sa[2 * t][2],     Sa[2 * t][3]);
                ah[2] = pack_f16(Sa[2 * t + 1][0], Sa[2 * t + 1][1]);
                ah[3] = pack_f16(Sa[2 * t + 1][2], Sa[2 * t + 1][3]);
                const uint32_t ro = (uint32_t)(t * 16 * KSTR) * 2;
                #pragma unroll
                for (int jp = 0; jp < 4; jp++) {
                    const uint32_t co = (uint32_t)(jp * 16) * 2;
                    uint32_t vh4[4];
                    ldsm4t(vh4, vbh + ro + v_lro + co);
                    mma_f16(Oa[2 * jp],     ah, &vh4[0]);
                    mma_f16(Oa[2 * jp + 1], ah, &vh4[2]);
                }
            }
        }
        __syncthreads();
    }

    const float inv0 = 1.0f / l0, inv1 = 1.0f / l1;
    const size_t row_off = (size_t)(b * L_ + r0) * D_ + h * 64;
    #pragma unroll
    for (int j = 0; j < 8; j++) {
        const int n = j * 8 + 2 * (lane & 3);
        *(float2*)(ctx + row_off + n) =
            make_float2(Oa[j][0] * inv0, Oa[j][1] * inv0);
        *(float2*)(ctx + row_off + (size_t)8 * D_ + n) =
            make_float2(Oa[j][2] * inv1, Oa[j][3] * inv1);
    }
}

// ---------------------------------------------------------------------------
// kernel_launch — graph-capturable, allocation-free
// ---------------------------------------------------------------------------
extern "C" void kernel_launch(void* const* d_in, const int* in_sizes, int n_in,
                              void* d_out, int out_size)
{
    (void)in_sizes; (void)n_in; (void)out_size;
    const float* x     = (const float*)d_in[0];
    const float* w_qkv = (const float*)d_in[1];
    const float* w_out = (const float*)d_in[2];
    float* out = (float*)d_out;

    int8_t *x1, *x2, *wq1, *wq2, *wo1, *wo2, *c1, *c2, *qk1, *qk2;
    __nv_bfloat16 *qh, *ql;
    float *ctx, *rsx, *rswq, *rswo, *rsc, *rsqk;
    cudaGetSymbolAddress((void**)&x1, g_x1);
    cudaGetSymbolAddress((void**)&x2, g_x2);
    cudaGetSymbolAddress((void**)&wq1, g_wq1);
    cudaGetSymbolAddress((void**)&wq2, g_wq2);
    cudaGetSymbolAddress((void**)&wo1, g_wo1);
    cudaGetSymbolAddress((void**)&wo2, g_wo2);
    cudaGetSymbolAddress((void**)&c1, g_c1);
    cudaGetSymbolAddress((void**)&c2, g_c2);
    cudaGetSymbolAddress((void**)&qk1, g_qk1);
    cudaGetSymbolAddress((void**)&qk2, g_qk2);
    cudaGetSymbolAddress((void**)&qh, g_qkvh);
    cudaGetSymbolAddress((void**)&ql, g_qkvl);
    cudaGetSymbolAddress((void**)&ctx, g_ctx);
    cudaGetSymbolAddress((void**)&rsx, g_rsx);
    cudaGetSymbolAddress((void**)&rswq, g_rswq);
    cudaGetSymbolAddress((void**)&rswo, g_rswo);
    cudaGetSymbolAddress((void**)&rsc, g_rsc);
    cudaGetSymbolAddress((void**)&rsqk, g_rsqk);

    cudaFuncSetAttribute(attn_mma,
                         cudaFuncAttributeMaxDynamicSharedMemorySize, AT_SMEM);
    cudaFuncSetAttribute(gemm_i8_qkv,
                         cudaFuncAttributeMaxDynamicSharedMemorySize, I_SMEM);
    cudaFuncSetAttribute(gemm_i8_out,
                         cudaFuncAttributeMaxDynamicSharedMemorySize, I_SMEM);

    // fused warp-per-row quantization of x, w_qkv, w_out (one launch)
    rowquant3_k<<<(TOK + 3 * D_ + D_) / 8, 256>>>(
        (const float4*)x, (const float4*)w_qkv, (const float4*)w_out,
        (char4*)x1, (char4*)x2, (char4*)wq1, (char4*)wq2,
        (char4*)wo1, (char4*)wo2, rsx, rswq, rswo);

    // 1) QKV projection (int8, 3-term) -> Q/K bf16 hi/lo, V single fp16
    {
        dim3 grid(3 * D_ / 128, TOK / 64);
        gemm_i8_qkv<<<grid, 256, I_SMEM>>>(x1, x2, wq1, wq2, rsx, rswq, qh, ql, D_);
    }
    // 1b) quantize Q,K head-rows to 2-level int8
    qk_quant_k<<<QKROWS / 8, 256>>>(qh, ql, qk1, qk2, rsqk);

    // 2) flash attention (int8 QK^T + fp16 PV) -> fp32 ctx
    {
        dim3 grid(L_ / 128, B_ * H_);
        attn_mma<<<grid, 256, AT_SMEM>>>(qk1, qk2, rsqk, qh, ctx);
    }
    // 3) per-row quantize ctx, output projection (int8, 3-term)
    rowquant_k<<<TOK / 8, 256>>>((const float4*)ctx, (char4*)c1, (char4*)c2, rsc);
    {
        dim3 grid(D_ / 128, TOK / 64);
        gemm_i8_out<<<grid, 256, I_SMEM>>>(c1, c2, wo1, wo2, rsc, rswo, out, D_, D_);
    }
}